// round 9
// baseline (speedup 1.0000x reference)
#include <cuda_runtime.h>
#include <cuda_bf16.h>
#include <cstdint>

#define Bb 4
#define Tt 2048
#define Cc 1024
#define Hh 16
#define HD 64
#define MR (Bb*Tt)      // 8192 rows

// ---------------------------------------------------------------------------
// device scratch (allocation-free rule)
// ---------------------------------------------------------------------------
__device__ __nv_bfloat16 g_Qhi[Bb*Hh*Tt*HD];
__device__ __nv_bfloat16 g_Qlo[Bb*Hh*Tt*HD];
__device__ __nv_bfloat16 g_Khi[Bb*Hh*Tt*HD];
__device__ __nv_bfloat16 g_Klo[Bb*Hh*Tt*HD];
__device__ __nv_bfloat16 g_Vhi[Bb*Hh*Tt*HD];
__device__ __nv_bfloat16 g_Vlo[Bb*Hh*Tt*HD];
__device__ __nv_bfloat16 g_Vthi[Bb*Hh*Tt*HD];   // [bh][d][kv]
__device__ __nv_bfloat16 g_Vtlo[Bb*Hh*Tt*HD];
__device__ __nv_bfloat16 g_Xhi[MR*Cc];
__device__ __nv_bfloat16 g_Xlo[MR*Cc];
__device__ __nv_bfloat16 g_WAhi[3*Cc*Cc];
__device__ __nv_bfloat16 g_WAlo[3*Cc*Cc];
__device__ __nv_bfloat16 g_WPhi[Cc*Cc];
__device__ __nv_bfloat16 g_WPlo[Cc*Cc];
__device__ __nv_bfloat16 g_Yhi[MR*Cc];
__device__ __nv_bfloat16 g_Ylo[MR*Cc];

// ---------------------------------------------------------------------------
// helpers (base sm_10x-legal PTX only: cp.async / ldmatrix / mma.sync)
// ---------------------------------------------------------------------------
__device__ __forceinline__ uint32_t smem_u32(const void* p) {
    uint32_t a;
    asm("{ .reg .u64 t; cvta.to.shared.u64 t, %1; cvt.u32.u64 %0, t; }" : "=r"(a) : "l"(p));
    return a;
}

__device__ __forceinline__ void cp_async16(uint32_t s, const void* g) {
    asm volatile("cp.async.cg.shared.global [%0], [%1], 16;" :: "r"(s), "l"(g));
}
__device__ __forceinline__ void cp_commit() {
    asm volatile("cp.async.commit_group;" ::: "memory");
}

#define LDSM_X4(r, addr) \
    asm volatile("ldmatrix.sync.aligned.m8n8.x4.shared.b16 {%0,%1,%2,%3}, [%4];" \
        : "=r"((r)[0]), "=r"((r)[1]), "=r"((r)[2]), "=r"((r)[3]) : "r"(addr))

#define MMA16816(c, a, b0v, b1v) \
    asm volatile("mma.sync.aligned.m16n8k16.row.col.f32.bf16.bf16.f32 " \
        "{%0,%1,%2,%3}, {%4,%5,%6,%7}, {%8,%9}, {%0,%1,%2,%3};" \
        : "+f"((c)[0]), "+f"((c)[1]), "+f"((c)[2]), "+f"((c)[3]) \
        : "r"((a)[0]), "r"((a)[1]), "r"((a)[2]), "r"((a)[3]), "r"(b0v), "r"(b1v))

// ---------------------------------------------------------------------------
// prep kernels
// ---------------------------------------------------------------------------
__global__ void convert_x_kernel(const float4* __restrict__ x, int n4) {
    __nv_bfloat162* hi2 = (__nv_bfloat162*)g_Xhi;
    __nv_bfloat162* lo2 = (__nv_bfloat162*)g_Xlo;
    for (int i = blockIdx.x * blockDim.x + threadIdx.x; i < n4; i += gridDim.x * blockDim.x) {
        float4 v = x[i];
        __nv_bfloat16 h0 = __float2bfloat16(v.x), h1 = __float2bfloat16(v.y);
        __nv_bfloat16 h2 = __float2bfloat16(v.z), h3 = __float2bfloat16(v.w);
        __nv_bfloat162 a, b, c, d;
        a.x = h0; a.y = h1; b.x = h2; b.y = h3;
        c.x = __float2bfloat16(v.x - __bfloat162float(h0));
        c.y = __float2bfloat16(v.y - __bfloat162float(h1));
        d.x = __float2bfloat16(v.z - __bfloat162float(h2));
        d.y = __float2bfloat16(v.w - __bfloat162float(h3));
        hi2[i * 2] = a; hi2[i * 2 + 1] = b;
        lo2[i * 2] = c; lo2[i * 2 + 1] = d;
    }
}

// src [K,N] fp32 -> dst [N,K] bf16 hi/lo
__global__ void transconv_kernel(const float* __restrict__ src, __nv_bfloat16* __restrict__ dhi,
                                 __nv_bfloat16* __restrict__ dlo, int K, int N) {
    __shared__ float sm[32][33];
    int n0 = blockIdx.x * 32, k0 = blockIdx.y * 32;
    int tx = threadIdx.x, ty = threadIdx.y;   // 32 x 8
#pragma unroll
    for (int i = 0; i < 32; i += 8)
        sm[ty + i][tx] = src[(size_t)(k0 + ty + i) * N + n0 + tx];
    __syncthreads();
#pragma unroll
    for (int i = 0; i < 32; i += 8) {
        float v = sm[tx][ty + i];
        __nv_bfloat16 h = __float2bfloat16(v);
        size_t o = (size_t)(n0 + ty + i) * K + k0 + tx;
        dhi[o] = h;
        dlo[o] = __float2bfloat16(v - __bfloat162float(h));
    }
}

// V [bh][kv][d] bf16 -> Vt [bh][d][kv] bf16 (hi and lo)
__global__ void vtrans_kernel() {
    __shared__ __nv_bfloat16 th[32][33], tl[32][33];
    int kv0 = blockIdx.x * 32, d0 = blockIdx.y * 32, bh = blockIdx.z;
    int tx = threadIdx.x, ty = threadIdx.y;   // 32 x 8
    const __nv_bfloat16* sh = g_Vhi + (size_t)bh * Tt * HD;
    const __nv_bfloat16* sl = g_Vlo + (size_t)bh * Tt * HD;
    __nv_bfloat16* dh = g_Vthi + (size_t)bh * HD * Tt;
    __nv_bfloat16* dl = g_Vtlo + (size_t)bh * HD * Tt;
#pragma unroll
    for (int i = 0; i < 32; i += 8) {
        th[ty + i][tx] = sh[(size_t)(kv0 + ty + i) * HD + d0 + tx];
        tl[ty + i][tx] = sl[(size_t)(kv0 + ty + i) * HD + d0 + tx];
    }
    __syncthreads();
#pragma unroll
    for (int i = 0; i < 32; i += 8) {
        dh[(size_t)(d0 + ty + i) * Tt + kv0 + tx] = th[tx][ty + i];
        dl[(size_t)(d0 + ty + i) * Tt + kv0 + tx] = tl[tx][ty + i];
    }
}

// ---------------------------------------------------------------------------
// HMMA bf16 (hi/lo split) GEMM: CTA 128x128, 8 warps of 32x64, 256 threads,
// 2 CTAs/SM (16 warps/SM, regs<=128). BK=32, cp.async double-buffered.
// MODE 0: emit Q(0.125x)/K/V as bf16 hi/lo into [bh][t][d] arrays.
// MODE 1: row-major fp32 out [MR,Cc].
// ---------------------------------------------------------------------------
#define BK 32
#define PAD 40
#define AMATB (128*PAD*2)            // 10240 (A hi or lo)
#define BMATB (128*PAD*2)            // 10240 (B hi or lo)
#define B_OFF (2*AMATB)              // 20480
#define BUFB (2*AMATB + 2*BMATB)     // 40960
#define GSMEM (2*BUFB)               // 81920

__device__ __forceinline__ void issue_chunk(
    uint32_t sbase,
    const __nv_bfloat16* __restrict__ Ahi, const __nv_bfloat16* __restrict__ Alo,
    const __nv_bfloat16* __restrict__ Bhi, const __nv_bfloat16* __restrict__ Blo,
    int m0, int n0, int kc, int tid)
{
    // A: 128 rows x 32 cols (4 segs of 8), hi+lo ; B: same shape (256 threads)
#pragma unroll
    for (int it = 0; it < 2; it++) {
        int idx = it * 256 + tid;            // 0..511
        int row = idx >> 2, seg = idx & 3;
        uint32_t soff = (uint32_t)(row * PAD + seg * 8) * 2;
        size_t ga = (size_t)(m0 + row) * Cc + kc + seg * 8;
        size_t gb = (size_t)(n0 + row) * Cc + kc + seg * 8;
        cp_async16(sbase + soff,                 Ahi + ga);
        cp_async16(sbase + AMATB + soff,         Alo + ga);
        cp_async16(sbase + B_OFF + soff,         Bhi + gb);
        cp_async16(sbase + B_OFF + BMATB + soff, Blo + gb);
    }
    cp_commit();
}

template <int MODE>
__global__ __launch_bounds__(256, 2)
void tc_gemm(const __nv_bfloat16* __restrict__ Ahi, const __nv_bfloat16* __restrict__ Alo,
             const __nv_bfloat16* __restrict__ Bhi, const __nv_bfloat16* __restrict__ Blo,
             const float* __restrict__ bias, float* __restrict__ out) {
    extern __shared__ char smx[];
    uint32_t sb = smem_u32(smx);
    int tid = threadIdx.x;
    int lane = tid & 31, warp = tid >> 5;
    int wm = warp >> 1;         // 4 m-warps (32 rows each)
    int wn = warp & 1;          // 2 n-warps (64 cols each)
    int m0 = blockIdx.y * 128, n0 = blockIdx.x * 128;

    float acc[2][8][4] = {};    // [mt][np*2+half][frag]  (32x64 per warp)

    issue_chunk(sb, Ahi, Alo, Bhi, Blo, m0, n0, 0, tid);

    const int NCH = Cc / BK;   // 32
    int arow = wm * 32 + (lane & 15);
    int acol_base = (lane >> 4) * 8;
    int brow = wn * 64 + (lane >> 4) * 8 + (lane & 7);
    int bcol_base = ((lane >> 3) & 1) * 8;

    for (int i = 0; i < NCH; i++) {
        if (i + 1 < NCH) {
            issue_chunk(sb + ((i + 1) & 1) * BUFB, Ahi, Alo, Bhi, Blo, m0, n0, (i + 1) * BK, tid);
            asm volatile("cp.async.wait_group 1;" ::: "memory");
        } else {
            asm volatile("cp.async.wait_group 0;" ::: "memory");
        }
        __syncthreads();
        uint32_t buf = sb + (i & 1) * BUFB;

#pragma unroll
        for (int ks = 0; ks < 2; ks++) {
            int acol = ks * 16 + acol_base;
            int bcol = ks * 16 + bcol_base;
            // pass 1: hi*hi  (load ah, bh only)
            uint32_t ah[2][4];
#pragma unroll
            for (int mt = 0; mt < 2; mt++)
                LDSM_X4(ah[mt], buf + (uint32_t)((arow + mt * 16) * PAD + acol) * 2);
            uint32_t bh4[4][4];
#pragma unroll
            for (int np = 0; np < 4; np++)
                LDSM_X4(bh4[np], buf + B_OFF + (uint32_t)((brow + np * 16) * PAD + bcol) * 2);
#pragma unroll
            for (int np = 0; np < 4; np++)
#pragma unroll
                for (int mt = 0; mt < 2; mt++)
#pragma unroll
                    for (int half = 0; half < 2; half++)
                        MMA16816(acc[mt][np * 2 + half], ah[mt],
                                 bh4[np][half * 2], bh4[np][half * 2 + 1]);
            // pass 2: lo*hi  (load al; bh still live)
            {
                uint32_t al[2][4];
#pragma unroll
                for (int mt = 0; mt < 2; mt++)
                    LDSM_X4(al[mt], buf + AMATB + (uint32_t)((arow + mt * 16) * PAD + acol) * 2);
#pragma unroll
                for (int np = 0; np < 4; np++)
#pragma unroll
                    for (int mt = 0; mt < 2; mt++)
#pragma unroll
                        for (int half = 0; half < 2; half++)
                            MMA16816(acc[mt][np * 2 + half], al[mt],
                                     bh4[np][half * 2], bh4[np][half * 2 + 1]);
            }
            // pass 3: hi*lo  (load bl; al/bh dead)
            {
                uint32_t bl4[4][4];
#pragma unroll
                for (int np = 0; np < 4; np++)
                    LDSM_X4(bl4[np], buf + B_OFF + BMATB +
                                     (uint32_t)((brow + np * 16) * PAD + bcol) * 2);
#pragma unroll
                for (int np = 0; np < 4; np++)
#pragma unroll
                    for (int mt = 0; mt < 2; mt++)
#pragma unroll
                        for (int half = 0; half < 2; half++)
                            MMA16816(acc[mt][np * 2 + half], ah[mt],
                                     bl4[np][half * 2], bl4[np][half * 2 + 1]);
            }
        }
        __syncthreads();
    }

    int mrow = m0 + wm * 32 + (lane >> 2);
#pragma unroll
    for (int mt = 0; mt < 2; mt++) {
#pragma unroll
        for (int nt = 0; nt < 8; nt++) {
            int n = n0 + wn * 64 + nt * 8 + (lane & 3) * 2;
            float bx = bias[n], by = bias[n + 1];
            float2 v0 = make_float2(acc[mt][nt][0] + bx, acc[mt][nt][1] + by);
            float2 v1 = make_float2(acc[mt][nt][2] + bx, acc[mt][nt][3] + by);
            int m_a = mrow + mt * 16;
            int m_b = m_a + 8;
            if (MODE == 0) {
                int sec = n >> 10;
                int c2 = n & (Cc - 1);
                int h = c2 >> 6, d = c2 & 63;
                __nv_bfloat16 *dh, *dl;
                float scale;
                if (sec == 0)      { dh = g_Qhi; dl = g_Qlo; scale = 0.125f; }
                else if (sec == 1) { dh = g_Khi; dl = g_Klo; scale = 1.0f; }
                else               { dh = g_Vhi; dl = g_Vlo; scale = 1.0f; }
                v0.x *= scale; v0.y *= scale; v1.x *= scale; v1.y *= scale;
                int ba = m_a >> 11, ta = m_a & (Tt - 1);
                int bb2 = m_b >> 11, tb = m_b & (Tt - 1);
                size_t o0 = (((size_t)(ba * Hh + h)) * Tt + ta) * HD + d;
                size_t o1 = (((size_t)(bb2 * Hh + h)) * Tt + tb) * HD + d;
                __nv_bfloat162 hi = __floats2bfloat162_rn(v0.x, v0.y);
                __nv_bfloat162 lo = __floats2bfloat162_rn(
                    v0.x - __bfloat162float(hi.x), v0.y - __bfloat162float(hi.y));
                *(__nv_bfloat162*)&dh[o0] = hi;
                *(__nv_bfloat162*)&dl[o0] = lo;
                hi = __floats2bfloat162_rn(v1.x, v1.y);
                lo = __floats2bfloat162_rn(
                    v1.x - __bfloat162float(hi.x), v1.y - __bfloat162float(hi.y));
                *(__nv_bfloat162*)&dh[o1] = hi;
                *(__nv_bfloat162*)&dl[o1] = lo;
            } else {
                *(float2*)&out[(size_t)m_a * Cc + n] = v0;
                *(float2*)&out[(size_t)m_b * Cc + n] = v1;
            }
        }
    }
}

// ---------------------------------------------------------------------------
// Tensor-core flash attention, bf16 hi/lo split (3-term), Bq=128, Bk=64,
// 128 threads (4 warps x 32 q-rows, 2 m-tiles each). 2 CTAs/SM.
// ---------------------------------------------------------------------------
#define BQ 128
#define APAD 72
#define QMAT (BQ*APAD)               // Q matrix elems (hi or lo)
#define KMAT (64*APAD)               // K/V matrix elems
#define ASMEM ((2*QMAT + 4*KMAT)*2)  // 73728 B

__global__ __launch_bounds__(128, 2) void attn_tc() {
    extern __shared__ __nv_bfloat16 sa[];
    __nv_bfloat16* Qh = sa;
    __nv_bfloat16* Ql = sa + QMAT;
    __nv_bfloat16* Kh = sa + 2 * QMAT;
    __nv_bfloat16* Kl = sa + 2 * QMAT + KMAT;
    __nv_bfloat16* Vh = sa + 2 * QMAT + 2 * KMAT;
    __nv_bfloat16* Vl = sa + 2 * QMAT + 3 * KMAT;
    uint32_t sQh = smem_u32(Qh), sQl = smem_u32(Ql);
    uint32_t sKh = smem_u32(Kh), sKl = smem_u32(Kl);
    uint32_t sVh = smem_u32(Vh), sVl = smem_u32(Vl);

    int tid = threadIdx.x;
    int lane = tid & 31, w = tid >> 5;
    int bh = blockIdx.y;
    int qtile = (gridDim.x - 1) - blockIdx.x;    // heavy tiles first
    int q0 = qtile * BQ;

    const __nv_bfloat16* gQh = g_Qhi + (size_t)bh * Tt * HD;
    const __nv_bfloat16* gQl = g_Qlo + (size_t)bh * Tt * HD;
    const __nv_bfloat16* gKh = g_Khi + (size_t)bh * Tt * HD;
    const __nv_bfloat16* gKl = g_Klo + (size_t)bh * Tt * HD;
    const __nv_bfloat16* gVh = g_Vthi + (size_t)bh * HD * Tt;
    const __nv_bfloat16* gVl = g_Vtlo + (size_t)bh * HD * Tt;

    // load Q tile (128 x 64), hi+lo
#pragma unroll
    for (int it = 0; it < 8; it++) {
        int idx = it * 128 + tid;
        int row = idx >> 3, seg = idx & 7;
        uint32_t so = (uint32_t)(row * APAD + seg * 8) * 2;
        size_t go = (size_t)(q0 + row) * HD + seg * 8;
        cp_async16(sQh + so, gQh + go);
        cp_async16(sQl + so, gQl + go);
    }
    cp_commit();

    float o[2][8][4] = {};
    float mrow[2][2] = {{-1e30f, -1e30f}, {-1e30f, -1e30f}};
    float lrow[2][2] = {};

    int r0 = lane >> 2;

    int ktmax = 2 * qtile + 1;
    for (int kt = 0; kt <= ktmax; kt++) {
        int kv0 = kt * 64;
        __syncthreads();
#pragma unroll
        for (int it = 0; it < 4; it++) {
            int idx = it * 128 + tid;
            int row = idx >> 3, seg = idx & 7;
            uint32_t so = (uint32_t)(row * APAD + seg * 8) * 2;
            size_t gk = (size_t)(kv0 + row) * HD + seg * 8;
            size_t gv = (size_t)row * Tt + kv0 + seg * 8;   // row = d
            cp_async16(sKh + so, gKh + gk);
            cp_async16(sKl + so, gKl + gk);
            cp_async16(sVh + so, gVh + gv);
            cp_async16(sVl + so, gVl + gv);
        }
        cp_commit();
        asm volatile("cp.async.wait_group 0;" ::: "memory");
        __syncthreads();

        // ---- S = Q K^T  (3-term split, liveness-ordered passes) ----
        float s[2][8][4] = {};
#pragma unroll
        for (int ks = 0; ks < 4; ks++) {
            uint32_t aq_h[2][4];
#pragma unroll
            for (int mt = 0; mt < 2; mt++)
                LDSM_X4(aq_h[mt], sQh + (uint32_t)((w * 32 + mt * 16 + (lane & 15)) * APAD +
                                                   ks * 16 + (lane >> 4) * 8) * 2);
            uint32_t bkh[4][4];
#pragma unroll
            for (int ntp = 0; ntp < 4; ntp++)
                LDSM_X4(bkh[ntp], sKh + (uint32_t)((ntp * 16 + (lane >> 4) * 8 + (lane & 7)) * APAD +
                                                   ks * 16 + ((lane >> 3) & 1) * 8) * 2);
#pragma unroll
            for (int ntp = 0; ntp < 4; ntp++)
#pragma unroll
                for (int mt = 0; mt < 2; mt++)
#pragma unroll
                    for (int h2 = 0; h2 < 2; h2++)
                        MMA16816(s[mt][ntp * 2 + h2], aq_h[mt],
                                 bkh[ntp][h2 * 2], bkh[ntp][h2 * 2 + 1]);
            {
                uint32_t aq_l[2][4];
#pragma unroll
                for (int mt = 0; mt < 2; mt++)
                    LDSM_X4(aq_l[mt], sQl + (uint32_t)((w * 32 + mt * 16 + (lane & 15)) * APAD +
                                                       ks * 16 + (lane >> 4) * 8) * 2);
#pragma unroll
                for (int ntp = 0; ntp < 4; ntp++)
#pragma unroll
                    for (int mt = 0; mt < 2; mt++)
#pragma unroll
                        for (int h2 = 0; h2 < 2; h2++)
                            MMA16816(s[mt][ntp * 2 + h2], aq_l[mt],
                                     bkh[ntp][h2 * 2], bkh[ntp][h2 * 2 + 1]);
            }
            {
                uint32_t bkl[4][4];
#pragma unroll
                for (int ntp = 0; ntp < 4; ntp++)
                    LDSM_X4(bkl[ntp], sKl + (uint32_t)((ntp * 16 + (lane >> 4) * 8 + (lane & 7)) * APAD +
                                                       ks * 16 + ((lane >> 3) & 1) * 8) * 2);
#pragma unroll
                for (int ntp = 0; ntp < 4; ntp++)
#pragma unroll
                    for (int mt = 0; mt < 2; mt++)
#pragma unroll
                        for (int h2 = 0; h2 < 2; h2++)
                            MMA16816(s[mt][ntp * 2 + h2], aq_h[mt],
                                     bkl[ntp][h2 * 2], bkl[ntp][h2 * 2 + 1]);
            }
        }

        // causal mask (only tiles near/above the warp's diagonal need it)
        if (kv0 + 63 > q0 + w * 32) {
#pragma unroll
            for (int mt = 0; mt < 2; mt++)
#pragma unroll
                for (int nt = 0; nt < 8; nt++)
#pragma unroll
                    for (int j = 0; j < 4; j++) {
                        int c = kv0 + nt * 8 + (lane & 3) * 2 + (j & 1);
                        int r = q0 + w * 32 + mt * 16 + r0 + ((j >> 1) ? 8 : 0);
                        if (c > r) s[mt][nt][j] = -1e30f;
                    }
        }

        // ---- online softmax (4 row groups: mt x rr) ----
#pragma unroll
        for (int mt = 0; mt < 2; mt++)
#pragma unroll
            for (int rr = 0; rr < 2; rr++) {
                float rm = -1e30f;
#pragma unroll
                for (int nt = 0; nt < 8; nt++)
                    rm = fmaxf(rm, fmaxf(s[mt][nt][rr * 2], s[mt][nt][rr * 2 + 1]));
                rm = fmaxf(rm, __shfl_xor_sync(0xffffffffu, rm, 1));
                rm = fmaxf(rm, __shfl_xor_sync(0xffffffffu, rm, 2));
                float mnew = fmaxf(mrow[mt][rr], rm);
                float alpha = __expf(mrow[mt][rr] - mnew);
                mrow[mt][rr] = mnew;
                float rs = 0.0f;
#pragma unroll
                for (int nt = 0; nt < 8; nt++) {
                    s[mt][nt][rr * 2]     = __expf(s[mt][nt][rr * 2] - mnew);
                    s[mt][nt][rr * 2 + 1] = __expf(s[mt][nt][rr * 2 + 1] - mnew);
                    rs += s[mt][nt][rr * 2] + s[mt][nt][rr * 2 + 1];
                }
                rs += __shfl_xor_sync(0xffffffffu, rs, 1);
                rs += __shfl_xor_sync(0xffffffffu, rs, 2);
                lrow[mt][rr] = lrow[mt][rr] * alpha + rs;
#pragma unroll
                for (int dt = 0; dt < 8; dt++) {
                    o[mt][dt][rr * 2]     *= alpha;
                    o[mt][dt][rr * 2 + 1] *= alpha;
                }
            }

        // ---- O += P V  (P from regs; V frags shared across mt) ----
#pragma unroll
        for (int ksv = 0; ksv < 4; ksv++) {
            uint32_t pah[2][4], pal[2][4];
#pragma unroll
            for (int mt = 0; mt < 2; mt++)
#pragma unroll
                for (int q = 0; q < 4; q++) {
                    int nt = 2 * ksv + (q >> 1);
                    int j0 = (q & 1) * 2;
                    float x = s[mt][nt][j0], y = s[mt][nt][j0 + 1];
                    __nv_bfloat162 hv = __floats2bfloat162_rn(x, y);
                    __nv_bfloat162 lv = __floats2bfloat162_rn(
                        x - __bfloat162float(hv.x), y - __bfloat162float(hv.y));
                    pah[mt][q] = *(uint32_t*)&hv;
                    pal[mt][q] = *(uint32_t*)&lv;
                }
            uint32_t bvh[4][4];
#pragma unroll
            for (int dtp = 0; dtp < 4; dtp++)
                LDSM_X4(bvh[dtp], sVh + (uint32_t)((dtp * 16 + (lane >> 4) * 8 + (lane & 7)) * APAD +
                                                   ksv * 16 + ((lane >> 3) & 1) * 8) * 2);
#pragma unroll
            for (int dtp = 0; dtp < 4; dtp++)
#pragma unroll
                for (int mt = 0; mt < 2; mt++)
#pragma unroll
                    for (int h2 = 0; h2 < 2; h2++)
                        MMA16816(o[mt][dtp * 2 + h2], pah[mt],
                                 bvh[dtp][h2 * 2], bvh[dtp][h2 * 2 + 1]);
#pragma unroll
            for (int dtp = 0; dtp < 4; dtp++)
#pragma unroll
                for (int mt = 0; mt < 2; mt++)
#pragma unroll
                    for (int h2 = 0; h2 < 2; h2++)
                        MMA16816(o[mt][dtp * 2 + h2], pal[mt],
                                 bvh[dtp][h2 * 2], bvh[dtp][h2 * 2 + 1]);
            {
                uint32_t bvl[4][4];
#pragma unroll
                for (int dtp = 0; dtp < 4; dtp++)
                    LDSM_X4(bvl[dtp], sVl + (uint32_t)((dtp * 16 + (lane >> 4) * 8 + (lane & 7)) * APAD +
                                                       ksv * 16 + ((lane >> 3) & 1) * 8) * 2);
#pragma unroll
                for (int dtp = 0; dtp < 4; dtp++)
#pragma unroll
                    for (int mt = 0; mt < 2; mt++)
#pragma unroll
                        for (int h2 = 0; h2 < 2; h2++)
                            MMA16816(o[mt][dtp * 2 + h2], pah[mt],
                                     bvl[dtp][h2 * 2], bvl[dtp][h2 * 2 + 1]);
            }
        }
    }

    // ---- epilogue: normalize, emit Y as bf16 hi/lo [B,T,C] ----
    int b = bh >> 4, h = bh & 15;
#pragma unroll
    for (int mt = 0; mt < 2; mt++) {
        float inv0 = 1.0f / lrow[mt][0];
        float inv1 = 1.0f / lrow[mt][1];
        int gq0 = q0 + w * 32 + mt * 16 + r0;
        int gq1 = gq0 + 8;
#pragma unroll
        for (int dt = 0; dt < 8; dt++) {
            int col = h * HD + dt * 8 + (lane & 3) * 2;
            size_t o0 = (size_t)(b * Tt + gq0) * Cc + col;
            size_t o1 = (size_t)(b * Tt + gq1) * Cc + col;
            float y0 = o[mt][dt][0] * inv0, y1 = o[mt][dt][1] * inv0;
            float y2 = o[mt][dt][2] * inv1, y3 = o[mt][dt][3] * inv1;
            __nv_bfloat162 hv = __floats2bfloat162_rn(y0, y1);
            __nv_bfloat162 lv = __floats2bfloat162_rn(
                y0 - __bfloat162float(hv.x), y1 - __bfloat162float(hv.y));
            *(__nv_bfloat162*)&g_Yhi[o0] = hv;
            *(__nv_bfloat162*)&g_Ylo[o0] = lv;
            hv = __floats2bfloat162_rn(y2, y3);
            lv = __floats2bfloat162_rn(
                y2 - __bfloat162float(hv.x), y3 - __bfloat162float(hv.y));
            *(__nv_bfloat162*)&g_Yhi[o1] = hv;
            *(__nv_bfloat162*)&g_Ylo[o1] = lv;
        }
    }
}

// ---------------------------------------------------------------------------
extern "C" void kernel_launch(void* const* d_in, const int* in_sizes, int n_in,
                              void* d_out, int out_size) {
    const float* x      = (const float*)d_in[0];
    const float* W_attn = (const float*)d_in[1];
    const float* b_attn = (const float*)d_in[2];
    const float* W_proj = (const float*)d_in[3];
    const float* b_proj = (const float*)d_in[4];
    float* out = (float*)d_out;

    __nv_bfloat16 *xhi, *xlo, *wahi, *walo, *wphi, *wplo, *yhi, *ylo;
    cudaGetSymbolAddress((void**)&xhi,  g_Xhi);
    cudaGetSymbolAddress((void**)&xlo,  g_Xlo);
    cudaGetSymbolAddress((void**)&wahi, g_WAhi);
    cudaGetSymbolAddress((void**)&walo, g_WAlo);
    cudaGetSymbolAddress((void**)&wphi, g_WPhi);
    cudaGetSymbolAddress((void**)&wplo, g_WPlo);
    cudaGetSymbolAddress((void**)&yhi,  g_Yhi);
    cudaGetSymbolAddress((void**)&ylo,  g_Ylo);

    cudaFuncSetAttribute(tc_gemm<0>, cudaFuncAttributeMaxDynamicSharedMemorySize, GSMEM);
    cudaFuncSetAttribute(tc_gemm<1>, cudaFuncAttributeMaxDynamicSharedMemorySize, GSMEM);
    cudaFuncSetAttribute(attn_tc, cudaFuncAttributeMaxDynamicSharedMemorySize, ASMEM);

    convert_x_kernel<<<1024, 256>>>((const float4*)x, MR * Cc / 4);
    transconv_kernel<<<dim3(3 * Cc / 32, Cc / 32), dim3(32, 8)>>>(W_attn, wahi, walo, Cc, 3 * Cc);
    transconv_kernel<<<dim3(Cc / 32, Cc / 32), dim3(32, 8)>>>(W_proj, wphi, wplo, Cc, Cc);

    tc_gemm<0><<<dim3(3 * Cc / 128, MR / 128), 256, GSMEM>>>(xhi, xlo, wahi, walo, b_attn, nullptr);

    vtrans_kernel<<<dim3(Tt / 32, HD / 32, Bb * Hh), dim3(32, 8)>>>();

    attn_tc<<<dim3(Tt / BQ, Bb * Hh), 128, ASMEM>>>();

    tc_gemm<1><<<dim3(Cc / 128, MR / 128), 256, GSMEM>>>(yhi, ylo, wphi, wplo, b_proj, out);
}

// round 10
// speedup vs baseline: 1.4155x; 1.4155x over previous
#include <cuda_runtime.h>
#include <cuda_fp16.h>
#include <cstdint>

#define Bb 4
#define Tt 2048
#define Cc 1024
#define Hh 16
#define HD 64
#define MR (Bb*Tt)      // 8192 rows

// ---------------------------------------------------------------------------
// device scratch (allocation-free rule)
// ---------------------------------------------------------------------------
__device__ __half g_Qhi[Bb*Hh*Tt*HD];
__device__ __half g_Qlo[Bb*Hh*Tt*HD];
__device__ __half g_K  [Bb*Hh*Tt*HD];
__device__ __half g_V  [Bb*Hh*Tt*HD];
__device__ __half g_Vt [Bb*Hh*Tt*HD];    // [bh][d][kv]
__device__ __half g_Xhi[MR*Cc];
__device__ __half g_Xlo[MR*Cc];
__device__ __half g_WA [3*Cc*Cc];        // [N,K] single fp16
__device__ __half g_WP [Cc*Cc];
__device__ __half g_Yhi[MR*Cc];
__device__ __half g_Ylo[MR*Cc];

// ---------------------------------------------------------------------------
// helpers (base sm_10x-legal PTX only: cp.async / ldmatrix / mma.sync)
// ---------------------------------------------------------------------------
__device__ __forceinline__ uint32_t smem_u32(const void* p) {
    uint32_t a;
    asm("{ .reg .u64 t; cvta.to.shared.u64 t, %1; cvt.u32.u64 %0, t; }" : "=r"(a) : "l"(p));
    return a;
}

__device__ __forceinline__ void cp_async16(uint32_t s, const void* g) {
    asm volatile("cp.async.cg.shared.global [%0], [%1], 16;" :: "r"(s), "l"(g));
}
__device__ __forceinline__ void cp_commit() {
    asm volatile("cp.async.commit_group;" ::: "memory");
}

#define LDSM_X4(r, addr) \
    asm volatile("ldmatrix.sync.aligned.m8n8.x4.shared.b16 {%0,%1,%2,%3}, [%4];" \
        : "=r"((r)[0]), "=r"((r)[1]), "=r"((r)[2]), "=r"((r)[3]) : "r"(addr))

#define MMA16816(c, a, b0v, b1v) \
    asm volatile("mma.sync.aligned.m16n8k16.row.col.f32.f16.f16.f32 " \
        "{%0,%1,%2,%3}, {%4,%5,%6,%7}, {%8,%9}, {%0,%1,%2,%3};" \
        : "+f"((c)[0]), "+f"((c)[1]), "+f"((c)[2]), "+f"((c)[3]) \
        : "r"((a)[0]), "r"((a)[1]), "r"((a)[2]), "r"((a)[3]), "r"(b0v), "r"(b1v))

// ---------------------------------------------------------------------------
// prep kernels
// ---------------------------------------------------------------------------
__global__ void convert_x_kernel(const float4* __restrict__ x, int n4) {
    __half2* hi2 = (__half2*)g_Xhi;
    __half2* lo2 = (__half2*)g_Xlo;
    for (int i = blockIdx.x * blockDim.x + threadIdx.x; i < n4; i += gridDim.x * blockDim.x) {
        float4 v = x[i];
        __half2 a = __floats2half2_rn(v.x, v.y);
        __half2 b = __floats2half2_rn(v.z, v.w);
        __half2 c = __floats2half2_rn(v.x - __half2float(a.x), v.y - __half2float(a.y));
        __half2 d = __floats2half2_rn(v.z - __half2float(b.x), v.w - __half2float(b.y));
        hi2[i * 2] = a; hi2[i * 2 + 1] = b;
        lo2[i * 2] = c; lo2[i * 2 + 1] = d;
    }
}

// src [K,N] fp32 -> dst [N,K] single fp16
__global__ void transconv_kernel(const float* __restrict__ src, __half* __restrict__ dst,
                                 int K, int N) {
    __shared__ float sm[32][33];
    int n0 = blockIdx.x * 32, k0 = blockIdx.y * 32;
    int tx = threadIdx.x, ty = threadIdx.y;   // 32 x 8
#pragma unroll
    for (int i = 0; i < 32; i += 8)
        sm[ty + i][tx] = src[(size_t)(k0 + ty + i) * N + n0 + tx];
    __syncthreads();
#pragma unroll
    for (int i = 0; i < 32; i += 8)
        dst[(size_t)(n0 + ty + i) * K + k0 + tx] = __float2half(sm[tx][ty + i]);
}

// V [bh][kv][d] -> Vt [bh][d][kv] (single fp16)
__global__ void vtrans_kernel() {
    __shared__ __half th[32][33];
    int kv0 = blockIdx.x * 32, d0 = blockIdx.y * 32, bh = blockIdx.z;
    int tx = threadIdx.x, ty = threadIdx.y;   // 32 x 8
    const __half* sh = g_V + (size_t)bh * Tt * HD;
    __half* dh = g_Vt + (size_t)bh * HD * Tt;
#pragma unroll
    for (int i = 0; i < 32; i += 8)
        th[ty + i][tx] = sh[(size_t)(kv0 + ty + i) * HD + d0 + tx];
    __syncthreads();
#pragma unroll
    for (int i = 0; i < 32; i += 8)
        dh[(size_t)(d0 + ty + i) * Tt + kv0 + tx] = th[tx][ty + i];
}

// ---------------------------------------------------------------------------
// HMMA fp16 GEMM, A split hi/lo (2 MMA terms), B single fp16.
// CTA 128x128, 4 warps of 64x64, 128 threads, 2 CTAs/SM, BK=32, x2 buffered.
// MODE 0: emit Qhi/Qlo(0.125x), K, V (fp16) into [bh][t][d].
// MODE 1: row-major fp32 out [MR,Cc].
// ---------------------------------------------------------------------------
#define BK 32
#define PAD 40
#define MATB (128*PAD*2)             // 10240 per matrix (Ahi | Alo | B)
#define BUFB (3*MATB)                // 30720
#define GSMEM (2*BUFB)               // 61440

__device__ __forceinline__ void issue_chunk(
    uint32_t sbase,
    const __half* __restrict__ Ahi, const __half* __restrict__ Alo,
    const __half* __restrict__ Bm,
    int m0, int n0, int kc, int tid)
{
#pragma unroll
    for (int it = 0; it < 4; it++) {
        int idx = it * 128 + tid;            // 0..511
        int row = idx >> 2, seg = idx & 3;
        uint32_t soff = (uint32_t)(row * PAD + seg * 8) * 2;
        size_t ga = (size_t)(m0 + row) * Cc + kc + seg * 8;
        size_t gb = (size_t)(n0 + row) * Cc + kc + seg * 8;
        cp_async16(sbase + soff,            Ahi + ga);
        cp_async16(sbase + MATB + soff,     Alo + ga);
        cp_async16(sbase + 2 * MATB + soff, Bm + gb);
    }
    cp_commit();
}

template <int MODE>
__global__ __launch_bounds__(128, 2)
void tc_gemm(const __half* __restrict__ Ahi, const __half* __restrict__ Alo,
             const __half* __restrict__ Bm,
             const float* __restrict__ bias, float* __restrict__ out) {
    extern __shared__ char smx[];
    uint32_t sb = smem_u32(smx);
    int tid = threadIdx.x;
    int lane = tid & 31, warp = tid >> 5;
    int wm = warp >> 1;         // 2 m-warps (64 rows each)
    int wn = warp & 1;          // 2 n-warps (64 cols each)
    int m0 = blockIdx.y * 128, n0 = blockIdx.x * 128;

    float acc[4][8][4] = {};    // 64x64 per warp

    issue_chunk(sb, Ahi, Alo, Bm, m0, n0, 0, tid);

    const int NCH = Cc / BK;   // 32
    int arow = wm * 64 + (lane & 15);
    int acol_base = (lane >> 4) * 8;
    int brow = wn * 64 + (lane >> 4) * 8 + (lane & 7);
    int bcol_base = ((lane >> 3) & 1) * 8;

    for (int i = 0; i < NCH; i++) {
        if (i + 1 < NCH) {
            issue_chunk(sb + ((i + 1) & 1) * BUFB, Ahi, Alo, Bm, m0, n0, (i + 1) * BK, tid);
            asm volatile("cp.async.wait_group 1;" ::: "memory");
        } else {
            asm volatile("cp.async.wait_group 0;" ::: "memory");
        }
        __syncthreads();
        uint32_t buf = sb + (i & 1) * BUFB;

#pragma unroll
        for (int ks = 0; ks < 2; ks++) {
            int acol = ks * 16 + acol_base;
            int bcol = ks * 16 + bcol_base;
            // pass 1: Ah * B
            uint32_t ah[4][4], bf4[4][4];
#pragma unroll
            for (int mt = 0; mt < 4; mt++)
                LDSM_X4(ah[mt], buf + (uint32_t)((arow + mt * 16) * PAD + acol) * 2);
#pragma unroll
            for (int np = 0; np < 4; np++)
                LDSM_X4(bf4[np], buf + 2 * MATB + (uint32_t)((brow + np * 16) * PAD + bcol) * 2);
#pragma unroll
            for (int np = 0; np < 4; np++)
#pragma unroll
                for (int mt = 0; mt < 4; mt++)
#pragma unroll
                    for (int half = 0; half < 2; half++)
                        MMA16816(acc[mt][np * 2 + half], ah[mt],
                                 bf4[np][half * 2], bf4[np][half * 2 + 1]);
            // pass 2: Al * B (load al just-in-time; ah dead)
            {
                uint32_t al[4][4];
#pragma unroll
                for (int mt = 0; mt < 4; mt++)
                    LDSM_X4(al[mt], buf + MATB + (uint32_t)((arow + mt * 16) * PAD + acol) * 2);
#pragma unroll
                for (int np = 0; np < 4; np++)
#pragma unroll
                    for (int mt = 0; mt < 4; mt++)
#pragma unroll
                        for (int half = 0; half < 2; half++)
                            MMA16816(acc[mt][np * 2 + half], al[mt],
                                     bf4[np][half * 2], bf4[np][half * 2 + 1]);
            }
        }
        __syncthreads();
    }

    int mrow = m0 + wm * 64 + (lane >> 2);
#pragma unroll
    for (int mt = 0; mt < 4; mt++) {
#pragma unroll
        for (int nt = 0; nt < 8; nt++) {
            int n = n0 + wn * 64 + nt * 8 + (lane & 3) * 2;
            float bx = bias[n], by = bias[n + 1];
            float2 v0 = make_float2(acc[mt][nt][0] + bx, acc[mt][nt][1] + by);
            float2 v1 = make_float2(acc[mt][nt][2] + bx, acc[mt][nt][3] + by);
            int m_a = mrow + mt * 16;
            int m_b = m_a + 8;
            if (MODE == 0) {
                int sec = n >> 10;
                int c2 = n & (Cc - 1);
                int h = c2 >> 6, d = c2 & 63;
                int ba = m_a >> 11, ta = m_a & (Tt - 1);
                int bb2 = m_b >> 11, tb = m_b & (Tt - 1);
                size_t o0 = (((size_t)(ba * Hh + h)) * Tt + ta) * HD + d;
                size_t o1 = (((size_t)(bb2 * Hh + h)) * Tt + tb) * HD + d;
                if (sec == 0) {
                    v0.x *= 0.125f; v0.y *= 0.125f; v1.x *= 0.125f; v1.y *= 0.125f;
                    __half2 hi = __floats2half2_rn(v0.x, v0.y);
                    __half2 lo = __floats2half2_rn(v0.x - __half2float(hi.x),
                                                   v0.y - __half2float(hi.y));
                    *(__half2*)&g_Qhi[o0] = hi;
                    *(__half2*)&g_Qlo[o0] = lo;
                    hi = __floats2half2_rn(v1.x, v1.y);
                    lo = __floats2half2_rn(v1.x - __half2float(hi.x),
                                           v1.y - __half2float(hi.y));
                    *(__half2*)&g_Qhi[o1] = hi;
                    *(__half2*)&g_Qlo[o1] = lo;
                } else {
                    __half* dst = (sec == 1) ? g_K : g_V;
                    *(__half2*)&dst[o0] = __floats2half2_rn(v0.x, v0.y);
                    *(__half2*)&dst[o1] = __floats2half2_rn(v1.x, v1.y);
                }
            } else {
                *(float2*)&out[(size_t)m_a * Cc + n] = v0;
                *(float2*)&out[(size_t)m_b * Cc + n] = v1;
            }
        }
    }
}

// ---------------------------------------------------------------------------
// Tensor-core flash attention, fp16: Q split hi/lo + K single (2-term S),
// P split from regs + V single (2-term PV). Bq=128, Bk=64, 128 threads.
// ---------------------------------------------------------------------------
#define BQ 128
#define APAD 72
#define QMAT (BQ*APAD)
#define KMAT (64*APAD)
#define ASMEM ((2*QMAT + 2*KMAT)*2)  // 55296 B

__global__ __launch_bounds__(128, 2) void attn_tc() {
    extern __shared__ __half sa[];
    __half* Qh = sa;
    __half* Ql = sa + QMAT;
    __half* Kh = sa + 2 * QMAT;
    __half* Vh = sa + 2 * QMAT + KMAT;
    uint32_t sQh = smem_u32(Qh), sQl = smem_u32(Ql);
    uint32_t sKh = smem_u32(Kh), sVh = smem_u32(Vh);

    int tid = threadIdx.x;
    int lane = tid & 31, w = tid >> 5;
    int bh = blockIdx.y;
    int qtile = (gridDim.x - 1) - blockIdx.x;    // heavy tiles first
    int q0 = qtile * BQ;

    const __half* gQh = g_Qhi + (size_t)bh * Tt * HD;
    const __half* gQl = g_Qlo + (size_t)bh * Tt * HD;
    const __half* gK  = g_K  + (size_t)bh * Tt * HD;
    const __half* gV  = g_Vt + (size_t)bh * HD * Tt;

    // load Q tile (128 x 64), hi+lo
#pragma unroll
    for (int it = 0; it < 8; it++) {
        int idx = it * 128 + tid;
        int row = idx >> 3, seg = idx & 7;
        uint32_t so = (uint32_t)(row * APAD + seg * 8) * 2;
        size_t go = (size_t)(q0 + row) * HD + seg * 8;
        cp_async16(sQh + so, gQh + go);
        cp_async16(sQl + so, gQl + go);
    }
    cp_commit();

    float o[2][8][4] = {};
    float mrow[2][2] = {{-1e30f, -1e30f}, {-1e30f, -1e30f}};
    float lrow[2][2] = {};

    int r0 = lane >> 2;

    int ktmax = 2 * qtile + 1;
    for (int kt = 0; kt <= ktmax; kt++) {
        int kv0 = kt * 64;
        __syncthreads();
#pragma unroll
        for (int it = 0; it < 4; it++) {
            int idx = it * 128 + tid;
            int row = idx >> 3, seg = idx & 7;
            uint32_t so = (uint32_t)(row * APAD + seg * 8) * 2;
            size_t gk = (size_t)(kv0 + row) * HD + seg * 8;
            size_t gv = (size_t)row * Tt + kv0 + seg * 8;   // row = d
            cp_async16(sKh + so, gK + gk);
            cp_async16(sVh + so, gV + gv);
        }
        cp_commit();
        asm volatile("cp.async.wait_group 0;" ::: "memory");
        __syncthreads();

        // ---- S = Q K^T  (Qh·K then Ql·K) ----
        float s[2][8][4] = {};
#pragma unroll
        for (int ks = 0; ks < 4; ks++) {
            uint32_t aq_h[2][4], bk[4][4];
#pragma unroll
            for (int mt = 0; mt < 2; mt++)
                LDSM_X4(aq_h[mt], sQh + (uint32_t)((w * 32 + mt * 16 + (lane & 15)) * APAD +
                                                   ks * 16 + (lane >> 4) * 8) * 2);
#pragma unroll
            for (int ntp = 0; ntp < 4; ntp++)
                LDSM_X4(bk[ntp], sKh + (uint32_t)((ntp * 16 + (lane >> 4) * 8 + (lane & 7)) * APAD +
                                                  ks * 16 + ((lane >> 3) & 1) * 8) * 2);
#pragma unroll
            for (int ntp = 0; ntp < 4; ntp++)
#pragma unroll
                for (int mt = 0; mt < 2; mt++)
#pragma unroll
                    for (int h2 = 0; h2 < 2; h2++)
                        MMA16816(s[mt][ntp * 2 + h2], aq_h[mt],
                                 bk[ntp][h2 * 2], bk[ntp][h2 * 2 + 1]);
            {
                uint32_t aq_l[2][4];
#pragma unroll
                for (int mt = 0; mt < 2; mt++)
                    LDSM_X4(aq_l[mt], sQl + (uint32_t)((w * 32 + mt * 16 + (lane & 15)) * APAD +
                                                       ks * 16 + (lane >> 4) * 8) * 2);
#pragma unroll
                for (int ntp = 0; ntp < 4; ntp++)
#pragma unroll
                    for (int mt = 0; mt < 2; mt++)
#pragma unroll
                        for (int h2 = 0; h2 < 2; h2++)
                            MMA16816(s[mt][ntp * 2 + h2], aq_l[mt],
                                     bk[ntp][h2 * 2], bk[ntp][h2 * 2 + 1]);
            }
        }

        // causal mask
        if (kv0 + 63 > q0 + w * 32) {
#pragma unroll
            for (int mt = 0; mt < 2; mt++)
#pragma unroll
                for (int nt = 0; nt < 8; nt++)
#pragma unroll
                    for (int j = 0; j < 4; j++) {
                        int c = kv0 + nt * 8 + (lane & 3) * 2 + (j & 1);
                        int r = q0 + w * 32 + mt * 16 + r0 + ((j >> 1) ? 8 : 0);
                        if (c > r) s[mt][nt][j] = -1e30f;
                    }
        }

        // ---- online softmax ----
#pragma unroll
        for (int mt = 0; mt < 2; mt++)
#pragma unroll
            for (int rr = 0; rr < 2; rr++) {
                float rm = -1e30f;
#pragma unroll
                for (int nt = 0; nt < 8; nt++)
                    rm = fmaxf(rm, fmaxf(s[mt][nt][rr * 2], s[mt][nt][rr * 2 + 1]));
                rm = fmaxf(rm, __shfl_xor_sync(0xffffffffu, rm, 1));
                rm = fmaxf(rm, __shfl_xor_sync(0xffffffffu, rm, 2));
                float mnew = fmaxf(mrow[mt][rr], rm);
                float alpha = __expf(mrow[mt][rr] - mnew);
                mrow[mt][rr] = mnew;
                float rs = 0.0f;
#pragma unroll
                for (int nt = 0; nt < 8; nt++) {
                    s[mt][nt][rr * 2]     = __expf(s[mt][nt][rr * 2] - mnew);
                    s[mt][nt][rr * 2 + 1] = __expf(s[mt][nt][rr * 2 + 1] - mnew);
                    rs += s[mt][nt][rr * 2] + s[mt][nt][rr * 2 + 1];
                }
                rs += __shfl_xor_sync(0xffffffffu, rs, 1);
                rs += __shfl_xor_sync(0xffffffffu, rs, 2);
                lrow[mt][rr] = lrow[mt][rr] * alpha + rs;
#pragma unroll
                for (int dt = 0; dt < 8; dt++) {
                    o[mt][dt][rr * 2]     *= alpha;
                    o[mt][dt][rr * 2 + 1] *= alpha;
                }
            }

        // ---- O += P V  (Ph·V then Pl·V; V single) ----
#pragma unroll
        for (int ksv = 0; ksv < 4; ksv++) {
            uint32_t pah[2][4], pal[2][4];
#pragma unroll
            for (int mt = 0; mt < 2; mt++)
#pragma unroll
                for (int q = 0; q < 4; q++) {
                    int nt = 2 * ksv + (q >> 1);
                    int j0 = (q & 1) * 2;
                    float x = s[mt][nt][j0], y = s[mt][nt][j0 + 1];
                    __half2 hv = __floats2half2_rn(x, y);
                    __half2 lv = __floats2half2_rn(x - __half2float(hv.x),
                                                   y - __half2float(hv.y));
                    pah[mt][q] = *(uint32_t*)&hv;
                    pal[mt][q] = *(uint32_t*)&lv;
                }
            uint32_t bv[4][4];
#pragma unroll
            for (int dtp = 0; dtp < 4; dtp++)
                LDSM_X4(bv[dtp], sVh + (uint32_t)((dtp * 16 + (lane >> 4) * 8 + (lane & 7)) * APAD +
                                                  ksv * 16 + ((lane >> 3) & 1) * 8) * 2);
#pragma unroll
            for (int dtp = 0; dtp < 4; dtp++)
#pragma unroll
                for (int mt = 0; mt < 2; mt++)
#pragma unroll
                    for (int h2 = 0; h2 < 2; h2++)
                        MMA16816(o[mt][dtp * 2 + h2], pah[mt],
                                 bv[dtp][h2 * 2], bv[dtp][h2 * 2 + 1]);
#pragma unroll
            for (int dtp = 0; dtp < 4; dtp++)
#pragma unroll
                for (int mt = 0; mt < 2; mt++)
#pragma unroll
                    for (int h2 = 0; h2 < 2; h2++)
                        MMA16816(o[mt][dtp * 2 + h2], pal[mt],
                                 bv[dtp][h2 * 2], bv[dtp][h2 * 2 + 1]);
        }
    }

    // ---- epilogue: normalize, emit Y as fp16 hi/lo [B,T,C] ----
    int b = bh >> 4, h = bh & 15;
#pragma unroll
    for (int mt = 0; mt < 2; mt++) {
        float inv0 = 1.0f / lrow[mt][0];
        float inv1 = 1.0f / lrow[mt][1];
        int gq0 = q0 + w * 32 + mt * 16 + r0;
        int gq1 = gq0 + 8;
#pragma unroll
        for (int dt = 0; dt < 8; dt++) {
            int col = h * HD + dt * 8 + (lane & 3) * 2;
            size_t o0 = (size_t)(b * Tt + gq0) * Cc + col;
            size_t o1 = (size_t)(b * Tt + gq1) * Cc + col;
            float y0 = o[mt][dt][0] * inv0, y1 = o[mt][dt][1] * inv0;
            float y2 = o[mt][dt][2] * inv1, y3 = o[mt][dt][3] * inv1;
            __half2 hv = __floats2half2_rn(y0, y1);
            __half2 lv = __floats2half2_rn(y0 - __half2float(hv.x),
                                           y1 - __half2float(hv.y));
            *(__half2*)&g_Yhi[o0] = hv;
            *(__half2*)&g_Ylo[o0] = lv;
            hv = __floats2half2_rn(y2, y3);
            lv = __floats2half2_rn(y2 - __half2float(hv.x),
                                   y3 - __half2float(hv.y));
            *(__half2*)&g_Yhi[o1] = hv;
            *(__half2*)&g_Ylo[o1] = lv;
        }
    }
}

// ---------------------------------------------------------------------------
extern "C" void kernel_launch(void* const* d_in, const int* in_sizes, int n_in,
                              void* d_out, int out_size) {
    const float* x      = (const float*)d_in[0];
    const float* W_attn = (const float*)d_in[1];
    const float* b_attn = (const float*)d_in[2];
    const float* W_proj = (const float*)d_in[3];
    const float* b_proj = (const float*)d_in[4];
    float* out = (float*)d_out;

    __half *xhi, *xlo, *wa, *wp, *yhi, *ylo;
    cudaGetSymbolAddress((void**)&xhi, g_Xhi);
    cudaGetSymbolAddress((void**)&xlo, g_Xlo);
    cudaGetSymbolAddress((void**)&wa,  g_WA);
    cudaGetSymbolAddress((void**)&wp,  g_WP);
    cudaGetSymbolAddress((void**)&yhi, g_Yhi);
    cudaGetSymbolAddress((void**)&ylo, g_Ylo);

    cudaFuncSetAttribute(tc_gemm<0>, cudaFuncAttributeMaxDynamicSharedMemorySize, GSMEM);
    cudaFuncSetAttribute(tc_gemm<1>, cudaFuncAttributeMaxDynamicSharedMemorySize, GSMEM);
    cudaFuncSetAttribute(attn_tc, cudaFuncAttributeMaxDynamicSharedMemorySize, ASMEM);

    convert_x_kernel<<<1024, 256>>>((const float4*)x, MR * Cc / 4);
    transconv_kernel<<<dim3(3 * Cc / 32, Cc / 32), dim3(32, 8)>>>(W_attn, wa, Cc, 3 * Cc);
    transconv_kernel<<<dim3(Cc / 32, Cc / 32), dim3(32, 8)>>>(W_proj, wp, Cc, Cc);

    tc_gemm<0><<<dim3(3 * Cc / 128, MR / 128), 128, GSMEM>>>(xhi, xlo, wa, b_attn, nullptr);

    vtrans_kernel<<<dim3(Tt / 32, HD / 32, Bb * Hh), dim3(32, 8)>>>();

    attn_tc<<<dim3(Tt / BQ, Bb * Hh), 128, ASMEM>>>();

    tc_gemm<1><<<dim3(Cc / 128, MR / 128), 128, GSMEM>>>(yhi, ylo, wp, b_proj, out);
}

// round 11
// speedup vs baseline: 1.4293x; 1.0097x over previous
#include <cuda_runtime.h>
#include <cuda_fp16.h>
#include <cstdint>

#define Bb 4
#define Tt 2048
#define Cc 1024
#define Hh 16
#define HD 64
#define MR (Bb*Tt)      // 8192 rows

// ---------------------------------------------------------------------------
// device scratch (allocation-free rule)
// ---------------------------------------------------------------------------
__device__ __half g_Qhi[Bb*Hh*Tt*HD];
__device__ __half g_Qlo[Bb*Hh*Tt*HD];
__device__ __half g_K  [Bb*Hh*Tt*HD];
__device__ __half g_V  [Bb*Hh*Tt*HD];
__device__ __half g_Xhi[MR*Cc];
__device__ __half g_Xlo[MR*Cc];
__device__ __half g_WA [3*Cc*Cc];        // [N,K] single fp16
__device__ __half g_WP [Cc*Cc];
__device__ __half g_Yhi[MR*Cc];
__device__ __half g_Ylo[MR*Cc];

// ---------------------------------------------------------------------------
// helpers (base sm_10x-legal PTX only: cp.async / ldmatrix / mma.sync)
// ---------------------------------------------------------------------------
__device__ __forceinline__ uint32_t smem_u32(const void* p) {
    uint32_t a;
    asm("{ .reg .u64 t; cvta.to.shared.u64 t, %1; cvt.u32.u64 %0, t; }" : "=r"(a) : "l"(p));
    return a;
}

__device__ __forceinline__ void cp_async16(uint32_t s, const void* g) {
    asm volatile("cp.async.cg.shared.global [%0], [%1], 16;" :: "r"(s), "l"(g));
}
__device__ __forceinline__ void cp_commit() {
    asm volatile("cp.async.commit_group;" ::: "memory");
}

#define LDSM_X4(r, addr) \
    asm volatile("ldmatrix.sync.aligned.m8n8.x4.shared.b16 {%0,%1,%2,%3}, [%4];" \
        : "=r"((r)[0]), "=r"((r)[1]), "=r"((r)[2]), "=r"((r)[3]) : "r"(addr))

#define LDSM_X4_T(r, addr) \
    asm volatile("ldmatrix.sync.aligned.m8n8.x4.trans.shared.b16 {%0,%1,%2,%3}, [%4];" \
        : "=r"((r)[0]), "=r"((r)[1]), "=r"((r)[2]), "=r"((r)[3]) : "r"(addr))

#define MMA16816(c, a, b0v, b1v) \
    asm volatile("mma.sync.aligned.m16n8k16.row.col.f32.f16.f16.f32 " \
        "{%0,%1,%2,%3}, {%4,%5,%6,%7}, {%8,%9}, {%0,%1,%2,%3};" \
        : "+f"((c)[0]), "+f"((c)[1]), "+f"((c)[2]), "+f"((c)[3]) \
        : "r"((a)[0]), "r"((a)[1]), "r"((a)[2]), "r"((a)[3]), "r"(b0v), "r"(b1v))

// ---------------------------------------------------------------------------
// prep kernels
// ---------------------------------------------------------------------------
__global__ void convert_x_kernel(const float4* __restrict__ x, int n4) {
    __half2* hi2 = (__half2*)g_Xhi;
    __half2* lo2 = (__half2*)g_Xlo;
    for (int i = blockIdx.x * blockDim.x + threadIdx.x; i < n4; i += gridDim.x * blockDim.x) {
        float4 v = x[i];
        __half2 a = __floats2half2_rn(v.x, v.y);
        __half2 b = __floats2half2_rn(v.z, v.w);
        __half2 c = __floats2half2_rn(v.x - __half2float(a.x), v.y - __half2float(a.y));
        __half2 d = __floats2half2_rn(v.z - __half2float(b.x), v.w - __half2float(b.y));
        hi2[i * 2] = a; hi2[i * 2 + 1] = b;
        lo2[i * 2] = c; lo2[i * 2 + 1] = d;
    }
}

// src [K,N] fp32 -> dst [N,K] single fp16
__global__ void transconv_kernel(const float* __restrict__ src, __half* __restrict__ dst,
                                 int K, int N) {
    __shared__ float sm[32][33];
    int n0 = blockIdx.x * 32, k0 = blockIdx.y * 32;
    int tx = threadIdx.x, ty = threadIdx.y;   // 32 x 8
#pragma unroll
    for (int i = 0; i < 32; i += 8)
        sm[ty + i][tx] = src[(size_t)(k0 + ty + i) * N + n0 + tx];
    __syncthreads();
#pragma unroll
    for (int i = 0; i < 32; i += 8)
        dst[(size_t)(n0 + ty + i) * K + k0 + tx] = __float2half(sm[tx][ty + i]);
}

// ---------------------------------------------------------------------------
// HMMA fp16 GEMM, A split hi/lo (2 MMA terms), B single fp16.
// CTA 128x128, 4 warps of 64x64, 128 threads, 2 CTAs/SM, BK=32, x2 buffered.
// MODE 0: emit Qhi/Qlo(0.125x), K, V (fp16) into [bh][t][d].
// MODE 1: row-major fp32 out [MR,Cc].
// ---------------------------------------------------------------------------
#define BK 32
#define PAD 40
#define MATB (128*PAD*2)             // 10240 per matrix (Ahi | Alo | B)
#define BUFB (3*MATB)                // 30720
#define GSMEM (2*BUFB)               // 61440

__device__ __forceinline__ void issue_chunk(
    uint32_t sbase,
    const __half* __restrict__ Ahi, const __half* __restrict__ Alo,
    const __half* __restrict__ Bm,
    int m0, int n0, int kc, int tid)
{
#pragma unroll
    for (int it = 0; it < 4; it++) {
        int idx = it * 128 + tid;            // 0..511
        int row = idx >> 2, seg = idx & 3;
        uint32_t soff = (uint32_t)(row * PAD + seg * 8) * 2;
        size_t ga = (size_t)(m0 + row) * Cc + kc + seg * 8;
        size_t gb = (size_t)(n0 + row) * Cc + kc + seg * 8;
        cp_async16(sbase + soff,            Ahi + ga);
        cp_async16(sbase + MATB + soff,     Alo + ga);
        cp_async16(sbase + 2 * MATB + soff, Bm + gb);
    }
    cp_commit();
}

template <int MODE>
__global__ __launch_bounds__(128, 2)
void tc_gemm(const __half* __restrict__ Ahi, const __half* __restrict__ Alo,
             const __half* __restrict__ Bm,
             const float* __restrict__ bias, float* __restrict__ out) {
    extern __shared__ char smx[];
    uint32_t sb = smem_u32(smx);
    int tid = threadIdx.x;
    int lane = tid & 31, warp = tid >> 5;
    int wm = warp >> 1;         // 2 m-warps (64 rows each)
    int wn = warp & 1;          // 2 n-warps (64 cols each)
    int m0 = blockIdx.y * 128, n0 = blockIdx.x * 128;

    float acc[4][8][4] = {};    // 64x64 per warp

    issue_chunk(sb, Ahi, Alo, Bm, m0, n0, 0, tid);

    const int NCH = Cc / BK;   // 32
    int arow = wm * 64 + (lane & 15);
    int acol_base = (lane >> 4) * 8;
    int brow = wn * 64 + (lane >> 4) * 8 + (lane & 7);
    int bcol_base = ((lane >> 3) & 1) * 8;

    for (int i = 0; i < NCH; i++) {
        if (i + 1 < NCH) {
            issue_chunk(sb + ((i + 1) & 1) * BUFB, Ahi, Alo, Bm, m0, n0, (i + 1) * BK, tid);
            asm volatile("cp.async.wait_group 1;" ::: "memory");
        } else {
            asm volatile("cp.async.wait_group 0;" ::: "memory");
        }
        __syncthreads();
        uint32_t buf = sb + (i & 1) * BUFB;

#pragma unroll
        for (int ks = 0; ks < 2; ks++) {
            int acol = ks * 16 + acol_base;
            int bcol = ks * 16 + bcol_base;
            uint32_t ah[4][4], bf4[4][4];
#pragma unroll
            for (int mt = 0; mt < 4; mt++)
                LDSM_X4(ah[mt], buf + (uint32_t)((arow + mt * 16) * PAD + acol) * 2);
#pragma unroll
            for (int np = 0; np < 4; np++)
                LDSM_X4(bf4[np], buf + 2 * MATB + (uint32_t)((brow + np * 16) * PAD + bcol) * 2);
#pragma unroll
            for (int np = 0; np < 4; np++)
#pragma unroll
                for (int mt = 0; mt < 4; mt++)
#pragma unroll
                    for (int half = 0; half < 2; half++)
                        MMA16816(acc[mt][np * 2 + half], ah[mt],
                                 bf4[np][half * 2], bf4[np][half * 2 + 1]);
            {
                uint32_t al[4][4];
#pragma unroll
                for (int mt = 0; mt < 4; mt++)
                    LDSM_X4(al[mt], buf + MATB + (uint32_t)((arow + mt * 16) * PAD + acol) * 2);
#pragma unroll
                for (int np = 0; np < 4; np++)
#pragma unroll
                    for (int mt = 0; mt < 4; mt++)
#pragma unroll
                        for (int half = 0; half < 2; half++)
                            MMA16816(acc[mt][np * 2 + half], al[mt],
                                     bf4[np][half * 2], bf4[np][half * 2 + 1]);
            }
        }
        __syncthreads();
    }

    int mrow = m0 + wm * 64 + (lane >> 2);
#pragma unroll
    for (int mt = 0; mt < 4; mt++) {
#pragma unroll
        for (int nt = 0; nt < 8; nt++) {
            int n = n0 + wn * 64 + nt * 8 + (lane & 3) * 2;
            float bx = bias[n], by = bias[n + 1];
            float2 v0 = make_float2(acc[mt][nt][0] + bx, acc[mt][nt][1] + by);
            float2 v1 = make_float2(acc[mt][nt][2] + bx, acc[mt][nt][3] + by);
            int m_a = mrow + mt * 16;
            int m_b = m_a + 8;
            if (MODE == 0) {
                int sec = n >> 10;
                int c2 = n & (Cc - 1);
                int h = c2 >> 6, d = c2 & 63;
                int ba = m_a >> 11, ta = m_a & (Tt - 1);
                int bb2 = m_b >> 11, tb = m_b & (Tt - 1);
                size_t o0 = (((size_t)(ba * Hh + h)) * Tt + ta) * HD + d;
                size_t o1 = (((size_t)(bb2 * Hh + h)) * Tt + tb) * HD + d;
                if (sec == 0) {
                    v0.x *= 0.125f; v0.y *= 0.125f; v1.x *= 0.125f; v1.y *= 0.125f;
                    __half2 hi = __floats2half2_rn(v0.x, v0.y);
                    __half2 lo = __floats2half2_rn(v0.x - __half2float(hi.x),
                                                   v0.y - __half2float(hi.y));
                    *(__half2*)&g_Qhi[o0] = hi;
                    *(__half2*)&g_Qlo[o0] = lo;
                    hi = __floats2half2_rn(v1.x, v1.y);
                    lo = __floats2half2_rn(v1.x - __half2float(hi.x),
                                           v1.y - __half2float(hi.y));
                    *(__half2*)&g_Qhi[o1] = hi;
                    *(__half2*)&g_Qlo[o1] = lo;
                } else {
                    __half* dst = (sec == 1) ? g_K : g_V;
                    *(__half2*)&dst[o0] = __floats2half2_rn(v0.x, v0.y);
                    *(__half2*)&dst[o1] = __floats2half2_rn(v1.x, v1.y);
                }
            } else {
                *(float2*)&out[(size_t)m_a * Cc + n] = v0;
                *(float2*)&out[(size_t)m_b * Cc + n] = v1;
            }
        }
    }
}

// ---------------------------------------------------------------------------
// Tensor-core flash attention, fp16: Q split hi/lo + K single (2-term S),
// P split from regs + V single (2-term PV, trans-ldmatrix on V[kv][d]).
// Bq=128, Bk=64, 128 threads, double-buffered K/V cp.async pipeline.
// ---------------------------------------------------------------------------
#define BQ 128
#define APAD 72
#define QMAT (BQ*APAD)
#define KMAT (64*APAD)
#define ASMEM ((2*QMAT + 4*KMAT)*2)  // 73728 B

__device__ __forceinline__ void issue_kv(uint32_t sK, uint32_t sV,
                                         const __half* gK, const __half* gV,
                                         int kv0, int tid) {
#pragma unroll
    for (int it = 0; it < 4; it++) {
        int idx = it * 128 + tid;
        int row = idx >> 3, seg = idx & 7;
        uint32_t so = (uint32_t)(row * APAD + seg * 8) * 2;
        size_t g = (size_t)(kv0 + row) * HD + seg * 8;
        cp_async16(sK + so, gK + g);
        cp_async16(sV + so, gV + g);
    }
    cp_commit();
}

__global__ __launch_bounds__(128, 2) void attn_tc() {
    extern __shared__ __half sa[];
    uint32_t sQh = smem_u32(sa);
    uint32_t sQl = sQh + QMAT * 2;
    uint32_t sKV0 = sQl + QMAT * 2;            // K0 | V0 | K1 | V1
    uint32_t sK[2] = {sKV0, sKV0 + 2 * KMAT * 2};
    uint32_t sV[2] = {sKV0 + KMAT * 2, sKV0 + 3 * KMAT * 2};

    int tid = threadIdx.x;
    int lane = tid & 31, w = tid >> 5;
    int bh = blockIdx.y;
    int qtile = (gridDim.x - 1) - blockIdx.x;    // heavy tiles first
    int q0 = qtile * BQ;

    const __half* gQh = g_Qhi + (size_t)bh * Tt * HD;
    const __half* gQl = g_Qlo + (size_t)bh * Tt * HD;
    const __half* gK  = g_K  + (size_t)bh * Tt * HD;
    const __half* gV  = g_V  + (size_t)bh * Tt * HD;

    // group 1: Q tile (128 x 64), hi+lo
#pragma unroll
    for (int it = 0; it < 8; it++) {
        int idx = it * 128 + tid;
        int row = idx >> 3, seg = idx & 7;
        uint32_t so = (uint32_t)(row * APAD + seg * 8) * 2;
        size_t go = (size_t)(q0 + row) * HD + seg * 8;
        cp_async16(sQh + so, gQh + go);
        cp_async16(sQl + so, gQl + go);
    }
    cp_commit();
    // group 2: KV tile 0
    issue_kv(sK[0], sV[0], gK, gV, 0, tid);

    float o[2][8][4] = {};
    float mrow[2][2] = {{-1e30f, -1e30f}, {-1e30f, -1e30f}};
    float lrow[2][2] = {};

    int r0 = lane >> 2;

    int ktmax = 2 * qtile + 1;
    for (int kt = 0; kt <= ktmax; kt++) {
        int kv0 = kt * 64;
        int b = kt & 1;
        if (kt + 1 <= ktmax) {
            __syncthreads();   // all warps done reading buf (kt+1)&1 (from kt-1)
            issue_kv(sK[b ^ 1], sV[b ^ 1], gK, gV, (kt + 1) * 64, tid);
            asm volatile("cp.async.wait_group 1;" ::: "memory");
        } else {
            asm volatile("cp.async.wait_group 0;" ::: "memory");
        }
        __syncthreads();       // publish buf b to all warps

        // ---- S = Q K^T  (Qh·K then Ql·K) ----
        float s[2][8][4] = {};
#pragma unroll
        for (int ks = 0; ks < 4; ks++) {
            uint32_t aq_h[2][4], bk[4][4];
#pragma unroll
            for (int mt = 0; mt < 2; mt++)
                LDSM_X4(aq_h[mt], sQh + (uint32_t)((w * 32 + mt * 16 + (lane & 15)) * APAD +
                                                   ks * 16 + (lane >> 4) * 8) * 2);
#pragma unroll
            for (int ntp = 0; ntp < 4; ntp++)
                LDSM_X4(bk[ntp], sK[b] + (uint32_t)((ntp * 16 + (lane >> 4) * 8 + (lane & 7)) * APAD +
                                                    ks * 16 + ((lane >> 3) & 1) * 8) * 2);
#pragma unroll
            for (int ntp = 0; ntp < 4; ntp++)
#pragma unroll
                for (int mt = 0; mt < 2; mt++)
#pragma unroll
                    for (int h2 = 0; h2 < 2; h2++)
                        MMA16816(s[mt][ntp * 2 + h2], aq_h[mt],
                                 bk[ntp][h2 * 2], bk[ntp][h2 * 2 + 1]);
            {
                uint32_t aq_l[2][4];
#pragma unroll
                for (int mt = 0; mt < 2; mt++)
                    LDSM_X4(aq_l[mt], sQl + (uint32_t)((w * 32 + mt * 16 + (lane & 15)) * APAD +
                                                       ks * 16 + (lane >> 4) * 8) * 2);
#pragma unroll
                for (int ntp = 0; ntp < 4; ntp++)
#pragma unroll
                    for (int mt = 0; mt < 2; mt++)
#pragma unroll
                        for (int h2 = 0; h2 < 2; h2++)
                            MMA16816(s[mt][ntp * 2 + h2], aq_l[mt],
                                     bk[ntp][h2 * 2], bk[ntp][h2 * 2 + 1]);
            }
        }

        // causal mask
        if (kv0 + 63 > q0 + w * 32) {
#pragma unroll
            for (int mt = 0; mt < 2; mt++)
#pragma unroll
                for (int nt = 0; nt < 8; nt++)
#pragma unroll
                    for (int j = 0; j < 4; j++) {
                        int c = kv0 + nt * 8 + (lane & 3) * 2 + (j & 1);
                        int r = q0 + w * 32 + mt * 16 + r0 + ((j >> 1) ? 8 : 0);
                        if (c > r) s[mt][nt][j] = -1e30f;
                    }
        }

        // ---- online softmax ----
#pragma unroll
        for (int mt = 0; mt < 2; mt++)
#pragma unroll
            for (int rr = 0; rr < 2; rr++) {
                float rm = -1e30f;
#pragma unroll
                for (int nt = 0; nt < 8; nt++)
                    rm = fmaxf(rm, fmaxf(s[mt][nt][rr * 2], s[mt][nt][rr * 2 + 1]));
                rm = fmaxf(rm, __shfl_xor_sync(0xffffffffu, rm, 1));
                rm = fmaxf(rm, __shfl_xor_sync(0xffffffffu, rm, 2));
                float mnew = fmaxf(mrow[mt][rr], rm);
                float alpha = __expf(mrow[mt][rr] - mnew);
                mrow[mt][rr] = mnew;
                float rs = 0.0f;
#pragma unroll
                for (int nt = 0; nt < 8; nt++) {
                    s[mt][nt][rr * 2]     = __expf(s[mt][nt][rr * 2] - mnew);
                    s[mt][nt][rr * 2 + 1] = __expf(s[mt][nt][rr * 2 + 1] - mnew);
                    rs += s[mt][nt][rr * 2] + s[mt][nt][rr * 2 + 1];
                }
                rs += __shfl_xor_sync(0xffffffffu, rs, 1);
                rs += __shfl_xor_sync(0xffffffffu, rs, 2);
                lrow[mt][rr] = lrow[mt][rr] * alpha + rs;
#pragma unroll
                for (int dt = 0; dt < 8; dt++) {
                    o[mt][dt][rr * 2]     *= alpha;
                    o[mt][dt][rr * 2 + 1] *= alpha;
                }
            }

        // ---- O += P V  (Ph·V then Pl·V; V via trans-ldmatrix on [kv][d]) ----
#pragma unroll
        for (int ksv = 0; ksv < 4; ksv++) {
            uint32_t pah[2][4], pal[2][4];
#pragma unroll
            for (int mt = 0; mt < 2; mt++)
#pragma unroll
                for (int q = 0; q < 4; q++) {
                    int nt = 2 * ksv + (q >> 1);
                    int j0 = (q & 1) * 2;
                    float x = s[mt][nt][j0], y = s[mt][nt][j0 + 1];
                    __half2 hv = __floats2half2_rn(x, y);
                    __half2 lv = __floats2half2_rn(x - __half2float(hv.x),
                                                   y - __half2float(hv.y));
                    pah[mt][q] = *(uint32_t*)&hv;
                    pal[mt][q] = *(uint32_t*)&lv;
                }
            uint32_t bv[4][4];
#pragma unroll
            for (int dtp = 0; dtp < 4; dtp++) {
                // trans load: rows = kv (k), cols = d (n)
                uint32_t addr = sV[b] + (uint32_t)(
                    (ksv * 16 + ((lane >> 3) & 1) * 8 + (lane & 7)) * APAD +
                    dtp * 16 + (lane >> 4) * 8) * 2;
                LDSM_X4_T(bv[dtp], addr);
            }
#pragma unroll
            for (int dtp = 0; dtp < 4; dtp++)
#pragma unroll
                for (int mt = 0; mt < 2; mt++)
#pragma unroll
                    for (int h2 = 0; h2 < 2; h2++)
                        MMA16816(o[mt][dtp * 2 + h2], pah[mt],
                                 bv[dtp][h2 * 2], bv[dtp][h2 * 2 + 1]);
#pragma unroll
            for (int dtp = 0; dtp < 4; dtp++)
#pragma unroll
                for (int mt = 0; mt < 2; mt++)
#pragma unroll
                    for (int h2 = 0; h2 < 2; h2++)
                        MMA16816(o[mt][dtp * 2 + h2], pal[mt],
                                 bv[dtp][h2 * 2], bv[dtp][h2 * 2 + 1]);
        }
    }

    // ---- epilogue: normalize, emit Y as fp16 hi/lo [B,T,C] ----
    int bb = bh >> 4, h = bh & 15;
#pragma unroll
    for (int mt = 0; mt < 2; mt++) {
        float inv0 = 1.0f / lrow[mt][0];
        float inv1 = 1.0f / lrow[mt][1];
        int gq0 = q0 + w * 32 + mt * 16 + r0;
        int gq1 = gq0 + 8;
#pragma unroll
        for (int dt = 0; dt < 8; dt++) {
            int col = h * HD + dt * 8 + (lane & 3) * 2;
            size_t o0 = (size_t)(bb * Tt + gq0) * Cc + col;
            size_t o1 = (size_t)(bb * Tt + gq1) * Cc + col;
            float y0 = o[mt][dt][0] * inv0, y1 = o[mt][dt][1] * inv0;
            float y2 = o[mt][dt][2] * inv1, y3 = o[mt][dt][3] * inv1;
            __half2 hv = __floats2half2_rn(y0, y1);
            __half2 lv = __floats2half2_rn(y0 - __half2float(hv.x),
                                           y1 - __half2float(hv.y));
            *(__half2*)&g_Yhi[o0] = hv;
            *(__half2*)&g_Ylo[o0] = lv;
            hv = __floats2half2_rn(y2, y3);
            lv = __floats2half2_rn(y2 - __half2float(hv.x),
                                   y3 - __half2float(hv.y));
            *(__half2*)&g_Yhi[o1] = hv;
            *(__half2*)&g_Ylo[o1] = lv;
        }
    }
}

// ---------------------------------------------------------------------------
extern "C" void kernel_launch(void* const* d_in, const int* in_sizes, int n_in,
                              void* d_out, int out_size) {
    const float* x      = (const float*)d_in[0];
    const float* W_attn = (const float*)d_in[1];
    const float* b_attn = (const float*)d_in[2];
    const float* W_proj = (const float*)d_in[3];
    const float* b_proj = (const float*)d_in[4];
    float* out = (float*)d_out;

    __half *xhi, *xlo, *wa, *wp, *yhi, *ylo;
    cudaGetSymbolAddress((void**)&xhi, g_Xhi);
    cudaGetSymbolAddress((void**)&xlo, g_Xlo);
    cudaGetSymbolAddress((void**)&wa,  g_WA);
    cudaGetSymbolAddress((void**)&wp,  g_WP);
    cudaGetSymbolAddress((void**)&yhi, g_Yhi);
    cudaGetSymbolAddress((void**)&ylo, g_Ylo);

    cudaFuncSetAttribute(tc_gemm<0>, cudaFuncAttributeMaxDynamicSharedMemorySize, GSMEM);
    cudaFuncSetAttribute(tc_gemm<1>, cudaFuncAttributeMaxDynamicSharedMemorySize, GSMEM);
    cudaFuncSetAttribute(attn_tc, cudaFuncAttributeMaxDynamicSharedMemorySize, ASMEM);

    convert_x_kernel<<<1024, 256>>>((const float4*)x, MR * Cc / 4);
    transconv_kernel<<<dim3(3 * Cc / 32, Cc / 32), dim3(32, 8)>>>(W_attn, wa, Cc, 3 * Cc);
    transconv_kernel<<<dim3(Cc / 32, Cc / 32), dim3(32, 8)>>>(W_proj, wp, Cc, Cc);

    tc_gemm<0><<<dim3(3 * Cc / 128, MR / 128), 128, GSMEM>>>(xhi, xlo, wa, b_attn, nullptr);

    attn_tc<<<dim3(Tt / BQ, Bb * Hh), 128, ASMEM>>>();

    tc_gemm<1><<<dim3(Cc / 128, MR / 128), 128, GSMEM>>>(yhi, ylo, wp, b_proj, out);
}

// round 12
// speedup vs baseline: 1.5789x; 1.1047x over previous
#include <cuda_runtime.h>
#include <cuda_fp16.h>
#include <cstdint>

#define Bb 4
#define Tt 2048
#define Cc 1024
#define Hh 16
#define HD 64
#define MR (Bb*Tt)      // 8192 rows

// ---------------------------------------------------------------------------
// device scratch (allocation-free rule)
// ---------------------------------------------------------------------------
__device__ __half g_Qhi[Bb*Hh*Tt*HD];
__device__ __half g_Qlo[Bb*Hh*Tt*HD];
__device__ __half g_K  [Bb*Hh*Tt*HD];
__device__ __half g_V  [Bb*Hh*Tt*HD];
__device__ __half g_Xhi[MR*Cc];
__device__ __half g_Xlo[MR*Cc];
__device__ __half g_WA [3*Cc*Cc];        // [N,K] single fp16
__device__ __half g_WP [Cc*Cc];
__device__ __half g_Yhi[MR*Cc];
__device__ __half g_Ylo[MR*Cc];

// ---------------------------------------------------------------------------
// helpers (base sm_10x-legal PTX only: cp.async / ldmatrix / mma.sync)
// ---------------------------------------------------------------------------
__device__ __forceinline__ uint32_t smem_u32(const void* p) {
    uint32_t a;
    asm("{ .reg .u64 t; cvta.to.shared.u64 t, %1; cvt.u32.u64 %0, t; }" : "=r"(a) : "l"(p));
    return a;
}

__device__ __forceinline__ void cp_async16(uint32_t s, const void* g) {
    asm volatile("cp.async.cg.shared.global [%0], [%1], 16;" :: "r"(s), "l"(g));
}
__device__ __forceinline__ void cp_commit() {
    asm volatile("cp.async.commit_group;" ::: "memory");
}

__device__ __forceinline__ float ex2f(float x) {
    float r;
    asm("ex2.approx.ftz.f32 %0, %1;" : "=f"(r) : "f"(x));
    return r;
}

#define LDSM_X4(r, addr) \
    asm volatile("ldmatrix.sync.aligned.m8n8.x4.shared.b16 {%0,%1,%2,%3}, [%4];" \
        : "=r"((r)[0]), "=r"((r)[1]), "=r"((r)[2]), "=r"((r)[3]) : "r"(addr))

#define LDSM_X4_T(r, addr) \
    asm volatile("ldmatrix.sync.aligned.m8n8.x4.trans.shared.b16 {%0,%1,%2,%3}, [%4];" \
        : "=r"((r)[0]), "=r"((r)[1]), "=r"((r)[2]), "=r"((r)[3]) : "r"(addr))

#define MMA16816(c, a, b0v, b1v) \
    asm volatile("mma.sync.aligned.m16n8k16.row.col.f32.f16.f16.f32 " \
        "{%0,%1,%2,%3}, {%4,%5,%6,%7}, {%8,%9}, {%0,%1,%2,%3};" \
        : "+f"((c)[0]), "+f"((c)[1]), "+f"((c)[2]), "+f"((c)[3]) \
        : "r"((a)[0]), "r"((a)[1]), "r"((a)[2]), "r"((a)[3]), "r"(b0v), "r"(b1v))

// ---------------------------------------------------------------------------
// prep kernels
// ---------------------------------------------------------------------------
__global__ void convert_x_kernel(const float4* __restrict__ x, int n4) {
    __half2* hi2 = (__half2*)g_Xhi;
    __half2* lo2 = (__half2*)g_Xlo;
    for (int i = blockIdx.x * blockDim.x + threadIdx.x; i < n4; i += gridDim.x * blockDim.x) {
        float4 v = x[i];
        __half2 a = __floats2half2_rn(v.x, v.y);
        __half2 b = __floats2half2_rn(v.z, v.w);
        __half2 c = __floats2half2_rn(v.x - __half2float(a.x), v.y - __half2float(a.y));
        __half2 d = __floats2half2_rn(v.z - __half2float(b.x), v.w - __half2float(b.y));
        hi2[i * 2] = a; hi2[i * 2 + 1] = b;
        lo2[i * 2] = c; lo2[i * 2 + 1] = d;
    }
}

// src [K,N] fp32 -> dst [N,K] single fp16
__global__ void transconv_kernel(const float* __restrict__ src, __half* __restrict__ dst,
                                 int K, int N) {
    __shared__ float sm[32][33];
    int n0 = blockIdx.x * 32, k0 = blockIdx.y * 32;
    int tx = threadIdx.x, ty = threadIdx.y;   // 32 x 8
#pragma unroll
    for (int i = 0; i < 32; i += 8)
        sm[ty + i][tx] = src[(size_t)(k0 + ty + i) * N + n0 + tx];
    __syncthreads();
#pragma unroll
    for (int i = 0; i < 32; i += 8)
        dst[(size_t)(n0 + ty + i) * K + k0 + tx] = __float2half(sm[tx][ty + i]);
}

// ---------------------------------------------------------------------------
// HMMA fp16 GEMM, A split hi/lo (2 MMA terms), B single fp16.
// CTA 128x128, 4 warps of 64x64, 128 threads, 2 CTAs/SM, BK=64, x2 buffered.
// MODE 0: emit Qhi/Qlo(0.18034x = 0.125*log2e), K, V (fp16) into [bh][t][d].
// MODE 1: row-major fp32 out [MR,Cc].
// ---------------------------------------------------------------------------
#define BK 64
#define PAD 72
#define MATB (128*PAD*2)             // 18432 per matrix (Ahi | Alo | B)
#define BUFB (3*MATB)                // 55296
#define GSMEM (2*BUFB)               // 110592

#define QSCALE 0.1803368801111f      // 0.125 * log2(e)

__device__ __forceinline__ void issue_chunk(
    uint32_t sbase,
    const __half* __restrict__ Ahi, const __half* __restrict__ Alo,
    const __half* __restrict__ Bm,
    int m0, int n0, int kc, int tid)
{
#pragma unroll
    for (int it = 0; it < 8; it++) {
        int idx = it * 128 + tid;            // 0..1023
        int row = idx >> 3, seg = idx & 7;
        uint32_t soff = (uint32_t)(row * PAD + seg * 8) * 2;
        size_t ga = (size_t)(m0 + row) * Cc + kc + seg * 8;
        size_t gb = (size_t)(n0 + row) * Cc + kc + seg * 8;
        cp_async16(sbase + soff,            Ahi + ga);
        cp_async16(sbase + MATB + soff,     Alo + ga);
        cp_async16(sbase + 2 * MATB + soff, Bm + gb);
    }
    cp_commit();
}

template <int MODE>
__global__ __launch_bounds__(128, 2)
void tc_gemm(const __half* __restrict__ Ahi, const __half* __restrict__ Alo,
             const __half* __restrict__ Bm,
             const float* __restrict__ bias, float* __restrict__ out) {
    extern __shared__ char smx[];
    uint32_t sb = smem_u32(smx);
    int tid = threadIdx.x;
    int lane = tid & 31, warp = tid >> 5;
    int wm = warp >> 1;         // 2 m-warps (64 rows each)
    int wn = warp & 1;          // 2 n-warps (64 cols each)
    int m0 = blockIdx.y * 128, n0 = blockIdx.x * 128;

    float acc[4][8][4] = {};    // 64x64 per warp

    issue_chunk(sb, Ahi, Alo, Bm, m0, n0, 0, tid);

    const int NCH = Cc / BK;   // 16
    int arow = wm * 64 + (lane & 15);
    int acol_base = (lane >> 4) * 8;
    int brow = wn * 64 + (lane >> 4) * 8 + (lane & 7);
    int bcol_base = ((lane >> 3) & 1) * 8;

    for (int i = 0; i < NCH; i++) {
        if (i + 1 < NCH) {
            issue_chunk(sb + ((i + 1) & 1) * BUFB, Ahi, Alo, Bm, m0, n0, (i + 1) * BK, tid);
            asm volatile("cp.async.wait_group 1;" ::: "memory");
        } else {
            asm volatile("cp.async.wait_group 0;" ::: "memory");
        }
        __syncthreads();
        uint32_t buf = sb + (i & 1) * BUFB;

#pragma unroll
        for (int ks = 0; ks < 4; ks++) {
            int acol = ks * 16 + acol_base;
            int bcol = ks * 16 + bcol_base;
            uint32_t ah[4][4], bf4[4][4];
#pragma unroll
            for (int mt = 0; mt < 4; mt++)
                LDSM_X4(ah[mt], buf + (uint32_t)((arow + mt * 16) * PAD + acol) * 2);
#pragma unroll
            for (int np = 0; np < 4; np++)
                LDSM_X4(bf4[np], buf + 2 * MATB + (uint32_t)((brow + np * 16) * PAD + bcol) * 2);
#pragma unroll
            for (int np = 0; np < 4; np++)
#pragma unroll
                for (int mt = 0; mt < 4; mt++)
#pragma unroll
                    for (int half = 0; half < 2; half++)
                        MMA16816(acc[mt][np * 2 + half], ah[mt],
                                 bf4[np][half * 2], bf4[np][half * 2 + 1]);
            {
                uint32_t al[4][4];
#pragma unroll
                for (int mt = 0; mt < 4; mt++)
                    LDSM_X4(al[mt], buf + MATB + (uint32_t)((arow + mt * 16) * PAD + acol) * 2);
#pragma unroll
                for (int np = 0; np < 4; np++)
#pragma unroll
                    for (int mt = 0; mt < 4; mt++)
#pragma unroll
                        for (int half = 0; half < 2; half++)
                            MMA16816(acc[mt][np * 2 + half], al[mt],
                                     bf4[np][half * 2], bf4[np][half * 2 + 1]);
            }
        }
        __syncthreads();
    }

    int mrow = m0 + wm * 64 + (lane >> 2);
#pragma unroll
    for (int mt = 0; mt < 4; mt++) {
#pragma unroll
        for (int nt = 0; nt < 8; nt++) {
            int n = n0 + wn * 64 + nt * 8 + (lane & 3) * 2;
            float bx = bias[n], by = bias[n + 1];
            float2 v0 = make_float2(acc[mt][nt][0] + bx, acc[mt][nt][1] + by);
            float2 v1 = make_float2(acc[mt][nt][2] + bx, acc[mt][nt][3] + by);
            int m_a = mrow + mt * 16;
            int m_b = m_a + 8;
            if (MODE == 0) {
                int sec = n >> 10;
                int c2 = n & (Cc - 1);
                int h = c2 >> 6, d = c2 & 63;
                int ba = m_a >> 11, ta = m_a & (Tt - 1);
                int bb2 = m_b >> 11, tb = m_b & (Tt - 1);
                size_t o0 = (((size_t)(ba * Hh + h)) * Tt + ta) * HD + d;
                size_t o1 = (((size_t)(bb2 * Hh + h)) * Tt + tb) * HD + d;
                if (sec == 0) {
                    v0.x *= QSCALE; v0.y *= QSCALE; v1.x *= QSCALE; v1.y *= QSCALE;
                    __half2 hi = __floats2half2_rn(v0.x, v0.y);
                    __half2 lo = __floats2half2_rn(v0.x - __half2float(hi.x),
                                                   v0.y - __half2float(hi.y));
                    *(__half2*)&g_Qhi[o0] = hi;
                    *(__half2*)&g_Qlo[o0] = lo;
                    hi = __floats2half2_rn(v1.x, v1.y);
                    lo = __floats2half2_rn(v1.x - __half2float(hi.x),
                                           v1.y - __half2float(hi.y));
                    *(__half2*)&g_Qhi[o1] = hi;
                    *(__half2*)&g_Qlo[o1] = lo;
                } else {
                    __half* dst = (sec == 1) ? g_K : g_V;
                    *(__half2*)&dst[o0] = __floats2half2_rn(v0.x, v0.y);
                    *(__half2*)&dst[o1] = __floats2half2_rn(v1.x, v1.y);
                }
            } else {
                *(float2*)&out[(size_t)m_a * Cc + n] = v0;
                *(float2*)&out[(size_t)m_b * Cc + n] = v1;
            }
        }
    }
}

// ---------------------------------------------------------------------------
// Tensor-core flash attention, fp16: Q split hi/lo + K single (2-term S),
// P split from regs + V single (2-term PV, trans-ldmatrix on V[kv][d]).
// Softmax in exp2 domain (Q pre-scaled by log2e). Bq=128, Bk=64, 128 thr.
// ---------------------------------------------------------------------------
#define BQ 128
#define APAD 72
#define QMAT (BQ*APAD)
#define KMAT (64*APAD)
#define ASMEM ((2*QMAT + 4*KMAT)*2)  // 73728 B

__device__ __forceinline__ void issue_kv(uint32_t sK, uint32_t sV,
                                         const __half* gK, const __half* gV,
                                         int kv0, int tid) {
#pragma unroll
    for (int it = 0; it < 4; it++) {
        int idx = it * 128 + tid;
        int row = idx >> 3, seg = idx & 7;
        uint32_t so = (uint32_t)(row * APAD + seg * 8) * 2;
        size_t g = (size_t)(kv0 + row) * HD + seg * 8;
        cp_async16(sK + so, gK + g);
        cp_async16(sV + so, gV + g);
    }
    cp_commit();
}

__global__ __launch_bounds__(128, 2) void attn_tc() {
    extern __shared__ __half sa[];
    uint32_t sQh = smem_u32(sa);
    uint32_t sQl = sQh + QMAT * 2;
    uint32_t sKV0 = sQl + QMAT * 2;            // K0 | V0 | K1 | V1
    uint32_t sK[2] = {sKV0, sKV0 + 2 * KMAT * 2};
    uint32_t sV[2] = {sKV0 + KMAT * 2, sKV0 + 3 * KMAT * 2};

    int tid = threadIdx.x;
    int lane = tid & 31, w = tid >> 5;
    int bh = blockIdx.y;
    int qtile = (gridDim.x - 1) - blockIdx.x;    // heavy tiles first
    int q0 = qtile * BQ;

    const __half* gQh = g_Qhi + (size_t)bh * Tt * HD;
    const __half* gQl = g_Qlo + (size_t)bh * Tt * HD;
    const __half* gK  = g_K  + (size_t)bh * Tt * HD;
    const __half* gV  = g_V  + (size_t)bh * Tt * HD;

    // group 1: Q tile (128 x 64), hi+lo
#pragma unroll
    for (int it = 0; it < 8; it++) {
        int idx = it * 128 + tid;
        int row = idx >> 3, seg = idx & 7;
        uint32_t so = (uint32_t)(row * APAD + seg * 8) * 2;
        size_t go = (size_t)(q0 + row) * HD + seg * 8;
        cp_async16(sQh + so, gQh + go);
        cp_async16(sQl + so, gQl + go);
    }
    cp_commit();
    // group 2: KV tile 0
    issue_kv(sK[0], sV[0], gK, gV, 0, tid);

    float o[2][8][4] = {};
    float mrow[2][2] = {{-1e30f, -1e30f}, {-1e30f, -1e30f}};
    float lrow[2][2] = {};

    int r0 = lane >> 2;

    int ktmax = 2 * qtile + 1;
    for (int kt = 0; kt <= ktmax; kt++) {
        int kv0 = kt * 64;
        int b = kt & 1;
        if (kt + 1 <= ktmax) {
            __syncthreads();
            issue_kv(sK[b ^ 1], sV[b ^ 1], gK, gV, (kt + 1) * 64, tid);
            asm volatile("cp.async.wait_group 1;" ::: "memory");
        } else {
            asm volatile("cp.async.wait_group 0;" ::: "memory");
        }
        __syncthreads();

        // ---- S = Q K^T  (Qh·K then Ql·K); result in log2 domain ----
        float s[2][8][4] = {};
#pragma unroll
        for (int ks = 0; ks < 4; ks++) {
            uint32_t aq_h[2][4], bk[4][4];
#pragma unroll
            for (int mt = 0; mt < 2; mt++)
                LDSM_X4(aq_h[mt], sQh + (uint32_t)((w * 32 + mt * 16 + (lane & 15)) * APAD +
                                                   ks * 16 + (lane >> 4) * 8) * 2);
#pragma unroll
            for (int ntp = 0; ntp < 4; ntp++)
                LDSM_X4(bk[ntp], sK[b] + (uint32_t)((ntp * 16 + (lane >> 4) * 8 + (lane & 7)) * APAD +
                                                    ks * 16 + ((lane >> 3) & 1) * 8) * 2);
#pragma unroll
            for (int ntp = 0; ntp < 4; ntp++)
#pragma unroll
                for (int mt = 0; mt < 2; mt++)
#pragma unroll
                    for (int h2 = 0; h2 < 2; h2++)
                        MMA16816(s[mt][ntp * 2 + h2], aq_h[mt],
                                 bk[ntp][h2 * 2], bk[ntp][h2 * 2 + 1]);
            {
                uint32_t aq_l[2][4];
#pragma unroll
                for (int mt = 0; mt < 2; mt++)
                    LDSM_X4(aq_l[mt], sQl + (uint32_t)((w * 32 + mt * 16 + (lane & 15)) * APAD +
                                                       ks * 16 + (lane >> 4) * 8) * 2);
#pragma unroll
                for (int ntp = 0; ntp < 4; ntp++)
#pragma unroll
                    for (int mt = 0; mt < 2; mt++)
#pragma unroll
                        for (int h2 = 0; h2 < 2; h2++)
                            MMA16816(s[mt][ntp * 2 + h2], aq_l[mt],
                                     bk[ntp][h2 * 2], bk[ntp][h2 * 2 + 1]);
            }
        }

        // causal mask
        if (kv0 + 63 > q0 + w * 32) {
#pragma unroll
            for (int mt = 0; mt < 2; mt++)
#pragma unroll
                for (int nt = 0; nt < 8; nt++)
#pragma unroll
                    for (int j = 0; j < 4; j++) {
                        int c = kv0 + nt * 8 + (lane & 3) * 2 + (j & 1);
                        int r = q0 + w * 32 + mt * 16 + r0 + ((j >> 1) ? 8 : 0);
                        if (c > r) s[mt][nt][j] = -1e30f;
                    }
        }

        // ---- online softmax (exp2 domain) ----
#pragma unroll
        for (int mt = 0; mt < 2; mt++)
#pragma unroll
            for (int rr = 0; rr < 2; rr++) {
                float rm = -1e30f;
#pragma unroll
                for (int nt = 0; nt < 8; nt++)
                    rm = fmaxf(rm, fmaxf(s[mt][nt][rr * 2], s[mt][nt][rr * 2 + 1]));
                rm = fmaxf(rm, __shfl_xor_sync(0xffffffffu, rm, 1));
                rm = fmaxf(rm, __shfl_xor_sync(0xffffffffu, rm, 2));
                float mnew = fmaxf(mrow[mt][rr], rm);
                float alpha = ex2f(mrow[mt][rr] - mnew);
                mrow[mt][rr] = mnew;
                float rs = 0.0f;
#pragma unroll
                for (int nt = 0; nt < 8; nt++) {
                    s[mt][nt][rr * 2]     = ex2f(s[mt][nt][rr * 2] - mnew);
                    s[mt][nt][rr * 2 + 1] = ex2f(s[mt][nt][rr * 2 + 1] - mnew);
                    rs += s[mt][nt][rr * 2] + s[mt][nt][rr * 2 + 1];
                }
                rs += __shfl_xor_sync(0xffffffffu, rs, 1);
                rs += __shfl_xor_sync(0xffffffffu, rs, 2);
                lrow[mt][rr] = lrow[mt][rr] * alpha + rs;
#pragma unroll
                for (int dt = 0; dt < 8; dt++) {
                    o[mt][dt][rr * 2]     *= alpha;
                    o[mt][dt][rr * 2 + 1] *= alpha;
                }
            }

        // ---- O += P V  (Ph·V then Pl·V; V via trans-ldmatrix on [kv][d]) ----
#pragma unroll
        for (int ksv = 0; ksv < 4; ksv++) {
            uint32_t pah[2][4], pal[2][4];
#pragma unroll
            for (int mt = 0; mt < 2; mt++)
#pragma unroll
                for (int q = 0; q < 4; q++) {
                    int nt = 2 * ksv + (q >> 1);
                    int j0 = (q & 1) * 2;
                    float x = s[mt][nt][j0], y = s[mt][nt][j0 + 1];
                    __half2 hv = __floats2half2_rn(x, y);
                    __half2 lv = __floats2half2_rn(x - __half2float(hv.x),
                                                   y - __half2float(hv.y));
                    pah[mt][q] = *(uint32_t*)&hv;
                    pal[mt][q] = *(uint32_t*)&lv;
                }
            uint32_t bv[4][4];
#pragma unroll
            for (int dtp = 0; dtp < 4; dtp++) {
                uint32_t addr = sV[b] + (uint32_t)(
                    (ksv * 16 + ((lane >> 3) & 1) * 8 + (lane & 7)) * APAD +
                    dtp * 16 + (lane >> 4) * 8) * 2;
                LDSM_X4_T(bv[dtp], addr);
            }
#pragma unroll
            for (int dtp = 0; dtp < 4; dtp++)
#pragma unroll
                for (int mt = 0; mt < 2; mt++)
#pragma unroll
                    for (int h2 = 0; h2 < 2; h2++)
                        MMA16816(o[mt][dtp * 2 + h2], pah[mt],
                                 bv[dtp][h2 * 2], bv[dtp][h2 * 2 + 1]);
#pragma unroll
            for (int dtp = 0; dtp < 4; dtp++)
#pragma unroll
                for (int mt = 0; mt < 2; mt++)
#pragma unroll
                    for (int h2 = 0; h2 < 2; h2++)
                        MMA16816(o[mt][dtp * 2 + h2], pal[mt],
                                 bv[dtp][h2 * 2], bv[dtp][h2 * 2 + 1]);
        }
    }

    // ---- epilogue: normalize, emit Y as fp16 hi/lo [B,T,C] ----
    int bb = bh >> 4, h = bh & 15;
#pragma unroll
    for (int mt = 0; mt < 2; mt++) {
        float inv0 = 1.0f / lrow[mt][0];
        float inv1 = 1.0f / lrow[mt][1];
        int gq0 = q0 + w * 32 + mt * 16 + r0;
        int gq1 = gq0 + 8;
#pragma unroll
        for (int dt = 0; dt < 8; dt++) {
            int col = h * HD + dt * 8 + (lane & 3) * 2;
            size_t o0 = (size_t)(bb * Tt + gq0) * Cc + col;
            size_t o1 = (size_t)(bb * Tt + gq1) * Cc + col;
            float y0 = o[mt][dt][0] * inv0, y1 = o[mt][dt][1] * inv0;
            float y2 = o[mt][dt][2] * inv1, y3 = o[mt][dt][3] * inv1;
            __half2 hv = __floats2half2_rn(y0, y1);
            __half2 lv = __floats2half2_rn(y0 - __half2float(hv.x),
                                           y1 - __half2float(hv.y));
            *(__half2*)&g_Yhi[o0] = hv;
            *(__half2*)&g_Ylo[o0] = lv;
            hv = __floats2half2_rn(y2, y3);
            lv = __floats2half2_rn(y2 - __half2float(hv.x),
                                   y3 - __half2float(hv.y));
            *(__half2*)&g_Yhi[o1] = hv;
            *(__half2*)&g_Ylo[o1] = lv;
        }
    }
}

// ---------------------------------------------------------------------------
extern "C" void kernel_launch(void* const* d_in, const int* in_sizes, int n_in,
                              void* d_out, int out_size) {
    const float* x      = (const float*)d_in[0];
    const float* W_attn = (const float*)d_in[1];
    const float* b_attn = (const float*)d_in[2];
    const float* W_proj = (const float*)d_in[3];
    const float* b_proj = (const float*)d_in[4];
    float* out = (float*)d_out;

    __half *xhi, *xlo, *wa, *wp, *yhi, *ylo;
    cudaGetSymbolAddress((void**)&xhi, g_Xhi);
    cudaGetSymbolAddress((void**)&xlo, g_Xlo);
    cudaGetSymbolAddress((void**)&wa,  g_WA);
    cudaGetSymbolAddress((void**)&wp,  g_WP);
    cudaGetSymbolAddress((void**)&yhi, g_Yhi);
    cudaGetSymbolAddress((void**)&ylo, g_Ylo);

    cudaFuncSetAttribute(tc_gemm<0>, cudaFuncAttributeMaxDynamicSharedMemorySize, GSMEM);
    cudaFuncSetAttribute(tc_gemm<1>, cudaFuncAttributeMaxDynamicSharedMemorySize, GSMEM);
    cudaFuncSetAttribute(attn_tc, cudaFuncAttributeMaxDynamicSharedMemorySize, ASMEM);

    convert_x_kernel<<<1024, 256>>>((const float4*)x, MR * Cc / 4);
    transconv_kernel<<<dim3(3 * Cc / 32, Cc / 32), dim3(32, 8)>>>(W_attn, wa, Cc, 3 * Cc);
    transconv_kernel<<<dim3(Cc / 32, Cc / 32), dim3(32, 8)>>>(W_proj, wp, Cc, Cc);

    tc_gemm<0><<<dim3(3 * Cc / 128, MR / 128), 128, GSMEM>>>(xhi, xlo, wa, b_attn, nullptr);

    attn_tc<<<dim3(Tt / BQ, Bb * Hh), 128, ASMEM>>>();

    tc_gemm<1><<<dim3(Cc / 128, MR / 128), 128, GSMEM>>>(yhi, ylo, wp, b_proj, out);
}

// round 13
// speedup vs baseline: 1.6865x; 1.0681x over previous
#include <cuda_runtime.h>
#include <cuda_fp16.h>
#include <cstdint>

#define Bb 4
#define Tt 2048
#define Cc 1024
#define Hh 16
#define HD 64
#define MR (Bb*Tt)      // 8192 rows

// ---------------------------------------------------------------------------
// device scratch (allocation-free rule)
// ---------------------------------------------------------------------------
__device__ __half g_Qhi[Bb*Hh*Tt*HD];
__device__ __half g_Qlo[Bb*Hh*Tt*HD];
__device__ __half g_K  [Bb*Hh*Tt*HD];
__device__ __half g_V  [Bb*Hh*Tt*HD];
__device__ __half g_Xhi[MR*Cc];
__device__ __half g_Xlo[MR*Cc];
__device__ __half g_WA [3*Cc*Cc];        // [N,K] single fp16
__device__ __half g_WP [Cc*Cc];
__device__ __half g_Yhi[MR*Cc];
__device__ __half g_Ylo[MR*Cc];

// ---------------------------------------------------------------------------
// helpers (base sm_10x-legal PTX only: cp.async / ldmatrix / mma.sync)
// ---------------------------------------------------------------------------
__device__ __forceinline__ uint32_t smem_u32(const void* p) {
    uint32_t a;
    asm("{ .reg .u64 t; cvta.to.shared.u64 t, %1; cvt.u32.u64 %0, t; }" : "=r"(a) : "l"(p));
    return a;
}

__device__ __forceinline__ void cp_async16(uint32_t s, const void* g) {
    asm volatile("cp.async.cg.shared.global [%0], [%1], 16;" :: "r"(s), "l"(g));
}
__device__ __forceinline__ void cp_commit() {
    asm volatile("cp.async.commit_group;" ::: "memory");
}

__device__ __forceinline__ float ex2f(float x) {
    float r;
    asm("ex2.approx.ftz.f32 %0, %1;" : "=f"(r) : "f"(x));
    return r;
}

#define LDSM_X4(r, addr) \
    asm volatile("ldmatrix.sync.aligned.m8n8.x4.shared.b16 {%0,%1,%2,%3}, [%4];" \
        : "=r"((r)[0]), "=r"((r)[1]), "=r"((r)[2]), "=r"((r)[3]) : "r"(addr))

#define LDSM_X4_T(r, addr) \
    asm volatile("ldmatrix.sync.aligned.m8n8.x4.trans.shared.b16 {%0,%1,%2,%3}, [%4];" \
        : "=r"((r)[0]), "=r"((r)[1]), "=r"((r)[2]), "=r"((r)[3]) : "r"(addr))

#define MMA16816(c, a, b0v, b1v) \
    asm volatile("mma.sync.aligned.m16n8k16.row.col.f32.f16.f16.f32 " \
        "{%0,%1,%2,%3}, {%4,%5,%6,%7}, {%8,%9}, {%0,%1,%2,%3};" \
        : "+f"((c)[0]), "+f"((c)[1]), "+f"((c)[2]), "+f"((c)[3]) \
        : "r"((a)[0]), "r"((a)[1]), "r"((a)[2]), "r"((a)[3]), "r"(b0v), "r"(b1v))

// ---------------------------------------------------------------------------
// prep kernels
// ---------------------------------------------------------------------------
__global__ void convert_x_kernel(const float4* __restrict__ x, int n4) {
    __half2* hi2 = (__half2*)g_Xhi;
    __half2* lo2 = (__half2*)g_Xlo;
    for (int i = blockIdx.x * blockDim.x + threadIdx.x; i < n4; i += gridDim.x * blockDim.x) {
        float4 v = x[i];
        __half2 a = __floats2half2_rn(v.x, v.y);
        __half2 b = __floats2half2_rn(v.z, v.w);
        __half2 c = __floats2half2_rn(v.x - __half2float(a.x), v.y - __half2float(a.y));
        __half2 d = __floats2half2_rn(v.z - __half2float(b.x), v.w - __half2float(b.y));
        hi2[i * 2] = a; hi2[i * 2 + 1] = b;
        lo2[i * 2] = c; lo2[i * 2 + 1] = d;
    }
}

// src [K,N] fp32 -> dst [N,K] single fp16
__global__ void transconv_kernel(const float* __restrict__ src, __half* __restrict__ dst,
                                 int K, int N) {
    __shared__ float sm[32][33];
    int n0 = blockIdx.x * 32, k0 = blockIdx.y * 32;
    int tx = threadIdx.x, ty = threadIdx.y;   // 32 x 8
#pragma unroll
    for (int i = 0; i < 32; i += 8)
        sm[ty + i][tx] = src[(size_t)(k0 + ty + i) * N + n0 + tx];
    __syncthreads();
#pragma unroll
    for (int i = 0; i < 32; i += 8)
        dst[(size_t)(n0 + ty + i) * K + k0 + tx] = __float2half(sm[tx][ty + i]);
}

// ---------------------------------------------------------------------------
// HMMA fp16 GEMM, A split hi/lo (2 MMA terms), B single fp16.
// CTA 128x128, 4 warps of 64x64, 128 threads, 2 CTAs/SM, BK=64, x2 buffered.
// MODE 0: emit Qhi/Qlo(0.18034x = 0.125*log2e), K, V (fp16) into [bh][t][d].
// MODE 1: row-major fp32 out [MR,Cc].
// ---------------------------------------------------------------------------
#define BK 64
#define PAD 72
#define MATB (128*PAD*2)             // 18432 per matrix (Ahi | Alo | B)
#define BUFB (3*MATB)                // 55296
#define GSMEM (2*BUFB)               // 110592

#define QSCALE 0.1803368801111f      // 0.125 * log2(e)

__device__ __forceinline__ void issue_chunk(
    uint32_t sbase,
    const __half* __restrict__ Ahi, const __half* __restrict__ Alo,
    const __half* __restrict__ Bm,
    int m0, int n0, int kc, int tid)
{
#pragma unroll
    for (int it = 0; it < 8; it++) {
        int idx = it * 128 + tid;            // 0..1023
        int row = idx >> 3, seg = idx & 7;
        uint32_t soff = (uint32_t)(row * PAD + seg * 8) * 2;
        size_t ga = (size_t)(m0 + row) * Cc + kc + seg * 8;
        size_t gb = (size_t)(n0 + row) * Cc + kc + seg * 8;
        cp_async16(sbase + soff,            Ahi + ga);
        cp_async16(sbase + MATB + soff,     Alo + ga);
        cp_async16(sbase + 2 * MATB + soff, Bm + gb);
    }
    cp_commit();
}

template <int MODE>
__global__ __launch_bounds__(128, 2)
void tc_gemm(const __half* __restrict__ Ahi, const __half* __restrict__ Alo,
             const __half* __restrict__ Bm,
             const float* __restrict__ bias, float* __restrict__ out) {
    extern __shared__ char smx[];
    uint32_t sb = smem_u32(smx);
    int tid = threadIdx.x;
    int lane = tid & 31, warp = tid >> 5;
    int wm = warp >> 1;         // 2 m-warps (64 rows each)
    int wn = warp & 1;          // 2 n-warps (64 cols each)
    int m0 = blockIdx.y * 128, n0 = blockIdx.x * 128;

    float acc[4][8][4] = {};    // 64x64 per warp

    issue_chunk(sb, Ahi, Alo, Bm, m0, n0, 0, tid);

    const int NCH = Cc / BK;   // 16
    int arow = wm * 64 + (lane & 15);
    int acol_base = (lane >> 4) * 8;
    int brow = wn * 64 + (lane >> 4) * 8 + (lane & 7);
    int bcol_base = ((lane >> 3) & 1) * 8;

    for (int i = 0; i < NCH; i++) {
        if (i + 1 < NCH) {
            issue_chunk(sb + ((i + 1) & 1) * BUFB, Ahi, Alo, Bm, m0, n0, (i + 1) * BK, tid);
            asm volatile("cp.async.wait_group 1;" ::: "memory");
        } else {
            asm volatile("cp.async.wait_group 0;" ::: "memory");
        }
        __syncthreads();
        uint32_t buf = sb + (i & 1) * BUFB;

#pragma unroll
        for (int ks = 0; ks < 4; ks++) {
            int acol = ks * 16 + acol_base;
            int bcol = ks * 16 + bcol_base;
            uint32_t ah[4][4], bf4[4][4];
#pragma unroll
            for (int mt = 0; mt < 4; mt++)
                LDSM_X4(ah[mt], buf + (uint32_t)((arow + mt * 16) * PAD + acol) * 2);
#pragma unroll
            for (int np = 0; np < 4; np++)
                LDSM_X4(bf4[np], buf + 2 * MATB + (uint32_t)((brow + np * 16) * PAD + bcol) * 2);
#pragma unroll
            for (int np = 0; np < 4; np++)
#pragma unroll
                for (int mt = 0; mt < 4; mt++)
#pragma unroll
                    for (int half = 0; half < 2; half++)
                        MMA16816(acc[mt][np * 2 + half], ah[mt],
                                 bf4[np][half * 2], bf4[np][half * 2 + 1]);
            {
                uint32_t al[4][4];
#pragma unroll
                for (int mt = 0; mt < 4; mt++)
                    LDSM_X4(al[mt], buf + MATB + (uint32_t)((arow + mt * 16) * PAD + acol) * 2);
#pragma unroll
                for (int np = 0; np < 4; np++)
#pragma unroll
                    for (int mt = 0; mt < 4; mt++)
#pragma unroll
                        for (int half = 0; half < 2; half++)
                            MMA16816(acc[mt][np * 2 + half], al[mt],
                                     bf4[np][half * 2], bf4[np][half * 2 + 1]);
            }
        }
        __syncthreads();
    }

    int mrow = m0 + wm * 64 + (lane >> 2);
#pragma unroll
    for (int mt = 0; mt < 4; mt++) {
#pragma unroll
        for (int nt = 0; nt < 8; nt++) {
            int n = n0 + wn * 64 + nt * 8 + (lane & 3) * 2;
            float bx = bias[n], by = bias[n + 1];
            float2 v0 = make_float2(acc[mt][nt][0] + bx, acc[mt][nt][1] + by);
            float2 v1 = make_float2(acc[mt][nt][2] + bx, acc[mt][nt][3] + by);
            int m_a = mrow + mt * 16;
            int m_b = m_a + 8;
            if (MODE == 0) {
                int sec = n >> 10;
                int c2 = n & (Cc - 1);
                int h = c2 >> 6, d = c2 & 63;
                int ba = m_a >> 11, ta = m_a & (Tt - 1);
                int bb2 = m_b >> 11, tb = m_b & (Tt - 1);
                size_t o0 = (((size_t)(ba * Hh + h)) * Tt + ta) * HD + d;
                size_t o1 = (((size_t)(bb2 * Hh + h)) * Tt + tb) * HD + d;
                if (sec == 0) {
                    v0.x *= QSCALE; v0.y *= QSCALE; v1.x *= QSCALE; v1.y *= QSCALE;
                    __half2 hi = __floats2half2_rn(v0.x, v0.y);
                    __half2 lo = __floats2half2_rn(v0.x - __half2float(hi.x),
                                                   v0.y - __half2float(hi.y));
                    *(__half2*)&g_Qhi[o0] = hi;
                    *(__half2*)&g_Qlo[o0] = lo;
                    hi = __floats2half2_rn(v1.x, v1.y);
                    lo = __floats2half2_rn(v1.x - __half2float(hi.x),
                                           v1.y - __half2float(hi.y));
                    *(__half2*)&g_Qhi[o1] = hi;
                    *(__half2*)&g_Qlo[o1] = lo;
                } else {
                    __half* dst = (sec == 1) ? g_K : g_V;
                    *(__half2*)&dst[o0] = __floats2half2_rn(v0.x, v0.y);
                    *(__half2*)&dst[o1] = __floats2half2_rn(v1.x, v1.y);
                }
            } else {
                *(float2*)&out[(size_t)m_a * Cc + n] = v0;
                *(float2*)&out[(size_t)m_b * Cc + n] = v1;
            }
        }
    }
}

// ---------------------------------------------------------------------------
// Tensor-core flash attention, fp16: Q split hi/lo + K single (2-term S),
// P single fp16 + V single (1-term PV, trans-ldmatrix on V[kv][d]).
// Softmax in exp2 domain (Q pre-scaled by log2e). Bq=128, Bk=64, 128 thr.
// ---------------------------------------------------------------------------
#define BQ 128
#define APAD 72
#define QMAT (BQ*APAD)
#define KMAT (64*APAD)
#define ASMEM ((2*QMAT + 4*KMAT)*2)  // 73728 B

__device__ __forceinline__ void issue_kv(uint32_t sK, uint32_t sV,
                                         const __half* gK, const __half* gV,
                                         int kv0, int tid) {
#pragma unroll
    for (int it = 0; it < 4; it++) {
        int idx = it * 128 + tid;
        int row = idx >> 3, seg = idx & 7;
        uint32_t so = (uint32_t)(row * APAD + seg * 8) * 2;
        size_t g = (size_t)(kv0 + row) * HD + seg * 8;
        cp_async16(sK + so, gK + g);
        cp_async16(sV + so, gV + g);
    }
    cp_commit();
}

__global__ __launch_bounds__(128, 2) void attn_tc() {
    extern __shared__ __half sa[];
    uint32_t sQh = smem_u32(sa);
    uint32_t sQl = sQh + QMAT * 2;
    uint32_t sKV0 = sQl + QMAT * 2;            // K0 | V0 | K1 | V1
    uint32_t sK[2] = {sKV0, sKV0 + 2 * KMAT * 2};
    uint32_t sV[2] = {sKV0 + KMAT * 2, sKV0 + 3 * KMAT * 2};

    int tid = threadIdx.x;
    int lane = tid & 31, w = tid >> 5;
    int bh = blockIdx.y;
    int qtile = (gridDim.x - 1) - blockIdx.x;    // heavy tiles first
    int q0 = qtile * BQ;

    const __half* gQh = g_Qhi + (size_t)bh * Tt * HD;
    const __half* gQl = g_Qlo + (size_t)bh * Tt * HD;
    const __half* gK  = g_K  + (size_t)bh * Tt * HD;
    const __half* gV  = g_V  + (size_t)bh * Tt * HD;

    // group 1: Q tile (128 x 64), hi+lo
#pragma unroll
    for (int it = 0; it < 8; it++) {
        int idx = it * 128 + tid;
        int row = idx >> 3, seg = idx & 7;
        uint32_t so = (uint32_t)(row * APAD + seg * 8) * 2;
        size_t go = (size_t)(q0 + row) * HD + seg * 8;
        cp_async16(sQh + so, gQh + go);
        cp_async16(sQl + so, gQl + go);
    }
    cp_commit();
    // group 2: KV tile 0
    issue_kv(sK[0], sV[0], gK, gV, 0, tid);

    float o[2][8][4] = {};
    float mrow[2][2] = {{-1e30f, -1e30f}, {-1e30f, -1e30f}};
    float lrow[2][2] = {};

    int r0 = lane >> 2;

    int ktmax = 2 * qtile + 1;
    for (int kt = 0; kt <= ktmax; kt++) {
        int kv0 = kt * 64;
        int b = kt & 1;
        if (kt + 1 <= ktmax) {
            __syncthreads();
            issue_kv(sK[b ^ 1], sV[b ^ 1], gK, gV, (kt + 1) * 64, tid);
            asm volatile("cp.async.wait_group 1;" ::: "memory");
        } else {
            asm volatile("cp.async.wait_group 0;" ::: "memory");
        }
        __syncthreads();

        // ---- S = Q K^T  (Qh·K then Ql·K); result in log2 domain ----
        float s[2][8][4] = {};
#pragma unroll
        for (int ks = 0; ks < 4; ks++) {
            uint32_t aq_h[2][4], bk[4][4];
#pragma unroll
            for (int mt = 0; mt < 2; mt++)
                LDSM_X4(aq_h[mt], sQh + (uint32_t)((w * 32 + mt * 16 + (lane & 15)) * APAD +
                                                   ks * 16 + (lane >> 4) * 8) * 2);
#pragma unroll
            for (int ntp = 0; ntp < 4; ntp++)
                LDSM_X4(bk[ntp], sK[b] + (uint32_t)((ntp * 16 + (lane >> 4) * 8 + (lane & 7)) * APAD +
                                                    ks * 16 + ((lane >> 3) & 1) * 8) * 2);
#pragma unroll
            for (int ntp = 0; ntp < 4; ntp++)
#pragma unroll
                for (int mt = 0; mt < 2; mt++)
#pragma unroll
                    for (int h2 = 0; h2 < 2; h2++)
                        MMA16816(s[mt][ntp * 2 + h2], aq_h[mt],
                                 bk[ntp][h2 * 2], bk[ntp][h2 * 2 + 1]);
            {
                uint32_t aq_l[2][4];
#pragma unroll
                for (int mt = 0; mt < 2; mt++)
                    LDSM_X4(aq_l[mt], sQl + (uint32_t)((w * 32 + mt * 16 + (lane & 15)) * APAD +
                                                       ks * 16 + (lane >> 4) * 8) * 2);
#pragma unroll
                for (int ntp = 0; ntp < 4; ntp++)
#pragma unroll
                    for (int mt = 0; mt < 2; mt++)
#pragma unroll
                        for (int h2 = 0; h2 < 2; h2++)
                            MMA16816(s[mt][ntp * 2 + h2], aq_l[mt],
                                     bk[ntp][h2 * 2], bk[ntp][h2 * 2 + 1]);
            }
        }

        // causal mask
        if (kv0 + 63 > q0 + w * 32) {
#pragma unroll
            for (int mt = 0; mt < 2; mt++)
#pragma unroll
                for (int nt = 0; nt < 8; nt++)
#pragma unroll
                    for (int j = 0; j < 4; j++) {
                        int c = kv0 + nt * 8 + (lane & 3) * 2 + (j & 1);
                        int r = q0 + w * 32 + mt * 16 + r0 + ((j >> 1) ? 8 : 0);
                        if (c > r) s[mt][nt][j] = -1e30f;
                    }
        }

        // ---- online softmax (exp2 domain) ----
#pragma unroll
        for (int mt = 0; mt < 2; mt++)
#pragma unroll
            for (int rr = 0; rr < 2; rr++) {
                float rm = -1e30f;
#pragma unroll
                for (int nt = 0; nt < 8; nt++)
                    rm = fmaxf(rm, fmaxf(s[mt][nt][rr * 2], s[mt][nt][rr * 2 + 1]));
                rm = fmaxf(rm, __shfl_xor_sync(0xffffffffu, rm, 1));
                rm = fmaxf(rm, __shfl_xor_sync(0xffffffffu, rm, 2));
                float mnew = fmaxf(mrow[mt][rr], rm);
                float alpha = ex2f(mrow[mt][rr] - mnew);
                mrow[mt][rr] = mnew;
                float rs = 0.0f;
#pragma unroll
                for (int nt = 0; nt < 8; nt++) {
                    s[mt][nt][rr * 2]     = ex2f(s[mt][nt][rr * 2] - mnew);
                    s[mt][nt][rr * 2 + 1] = ex2f(s[mt][nt][rr * 2 + 1] - mnew);
                    rs += s[mt][nt][rr * 2] + s[mt][nt][rr * 2 + 1];
                }
                rs += __shfl_xor_sync(0xffffffffu, rs, 1);
                rs += __shfl_xor_sync(0xffffffffu, rs, 2);
                lrow[mt][rr] = lrow[mt][rr] * alpha + rs;
#pragma unroll
                for (int dt = 0; dt < 8; dt++) {
                    o[mt][dt][rr * 2]     *= alpha;
                    o[mt][dt][rr * 2 + 1] *= alpha;
                }
            }

        // ---- O += P V  (P single fp16; V via trans-ldmatrix on [kv][d]) ----
#pragma unroll
        for (int ksv = 0; ksv < 4; ksv++) {
            uint32_t pah[2][4];
#pragma unroll
            for (int mt = 0; mt < 2; mt++)
#pragma unroll
                for (int q = 0; q < 4; q++) {
                    int nt = 2 * ksv + (q >> 1);
                    int j0 = (q & 1) * 2;
                    __half2 hv = __floats2half2_rn(s[mt][nt][j0], s[mt][nt][j0 + 1]);
                    pah[mt][q] = *(uint32_t*)&hv;
                }
            uint32_t bv[4][4];
#pragma unroll
            for (int dtp = 0; dtp < 4; dtp++) {
                uint32_t addr = sV[b] + (uint32_t)(
                    (ksv * 16 + ((lane >> 3) & 1) * 8 + (lane & 7)) * APAD +
                    dtp * 16 + (lane >> 4) * 8) * 2;
                LDSM_X4_T(bv[dtp], addr);
            }
#pragma unroll
            for (int dtp = 0; dtp < 4; dtp++)
#pragma unroll
                for (int mt = 0; mt < 2; mt++)
#pragma unroll
                    for (int h2 = 0; h2 < 2; h2++)
                        MMA16816(o[mt][dtp * 2 + h2], pah[mt],
                                 bv[dtp][h2 * 2], bv[dtp][h2 * 2 + 1]);
        }
    }

    // ---- epilogue: normalize, emit Y as fp16 hi/lo [B,T,C] ----
    int bb = bh >> 4, h = bh & 15;
#pragma unroll
    for (int mt = 0; mt < 2; mt++) {
        float inv0 = 1.0f / lrow[mt][0];
        float inv1 = 1.0f / lrow[mt][1];
        int gq0 = q0 + w * 32 + mt * 16 + r0;
        int gq1 = gq0 + 8;
#pragma unroll
        for (int dt = 0; dt < 8; dt++) {
            int col = h * HD + dt * 8 + (lane & 3) * 2;
            size_t o0 = (size_t)(bb * Tt + gq0) * Cc + col;
            size_t o1 = (size_t)(bb * Tt + gq1) * Cc + col;
            float y0 = o[mt][dt][0] * inv0, y1 = o[mt][dt][1] * inv0;
            float y2 = o[mt][dt][2] * inv1, y3 = o[mt][dt][3] * inv1;
            __half2 hv = __floats2half2_rn(y0, y1);
            __half2 lv = __floats2half2_rn(y0 - __half2float(hv.x),
                                           y1 - __half2float(hv.y));
            *(__half2*)&g_Yhi[o0] = hv;
            *(__half2*)&g_Ylo[o0] = lv;
            hv = __floats2half2_rn(y2, y3);
            lv = __floats2half2_rn(y2 - __half2float(hv.x),
                                   y3 - __half2float(hv.y));
            *(__half2*)&g_Yhi[o1] = hv;
            *(__half2*)&g_Ylo[o1] = lv;
        }
    }
}

// ---------------------------------------------------------------------------
extern "C" void kernel_launch(void* const* d_in, const int* in_sizes, int n_in,
                              void* d_out, int out_size) {
    const float* x      = (const float*)d_in[0];
    const float* W_attn = (const float*)d_in[1];
    const float* b_attn = (const float*)d_in[2];
    const float* W_proj = (const float*)d_in[3];
    const float* b_proj = (const float*)d_in[4];
    float* out = (float*)d_out;

    __half *xhi, *xlo, *wa, *wp, *yhi, *ylo;
    cudaGetSymbolAddress((void**)&xhi, g_Xhi);
    cudaGetSymbolAddress((void**)&xlo, g_Xlo);
    cudaGetSymbolAddress((void**)&wa,  g_WA);
    cudaGetSymbolAddress((void**)&wp,  g_WP);
    cudaGetSymbolAddress((void**)&yhi, g_Yhi);
    cudaGetSymbolAddress((void**)&ylo, g_Ylo);

    cudaFuncSetAttribute(tc_gemm<0>, cudaFuncAttributeMaxDynamicSharedMemorySize, GSMEM);
    cudaFuncSetAttribute(tc_gemm<1>, cudaFuncAttributeMaxDynamicSharedMemorySize, GSMEM);
    cudaFuncSetAttribute(attn_tc, cudaFuncAttributeMaxDynamicSharedMemorySize, ASMEM);

    convert_x_kernel<<<1024, 256>>>((const float4*)x, MR * Cc / 4);
    transconv_kernel<<<dim3(3 * Cc / 32, Cc / 32), dim3(32, 8)>>>(W_attn, wa, Cc, 3 * Cc);
    transconv_kernel<<<dim3(Cc / 32, Cc / 32), dim3(32, 8)>>>(W_proj, wp, Cc, Cc);

    tc_gemm<0><<<dim3(3 * Cc / 128, MR / 128), 128, GSMEM>>>(xhi, xlo, wa, b_attn, nullptr);

    attn_tc<<<dim3(Tt / BQ, Bb * Hh), 128, ASMEM>>>();

    tc_gemm<1><<<dim3(Cc / 128, MR / 128), 128, GSMEM>>>(yhi, ylo, wp, b_proj, out);
}

// round 14
// speedup vs baseline: 2.2998x; 1.3636x over previous
#include <cuda_runtime.h>
#include <cuda_fp16.h>
#include <cstdint>

#define Bb 4
#define Tt 2048
#define Cc 1024
#define Hh 16
#define HD 64
#define MR (Bb*Tt)      // 8192 rows

// ---------------------------------------------------------------------------
// device scratch (allocation-free rule)
// ---------------------------------------------------------------------------
__device__ __half g_Qhi[Bb*Hh*Tt*HD];
__device__ __half g_Qlo[Bb*Hh*Tt*HD];
__device__ __half g_K  [Bb*Hh*Tt*HD];
__device__ __half g_V  [Bb*Hh*Tt*HD];
__device__ __half g_X  [MR*Cc];          // single fp16
__device__ __half g_WA [3*Cc*Cc];        // [N,K] single fp16
__device__ __half g_WP [Cc*Cc];
__device__ __half g_Y  [MR*Cc];          // single fp16

// ---------------------------------------------------------------------------
// helpers (base sm_10x-legal PTX only: cp.async / ldmatrix / mma.sync)
// ---------------------------------------------------------------------------
__device__ __forceinline__ uint32_t smem_u32(const void* p) {
    uint32_t a;
    asm("{ .reg .u64 t; cvta.to.shared.u64 t, %1; cvt.u32.u64 %0, t; }" : "=r"(a) : "l"(p));
    return a;
}

__device__ __forceinline__ void cp_async16(uint32_t s, const void* g) {
    asm volatile("cp.async.cg.shared.global [%0], [%1], 16;" :: "r"(s), "l"(g));
}
__device__ __forceinline__ void cp_commit() {
    asm volatile("cp.async.commit_group;" ::: "memory");
}

__device__ __forceinline__ float ex2f(float x) {
    float r;
    asm("ex2.approx.ftz.f32 %0, %1;" : "=f"(r) : "f"(x));
    return r;
}

#define LDSM_X4(r, addr) \
    asm volatile("ldmatrix.sync.aligned.m8n8.x4.shared.b16 {%0,%1,%2,%3}, [%4];" \
        : "=r"((r)[0]), "=r"((r)[1]), "=r"((r)[2]), "=r"((r)[3]) : "r"(addr))

#define LDSM_X4_T(r, addr) \
    asm volatile("ldmatrix.sync.aligned.m8n8.x4.trans.shared.b16 {%0,%1,%2,%3}, [%4];" \
        : "=r"((r)[0]), "=r"((r)[1]), "=r"((r)[2]), "=r"((r)[3]) : "r"(addr))

#define MMA16816(c, a, b0v, b1v) \
    asm volatile("mma.sync.aligned.m16n8k16.row.col.f32.f16.f16.f32 " \
        "{%0,%1,%2,%3}, {%4,%5,%6,%7}, {%8,%9}, {%0,%1,%2,%3};" \
        : "+f"((c)[0]), "+f"((c)[1]), "+f"((c)[2]), "+f"((c)[3]) \
        : "r"((a)[0]), "r"((a)[1]), "r"((a)[2]), "r"((a)[3]), "r"(b0v), "r"(b1v))

// ---------------------------------------------------------------------------
// prep kernels
// ---------------------------------------------------------------------------
__global__ void convert_x_kernel(const float4* __restrict__ x, int n4) {
    __half2* d2 = (__half2*)g_X;
    for (int i = blockIdx.x * blockDim.x + threadIdx.x; i < n4; i += gridDim.x * blockDim.x) {
        float4 v = x[i];
        d2[i * 2]     = __floats2half2_rn(v.x, v.y);
        d2[i * 2 + 1] = __floats2half2_rn(v.z, v.w);
    }
}

// src [K,N] fp32 -> dst [N,K] single fp16
__global__ void transconv_kernel(const float* __restrict__ src, __half* __restrict__ dst,
                                 int K, int N) {
    __shared__ float sm[32][33];
    int n0 = blockIdx.x * 32, k0 = blockIdx.y * 32;
    int tx = threadIdx.x, ty = threadIdx.y;   // 32 x 8
#pragma unroll
    for (int i = 0; i < 32; i += 8)
        sm[ty + i][tx] = src[(size_t)(k0 + ty + i) * N + n0 + tx];
    __syncthreads();
#pragma unroll
    for (int i = 0; i < 32; i += 8)
        dst[(size_t)(n0 + ty + i) * K + k0 + tx] = __float2half(sm[tx][ty + i]);
}

// ---------------------------------------------------------------------------
// HMMA fp16 GEMM, single-precision-fp16 A and B (1 MMA term).
// CTA 128x128, 4 warps of 64x64, 128 threads, 2 CTAs/SM, BK=64, x2 buffered.
// MODE 0: emit Qhi/Qlo(0.18034x = 0.125*log2e), K, V (fp16) into [bh][t][d].
// MODE 1: row-major fp32 out [MR,Cc].
// ---------------------------------------------------------------------------
#define BK 64
#define PAD 72
#define MATB (128*PAD*2)             // 18432 per matrix (A | B)
#define BUFB (2*MATB)                // 36864
#define GSMEM (2*BUFB)               // 73728

#define QSCALE 0.1803368801111f      // 0.125 * log2(e)

__device__ __forceinline__ void issue_chunk(
    uint32_t sbase,
    const __half* __restrict__ Am, const __half* __restrict__ Bm,
    int m0, int n0, int kc, int tid)
{
#pragma unroll
    for (int it = 0; it < 8; it++) {
        int idx = it * 128 + tid;            // 0..1023
        int row = idx >> 3, seg = idx & 7;
        uint32_t soff = (uint32_t)(row * PAD + seg * 8) * 2;
        size_t ga = (size_t)(m0 + row) * Cc + kc + seg * 8;
        size_t gb = (size_t)(n0 + row) * Cc + kc + seg * 8;
        cp_async16(sbase + soff,        Am + ga);
        cp_async16(sbase + MATB + soff, Bm + gb);
    }
    cp_commit();
}

template <int MODE>
__global__ __launch_bounds__(128, 2)
void tc_gemm(const __half* __restrict__ Am, const __half* __restrict__ Bm,
             const float* __restrict__ bias, float* __restrict__ out) {
    extern __shared__ char smx[];
    uint32_t sb = smem_u32(smx);
    int tid = threadIdx.x;
    int lane = tid & 31, warp = tid >> 5;
    int wm = warp >> 1;         // 2 m-warps (64 rows each)
    int wn = warp & 1;          // 2 n-warps (64 cols each)
    int m0 = blockIdx.y * 128, n0 = blockIdx.x * 128;

    float acc[4][8][4] = {};    // 64x64 per warp

    issue_chunk(sb, Am, Bm, m0, n0, 0, tid);

    const int NCH = Cc / BK;   // 16
    int arow = wm * 64 + (lane & 15);
    int acol_base = (lane >> 4) * 8;
    int brow = wn * 64 + (lane >> 4) * 8 + (lane & 7);
    int bcol_base = ((lane >> 3) & 1) * 8;

    for (int i = 0; i < NCH; i++) {
        if (i + 1 < NCH) {
            issue_chunk(sb + ((i + 1) & 1) * BUFB, Am, Bm, m0, n0, (i + 1) * BK, tid);
            asm volatile("cp.async.wait_group 1;" ::: "memory");
        } else {
            asm volatile("cp.async.wait_group 0;" ::: "memory");
        }
        __syncthreads();
        uint32_t buf = sb + (i & 1) * BUFB;

#pragma unroll
        for (int ks = 0; ks < 4; ks++) {
            int acol = ks * 16 + acol_base;
            int bcol = ks * 16 + bcol_base;
            uint32_t ah[4][4], bf4[4][4];
#pragma unroll
            for (int mt = 0; mt < 4; mt++)
                LDSM_X4(ah[mt], buf + (uint32_t)((arow + mt * 16) * PAD + acol) * 2);
#pragma unroll
            for (int np = 0; np < 4; np++)
                LDSM_X4(bf4[np], buf + MATB + (uint32_t)((brow + np * 16) * PAD + bcol) * 2);
#pragma unroll
            for (int np = 0; np < 4; np++)
#pragma unroll
                for (int mt = 0; mt < 4; mt++)
#pragma unroll
                    for (int half = 0; half < 2; half++)
                        MMA16816(acc[mt][np * 2 + half], ah[mt],
                                 bf4[np][half * 2], bf4[np][half * 2 + 1]);
        }
        __syncthreads();
    }

    int mrow = m0 + wm * 64 + (lane >> 2);
#pragma unroll
    for (int mt = 0; mt < 4; mt++) {
#pragma unroll
        for (int nt = 0; nt < 8; nt++) {
            int n = n0 + wn * 64 + nt * 8 + (lane & 3) * 2;
            float bx = bias[n], by = bias[n + 1];
            float2 v0 = make_float2(acc[mt][nt][0] + bx, acc[mt][nt][1] + by);
            float2 v1 = make_float2(acc[mt][nt][2] + bx, acc[mt][nt][3] + by);
            int m_a = mrow + mt * 16;
            int m_b = m_a + 8;
            if (MODE == 0) {
                int sec = n >> 10;
                int c2 = n & (Cc - 1);
                int h = c2 >> 6, d = c2 & 63;
                int ba = m_a >> 11, ta = m_a & (Tt - 1);
                int bb2 = m_b >> 11, tb = m_b & (Tt - 1);
                size_t o0 = (((size_t)(ba * Hh + h)) * Tt + ta) * HD + d;
                size_t o1 = (((size_t)(bb2 * Hh + h)) * Tt + tb) * HD + d;
                if (sec == 0) {
                    v0.x *= QSCALE; v0.y *= QSCALE; v1.x *= QSCALE; v1.y *= QSCALE;
                    __half2 hi = __floats2half2_rn(v0.x, v0.y);
                    __half2 lo = __floats2half2_rn(v0.x - __half2float(hi.x),
                                                   v0.y - __half2float(hi.y));
                    *(__half2*)&g_Qhi[o0] = hi;
                    *(__half2*)&g_Qlo[o0] = lo;
                    hi = __floats2half2_rn(v1.x, v1.y);
                    lo = __floats2half2_rn(v1.x - __half2float(hi.x),
                                           v1.y - __half2float(hi.y));
                    *(__half2*)&g_Qhi[o1] = hi;
                    *(__half2*)&g_Qlo[o1] = lo;
                } else {
                    __half* dst = (sec == 1) ? g_K : g_V;
                    *(__half2*)&dst[o0] = __floats2half2_rn(v0.x, v0.y);
                    *(__half2*)&dst[o1] = __floats2half2_rn(v1.x, v1.y);
                }
            } else {
                *(float2*)&out[(size_t)m_a * Cc + n] = v0;
                *(float2*)&out[(size_t)m_b * Cc + n] = v1;
            }
        }
    }
}

// ---------------------------------------------------------------------------
// Tensor-core flash attention, fp16: Q split hi/lo + K single (2-term S),
// P single fp16 + V single (1-term PV, trans-ldmatrix on V[kv][d]).
// Softmax in exp2 domain (Q pre-scaled by log2e). Bq=128, Bk=64, 128 thr.
// ---------------------------------------------------------------------------
#define BQ 128
#define APAD 72
#define QMAT (BQ*APAD)
#define KMAT (64*APAD)
#define ASMEM ((2*QMAT + 4*KMAT)*2)  // 73728 B

__device__ __forceinline__ void issue_kv(uint32_t sK, uint32_t sV,
                                         const __half* gK, const __half* gV,
                                         int kv0, int tid) {
#pragma unroll
    for (int it = 0; it < 4; it++) {
        int idx = it * 128 + tid;
        int row = idx >> 3, seg = idx & 7;
        uint32_t so = (uint32_t)(row * APAD + seg * 8) * 2;
        size_t g = (size_t)(kv0 + row) * HD + seg * 8;
        cp_async16(sK + so, gK + g);
        cp_async16(sV + so, gV + g);
    }
    cp_commit();
}

__global__ __launch_bounds__(128, 2) void attn_tc() {
    extern __shared__ __half sa[];
    uint32_t sQh = smem_u32(sa);
    uint32_t sQl = sQh + QMAT * 2;
    uint32_t sKV0 = sQl + QMAT * 2;            // K0 | V0 | K1 | V1
    uint32_t sK[2] = {sKV0, sKV0 + 2 * KMAT * 2};
    uint32_t sV[2] = {sKV0 + KMAT * 2, sKV0 + 3 * KMAT * 2};

    int tid = threadIdx.x;
    int lane = tid & 31, w = tid >> 5;
    int bh = blockIdx.y;
    int qtile = (gridDim.x - 1) - blockIdx.x;    // heavy tiles first
    int q0 = qtile * BQ;

    const __half* gQh = g_Qhi + (size_t)bh * Tt * HD;
    const __half* gQl = g_Qlo + (size_t)bh * Tt * HD;
    const __half* gK  = g_K  + (size_t)bh * Tt * HD;
    const __half* gV  = g_V  + (size_t)bh * Tt * HD;

    // group 1: Q tile (128 x 64), hi+lo
#pragma unroll
    for (int it = 0; it < 8; it++) {
        int idx = it * 128 + tid;
        int row = idx >> 3, seg = idx & 7;
        uint32_t so = (uint32_t)(row * APAD + seg * 8) * 2;
        size_t go = (size_t)(q0 + row) * HD + seg * 8;
        cp_async16(sQh + so, gQh + go);
        cp_async16(sQl + so, gQl + go);
    }
    cp_commit();
    // group 2: KV tile 0
    issue_kv(sK[0], sV[0], gK, gV, 0, tid);

    float o[2][8][4] = {};
    float mrow[2][2] = {{-1e30f, -1e30f}, {-1e30f, -1e30f}};
    float lrow[2][2] = {};

    int r0 = lane >> 2;

    int ktmax = 2 * qtile + 1;
    for (int kt = 0; kt <= ktmax; kt++) {
        int kv0 = kt * 64;
        int b = kt & 1;
        if (kt + 1 <= ktmax) {
            __syncthreads();
            issue_kv(sK[b ^ 1], sV[b ^ 1], gK, gV, (kt + 1) * 64, tid);
            asm volatile("cp.async.wait_group 1;" ::: "memory");
        } else {
            asm volatile("cp.async.wait_group 0;" ::: "memory");
        }
        __syncthreads();

        // ---- S = Q K^T  (Qh·K then Ql·K); result in log2 domain ----
        float s[2][8][4] = {};
#pragma unroll
        for (int ks = 0; ks < 4; ks++) {
            uint32_t aq_h[2][4], bk[4][4];
#pragma unroll
            for (int mt = 0; mt < 2; mt++)
                LDSM_X4(aq_h[mt], sQh + (uint32_t)((w * 32 + mt * 16 + (lane & 15)) * APAD +
                                                   ks * 16 + (lane >> 4) * 8) * 2);
#pragma unroll
            for (int ntp = 0; ntp < 4; ntp++)
                LDSM_X4(bk[ntp], sK[b] + (uint32_t)((ntp * 16 + (lane >> 4) * 8 + (lane & 7)) * APAD +
                                                    ks * 16 + ((lane >> 3) & 1) * 8) * 2);
#pragma unroll
            for (int ntp = 0; ntp < 4; ntp++)
#pragma unroll
                for (int mt = 0; mt < 2; mt++)
#pragma unroll
                    for (int h2 = 0; h2 < 2; h2++)
                        MMA16816(s[mt][ntp * 2 + h2], aq_h[mt],
                                 bk[ntp][h2 * 2], bk[ntp][h2 * 2 + 1]);
            {
                uint32_t aq_l[2][4];
#pragma unroll
                for (int mt = 0; mt < 2; mt++)
                    LDSM_X4(aq_l[mt], sQl + (uint32_t)((w * 32 + mt * 16 + (lane & 15)) * APAD +
                                                       ks * 16 + (lane >> 4) * 8) * 2);
#pragma unroll
                for (int ntp = 0; ntp < 4; ntp++)
#pragma unroll
                    for (int mt = 0; mt < 2; mt++)
#pragma unroll
                        for (int h2 = 0; h2 < 2; h2++)
                            MMA16816(s[mt][ntp * 2 + h2], aq_l[mt],
                                     bk[ntp][h2 * 2], bk[ntp][h2 * 2 + 1]);
            }
        }

        // causal mask
        if (kv0 + 63 > q0 + w * 32) {
#pragma unroll
            for (int mt = 0; mt < 2; mt++)
#pragma unroll
                for (int nt = 0; nt < 8; nt++)
#pragma unroll
                    for (int j = 0; j < 4; j++) {
                        int c = kv0 + nt * 8 + (lane & 3) * 2 + (j & 1);
                        int r = q0 + w * 32 + mt * 16 + r0 + ((j >> 1) ? 8 : 0);
                        if (c > r) s[mt][nt][j] = -1e30f;
                    }
        }

        // ---- online softmax (exp2 domain) ----
#pragma unroll
        for (int mt = 0; mt < 2; mt++)
#pragma unroll
            for (int rr = 0; rr < 2; rr++) {
                float rm = -1e30f;
#pragma unroll
                for (int nt = 0; nt < 8; nt++)
                    rm = fmaxf(rm, fmaxf(s[mt][nt][rr * 2], s[mt][nt][rr * 2 + 1]));
                rm = fmaxf(rm, __shfl_xor_sync(0xffffffffu, rm, 1));
                rm = fmaxf(rm, __shfl_xor_sync(0xffffffffu, rm, 2));
                float mnew = fmaxf(mrow[mt][rr], rm);
                float alpha = ex2f(mrow[mt][rr] - mnew);
                mrow[mt][rr] = mnew;
                float rs = 0.0f;
#pragma unroll
                for (int nt = 0; nt < 8; nt++) {
                    s[mt][nt][rr * 2]     = ex2f(s[mt][nt][rr * 2] - mnew);
                    s[mt][nt][rr * 2 + 1] = ex2f(s[mt][nt][rr * 2 + 1] - mnew);
                    rs += s[mt][nt][rr * 2] + s[mt][nt][rr * 2 + 1];
                }
                rs += __shfl_xor_sync(0xffffffffu, rs, 1);
                rs += __shfl_xor_sync(0xffffffffu, rs, 2);
                lrow[mt][rr] = lrow[mt][rr] * alpha + rs;
#pragma unroll
                for (int dt = 0; dt < 8; dt++) {
                    o[mt][dt][rr * 2]     *= alpha;
                    o[mt][dt][rr * 2 + 1] *= alpha;
                }
            }

        // ---- O += P V  (P single fp16; V via trans-ldmatrix on [kv][d]) ----
#pragma unroll
        for (int ksv = 0; ksv < 4; ksv++) {
            uint32_t pah[2][4];
#pragma unroll
            for (int mt = 0; mt < 2; mt++)
#pragma unroll
                for (int q = 0; q < 4; q++) {
                    int nt = 2 * ksv + (q >> 1);
                    int j0 = (q & 1) * 2;
                    __half2 hv = __floats2half2_rn(s[mt][nt][j0], s[mt][nt][j0 + 1]);
                    pah[mt][q] = *(uint32_t*)&hv;
                }
            uint32_t bv[4][4];
#pragma unroll
            for (int dtp = 0; dtp < 4; dtp++) {
                uint32_t addr = sV[b] + (uint32_t)(
                    (ksv * 16 + ((lane >> 3) & 1) * 8 + (lane & 7)) * APAD +
                    dtp * 16 + (lane >> 4) * 8) * 2;
                LDSM_X4_T(bv[dtp], addr);
            }
#pragma unroll
            for (int dtp = 0; dtp < 4; dtp++)
#pragma unroll
                for (int mt = 0; mt < 2; mt++)
#pragma unroll
                    for (int h2 = 0; h2 < 2; h2++)
                        MMA16816(o[mt][dtp * 2 + h2], pah[mt],
                                 bv[dtp][h2 * 2], bv[dtp][h2 * 2 + 1]);
        }
    }

    // ---- epilogue: normalize, emit Y single fp16 [B,T,C] ----
    int bb = bh >> 4, h = bh & 15;
#pragma unroll
    for (int mt = 0; mt < 2; mt++) {
        float inv0 = 1.0f / lrow[mt][0];
        float inv1 = 1.0f / lrow[mt][1];
        int gq0 = q0 + w * 32 + mt * 16 + r0;
        int gq1 = gq0 + 8;
#pragma unroll
        for (int dt = 0; dt < 8; dt++) {
            int col = h * HD + dt * 8 + (lane & 3) * 2;
            size_t o0 = (size_t)(bb * Tt + gq0) * Cc + col;
            size_t o1 = (size_t)(bb * Tt + gq1) * Cc + col;
            *(__half2*)&g_Y[o0] = __floats2half2_rn(o[mt][dt][0] * inv0, o[mt][dt][1] * inv0);
            *(__half2*)&g_Y[o1] = __floats2half2_rn(o[mt][dt][2] * inv1, o[mt][dt][3] * inv1);
        }
    }
}

// ---------------------------------------------------------------------------
extern "C" void kernel_launch(void* const* d_in, const int* in_sizes, int n_in,
                              void* d_out, int out_size) {
    const float* x      = (const float*)d_in[0];
    const float* W_attn = (const float*)d_in[1];
    const float* b_attn = (const float*)d_in[2];
    const float* W_proj = (const float*)d_in[3];
    const float* b_proj = (const float*)d_in[4];
    float* out = (float*)d_out;

    __half *xp, *wa, *wp, *yp;
    cudaGetSymbolAddress((void**)&xp, g_X);
    cudaGetSymbolAddress((void**)&wa, g_WA);
    cudaGetSymbolAddress((void**)&wp, g_WP);
    cudaGetSymbolAddress((void**)&yp, g_Y);

    cudaFuncSetAttribute(tc_gemm<0>, cudaFuncAttributeMaxDynamicSharedMemorySize, GSMEM);
    cudaFuncSetAttribute(tc_gemm<1>, cudaFuncAttributeMaxDynamicSharedMemorySize, GSMEM);
    cudaFuncSetAttribute(attn_tc, cudaFuncAttributeMaxDynamicSharedMemorySize, ASMEM);

    convert_x_kernel<<<1024, 256>>>((const float4*)x, MR * Cc / 4);
    transconv_kernel<<<dim3(3 * Cc / 32, Cc / 32), dim3(32, 8)>>>(W_attn, wa, Cc, 3 * Cc);
    transconv_kernel<<<dim3(Cc / 32, Cc / 32), dim3(32, 8)>>>(W_proj, wp, Cc, Cc);

    tc_gemm<0><<<dim3(3 * Cc / 128, MR / 128), 128, GSMEM>>>(xp, wa, b_attn, nullptr);

    attn_tc<<<dim3(Tt / BQ, Bb * Hh), 128, ASMEM>>>();

    tc_gemm<1><<<dim3(Cc / 128, MR / 128), 128, GSMEM>>>(yp, wp, b_proj, out);
}

// round 15
// speedup vs baseline: 2.3482x; 1.0210x over previous
#include <cuda_runtime.h>
#include <cuda_fp16.h>
#include <cstdint>

#define Bb 4
#define Tt 2048
#define Cc 1024
#define Hh 16
#define HD 64
#define MR (Bb*Tt)      // 8192 rows

// ---------------------------------------------------------------------------
// device scratch (allocation-free rule)
// ---------------------------------------------------------------------------
__device__ __half g_Qhi[Bb*Hh*Tt*HD];
__device__ __half g_Qlo[Bb*Hh*Tt*HD];
__device__ __half g_K  [Bb*Hh*Tt*HD];
__device__ __half g_V  [Bb*Hh*Tt*HD];
__device__ __half g_X  [MR*Cc];
__device__ __half g_WA [3*Cc*Cc];        // [N,K] single fp16
__device__ __half g_WP [Cc*Cc];
__device__ __half g_Y  [MR*Cc];

// ---------------------------------------------------------------------------
// helpers (base sm_10x-legal PTX only: cp.async / ldmatrix / mma.sync)
// ---------------------------------------------------------------------------
__device__ __forceinline__ uint32_t smem_u32(const void* p) {
    uint32_t a;
    asm("{ .reg .u64 t; cvta.to.shared.u64 t, %1; cvt.u32.u64 %0, t; }" : "=r"(a) : "l"(p));
    return a;
}

__device__ __forceinline__ void cp_async16(uint32_t s, const void* g) {
    asm volatile("cp.async.cg.shared.global [%0], [%1], 16;" :: "r"(s), "l"(g));
}
__device__ __forceinline__ void cp_commit() {
    asm volatile("cp.async.commit_group;" ::: "memory");
}

__device__ __forceinline__ float ex2f(float x) {
    float r;
    asm("ex2.approx.ftz.f32 %0, %1;" : "=f"(r) : "f"(x));
    return r;
}

#define LDSM_X4(r, addr) \
    asm volatile("ldmatrix.sync.aligned.m8n8.x4.shared.b16 {%0,%1,%2,%3}, [%4];" \
        : "=r"((r)[0]), "=r"((r)[1]), "=r"((r)[2]), "=r"((r)[3]) : "r"(addr))

#define LDSM_X4_T(r, addr) \
    asm volatile("ldmatrix.sync.aligned.m8n8.x4.trans.shared.b16 {%0,%1,%2,%3}, [%4];" \
        : "=r"((r)[0]), "=r"((r)[1]), "=r"((r)[2]), "=r"((r)[3]) : "r"(addr))

#define MMA16816(c, a, b0v, b1v) \
    asm volatile("mma.sync.aligned.m16n8k16.row.col.f32.f16.f16.f32 " \
        "{%0,%1,%2,%3}, {%4,%5,%6,%7}, {%8,%9}, {%0,%1,%2,%3};" \
        : "+f"((c)[0]), "+f"((c)[1]), "+f"((c)[2]), "+f"((c)[3]) \
        : "r"((a)[0]), "r"((a)[1]), "r"((a)[2]), "r"((a)[3]), "r"(b0v), "r"(b1v))

// ---------------------------------------------------------------------------
// prep kernels
// ---------------------------------------------------------------------------
__global__ void convert_x_kernel(const float4* __restrict__ x, int n4) {
    __half2* d2 = (__half2*)g_X;
    for (int i = blockIdx.x * blockDim.x + threadIdx.x; i < n4; i += gridDim.x * blockDim.x) {
        float4 v = x[i];
        d2[i * 2]     = __floats2half2_rn(v.x, v.y);
        d2[i * 2 + 1] = __floats2half2_rn(v.z, v.w);
    }
}

// src [K,N] fp32 -> dst [N,K] single fp16
__global__ void transconv_kernel(const float* __restrict__ src, __half* __restrict__ dst,
                                 int K, int N) {
    __shared__ float sm[32][33];
    int n0 = blockIdx.x * 32, k0 = blockIdx.y * 32;
    int tx = threadIdx.x, ty = threadIdx.y;   // 32 x 8
#pragma unroll
    for (int i = 0; i < 32; i += 8)
        sm[ty + i][tx] = src[(size_t)(k0 + ty + i) * N + n0 + tx];
    __syncthreads();
#pragma unroll
    for (int i = 0; i < 32; i += 8)
        dst[(size_t)(n0 + ty + i) * K + k0 + tx] = __float2half(sm[tx][ty + i]);
}

// ---------------------------------------------------------------------------
// HMMA fp16 GEMM, single fp16 A and B. CTA 128x128, 4 warps of 64x64,
// 128 threads, 2 CTAs/SM, BK=64, 3-stage cp.async pipeline (1 barrier/chunk).
// MODE 0: emit Qhi/Qlo(0.18034x = 0.125*log2e), K, V (fp16) into [bh][t][d].
// MODE 1: row-major fp32 out [MR,Cc].
// ---------------------------------------------------------------------------
#define BK 64
#define PAD 72
#define MATB (128*PAD*2)             // 18432 per matrix (A | B)
#define BUFB (2*MATB)                // 36864
#define GSMEM (3*BUFB)               // 110592

#define QSCALE 0.1803368801111f      // 0.125 * log2(e)

__device__ __forceinline__ void issue_chunk(
    uint32_t sbase,
    const __half* __restrict__ Am, const __half* __restrict__ Bm,
    int m0, int n0, int kc, int tid)
{
#pragma unroll
    for (int it = 0; it < 8; it++) {
        int idx = it * 128 + tid;            // 0..1023
        int row = idx >> 3, seg = idx & 7;
        uint32_t soff = (uint32_t)(row * PAD + seg * 8) * 2;
        size_t ga = (size_t)(m0 + row) * Cc + kc + seg * 8;
        size_t gb = (size_t)(n0 + row) * Cc + kc + seg * 8;
        cp_async16(sbase + soff,        Am + ga);
        cp_async16(sbase + MATB + soff, Bm + gb);
    }
    cp_commit();
}

template <int MODE>
__global__ __launch_bounds__(128, 2)
void tc_gemm(const __half* __restrict__ Am, const __half* __restrict__ Bm,
             const float* __restrict__ bias, float* __restrict__ out) {
    extern __shared__ char smx[];
    uint32_t sb = smem_u32(smx);
    int tid = threadIdx.x;
    int lane = tid & 31, warp = tid >> 5;
    int wm = warp >> 1;
    int wn = warp & 1;
    int m0 = blockIdx.y * 128, n0 = blockIdx.x * 128;

    float acc[4][8][4] = {};

    const int NCH = Cc / BK;   // 16
    issue_chunk(sb,        Am, Bm, m0, n0, 0,  tid);
    issue_chunk(sb + BUFB, Am, Bm, m0, n0, BK, tid);

    int arow = wm * 64 + (lane & 15);
    int acol_base = (lane >> 4) * 8;
    int brow = wn * 64 + (lane >> 4) * 8 + (lane & 7);
    int bcol_base = ((lane >> 3) & 1) * 8;

    int bufi = 0;           // i % 3
    int nbuf = 2;           // (i+2) % 3
    for (int i = 0; i < NCH; i++) {
        if (i + 1 < NCH) {
            asm volatile("cp.async.wait_group 1;" ::: "memory");
        } else {
            asm volatile("cp.async.wait_group 0;" ::: "memory");
        }
        __syncthreads();
        if (i + 2 < NCH)
            issue_chunk(sb + nbuf * BUFB, Am, Bm, m0, n0, (i + 2) * BK, tid);
        uint32_t buf = sb + bufi * BUFB;
        bufi = (bufi + 1 == 3) ? 0 : bufi + 1;
        nbuf = (nbuf + 1 == 3) ? 0 : nbuf + 1;

#pragma unroll
        for (int ks = 0; ks < 4; ks++) {
            int acol = ks * 16 + acol_base;
            int bcol = ks * 16 + bcol_base;
            uint32_t ah[4][4], bf4[4][4];
#pragma unroll
            for (int mt = 0; mt < 4; mt++)
                LDSM_X4(ah[mt], buf + (uint32_t)((arow + mt * 16) * PAD + acol) * 2);
#pragma unroll
            for (int np = 0; np < 4; np++)
                LDSM_X4(bf4[np], buf + MATB + (uint32_t)((brow + np * 16) * PAD + bcol) * 2);
#pragma unroll
            for (int np = 0; np < 4; np++)
#pragma unroll
                for (int mt = 0; mt < 4; mt++)
#pragma unroll
                    for (int half = 0; half < 2; half++)
                        MMA16816(acc[mt][np * 2 + half], ah[mt],
                                 bf4[np][half * 2], bf4[np][half * 2 + 1]);
        }
    }

    int mrow = m0 + wm * 64 + (lane >> 2);
#pragma unroll
    for (int mt = 0; mt < 4; mt++) {
#pragma unroll
        for (int nt = 0; nt < 8; nt++) {
            int n = n0 + wn * 64 + nt * 8 + (lane & 3) * 2;
            float bx = bias[n], by = bias[n + 1];
            float2 v0 = make_float2(acc[mt][nt][0] + bx, acc[mt][nt][1] + by);
            float2 v1 = make_float2(acc[mt][nt][2] + bx, acc[mt][nt][3] + by);
            int m_a = mrow + mt * 16;
            int m_b = m_a + 8;
            if (MODE == 0) {
                int sec = n >> 10;
                int c2 = n & (Cc - 1);
                int h = c2 >> 6, d = c2 & 63;
                int ba = m_a >> 11, ta = m_a & (Tt - 1);
                int bb2 = m_b >> 11, tb = m_b & (Tt - 1);
                size_t o0 = (((size_t)(ba * Hh + h)) * Tt + ta) * HD + d;
                size_t o1 = (((size_t)(bb2 * Hh + h)) * Tt + tb) * HD + d;
                if (sec == 0) {
                    v0.x *= QSCALE; v0.y *= QSCALE; v1.x *= QSCALE; v1.y *= QSCALE;
                    __half2 hi = __floats2half2_rn(v0.x, v0.y);
                    __half2 lo = __floats2half2_rn(v0.x - __half2float(hi.x),
                                                   v0.y - __half2float(hi.y));
                    *(__half2*)&g_Qhi[o0] = hi;
                    *(__half2*)&g_Qlo[o0] = lo;
                    hi = __floats2half2_rn(v1.x, v1.y);
                    lo = __floats2half2_rn(v1.x - __half2float(hi.x),
                                           v1.y - __half2float(hi.y));
                    *(__half2*)&g_Qhi[o1] = hi;
                    *(__half2*)&g_Qlo[o1] = lo;
                } else {
                    __half* dst = (sec == 1) ? g_K : g_V;
                    *(__half2*)&dst[o0] = __floats2half2_rn(v0.x, v0.y);
                    *(__half2*)&dst[o1] = __floats2half2_rn(v1.x, v1.y);
                }
            } else {
                *(float2*)&out[(size_t)m_a * Cc + n] = v0;
                *(float2*)&out[(size_t)m_b * Cc + n] = v1;
            }
        }
    }
}

// ---------------------------------------------------------------------------
// Tensor-core flash attention, fp16: Q split hi/lo + K single (2-term S),
// P single fp16 + V single (trans-ldmatrix). exp2-domain softmax.
// Bq=128, Bk=64, 128 threads. Q fragments hoisted to registers; 3-buffer KV
// pipeline with one barrier per tile.
// ---------------------------------------------------------------------------
#define BQ 128
#define APAD 72
#define QMAT (BQ*APAD)
#define KMAT (64*APAD)
#define ASMEM ((2*QMAT + 6*KMAT)*2)  // 92160 B

__device__ __forceinline__ void issue_kv(uint32_t sK, uint32_t sV,
                                         const __half* gK, const __half* gV,
                                         int kv0, int tid) {
#pragma unroll
    for (int it = 0; it < 4; it++) {
        int idx = it * 128 + tid;
        int row = idx >> 3, seg = idx & 7;
        uint32_t so = (uint32_t)(row * APAD + seg * 8) * 2;
        size_t g = (size_t)(kv0 + row) * HD + seg * 8;
        cp_async16(sK + so, gK + g);
        cp_async16(sV + so, gV + g);
    }
    cp_commit();
}

__global__ __launch_bounds__(128, 2) void attn_tc() {
    extern __shared__ __half sa[];
    uint32_t sQh = smem_u32(sa);
    uint32_t sQl = sQh + QMAT * 2;
    uint32_t sKV0 = sQl + QMAT * 2;            // K0|V0 | K1|V1 | K2|V2
    uint32_t sKb[3], sVb[3];
#pragma unroll
    for (int i = 0; i < 3; i++) {
        sKb[i] = sKV0 + (2 * i) * KMAT * 2;
        sVb[i] = sKV0 + (2 * i + 1) * KMAT * 2;
    }

    int tid = threadIdx.x;
    int lane = tid & 31, w = tid >> 5;
    int bh = blockIdx.y;
    int qtile = (gridDim.x - 1) - blockIdx.x;    // heavy tiles first
    int q0 = qtile * BQ;

    const __half* gQh = g_Qhi + (size_t)bh * Tt * HD;
    const __half* gQl = g_Qlo + (size_t)bh * Tt * HD;
    const __half* gK  = g_K  + (size_t)bh * Tt * HD;
    const __half* gV  = g_V  + (size_t)bh * Tt * HD;

    // G0: Q tile (128 x 64), hi+lo
#pragma unroll
    for (int it = 0; it < 8; it++) {
        int idx = it * 128 + tid;
        int row = idx >> 3, seg = idx & 7;
        uint32_t so = (uint32_t)(row * APAD + seg * 8) * 2;
        size_t go = (size_t)(q0 + row) * HD + seg * 8;
        cp_async16(sQh + so, gQh + go);
        cp_async16(sQl + so, gQl + go);
    }
    cp_commit();
    int ktmax = 2 * qtile + 1;                   // >= 1 always
    issue_kv(sKb[0], sVb[0], gK, gV, 0, tid);    // G1
    issue_kv(sKb[1], sVb[1], gK, gV, 64, tid);   // G2

    float o[2][8][4] = {};
    float mrow[2][2] = {{-1e30f, -1e30f}, {-1e30f, -1e30f}};
    float lrow[2][2] = {};
    uint32_t aqh[4][2][4], aql[4][2][4];         // hoisted Q fragments

    int r0 = lane >> 2;

    int bufi = 0;   // kt % 3
    int nbuf = 2;   // (kt+2) % 3
    for (int kt = 0; kt <= ktmax; kt++) {
        int kv0 = kt * 64;
        if (kt + 1 <= ktmax) {
            asm volatile("cp.async.wait_group 1;" ::: "memory");
        } else {
            asm volatile("cp.async.wait_group 0;" ::: "memory");
        }
        __syncthreads();
        if (kt == 0) {
            // Q resident: load all fragments once
#pragma unroll
            for (int ks = 0; ks < 4; ks++)
#pragma unroll
                for (int mt = 0; mt < 2; mt++) {
                    uint32_t off = (uint32_t)((w * 32 + mt * 16 + (lane & 15)) * APAD +
                                              ks * 16 + (lane >> 4) * 8) * 2;
                    LDSM_X4(aqh[ks][mt], sQh + off);
                    LDSM_X4(aql[ks][mt], sQl + off);
                }
        }
        if (kt + 2 <= ktmax)
            issue_kv(sKb[nbuf], sVb[nbuf], gK, gV, (kt + 2) * 64, tid);
        uint32_t sKc = sKb[bufi], sVc = sVb[bufi];
        bufi = (bufi + 1 == 3) ? 0 : bufi + 1;
        nbuf = (nbuf + 1 == 3) ? 0 : nbuf + 1;

        // ---- S = Q K^T  (Qh·K then Ql·K); result in log2 domain ----
        float s[2][8][4] = {};
#pragma unroll
        for (int ks = 0; ks < 4; ks++) {
            uint32_t bk[4][4];
#pragma unroll
            for (int ntp = 0; ntp < 4; ntp++)
                LDSM_X4(bk[ntp], sKc + (uint32_t)((ntp * 16 + (lane >> 4) * 8 + (lane & 7)) * APAD +
                                                  ks * 16 + ((lane >> 3) & 1) * 8) * 2);
#pragma unroll
            for (int ntp = 0; ntp < 4; ntp++)
#pragma unroll
                for (int mt = 0; mt < 2; mt++)
#pragma unroll
                    for (int h2 = 0; h2 < 2; h2++)
                        MMA16816(s[mt][ntp * 2 + h2], aqh[ks][mt],
                                 bk[ntp][h2 * 2], bk[ntp][h2 * 2 + 1]);
#pragma unroll
            for (int ntp = 0; ntp < 4; ntp++)
#pragma unroll
                for (int mt = 0; mt < 2; mt++)
#pragma unroll
                    for (int h2 = 0; h2 < 2; h2++)
                        MMA16816(s[mt][ntp * 2 + h2], aql[ks][mt],
                                 bk[ntp][h2 * 2], bk[ntp][h2 * 2 + 1]);
        }

        // causal mask
        if (kv0 + 63 > q0 + w * 32) {
#pragma unroll
            for (int mt = 0; mt < 2; mt++)
#pragma unroll
                for (int nt = 0; nt < 8; nt++)
#pragma unroll
                    for (int j = 0; j < 4; j++) {
                        int c = kv0 + nt * 8 + (lane & 3) * 2 + (j & 1);
                        int r = q0 + w * 32 + mt * 16 + r0 + ((j >> 1) ? 8 : 0);
                        if (c > r) s[mt][nt][j] = -1e30f;
                    }
        }

        // ---- online softmax (exp2 domain) ----
#pragma unroll
        for (int mt = 0; mt < 2; mt++)
#pragma unroll
            for (int rr = 0; rr < 2; rr++) {
                float rm = -1e30f;
#pragma unroll
                for (int nt = 0; nt < 8; nt++)
                    rm = fmaxf(rm, fmaxf(s[mt][nt][rr * 2], s[mt][nt][rr * 2 + 1]));
                rm = fmaxf(rm, __shfl_xor_sync(0xffffffffu, rm, 1));
                rm = fmaxf(rm, __shfl_xor_sync(0xffffffffu, rm, 2));
                float mnew = fmaxf(mrow[mt][rr], rm);
                float alpha = ex2f(mrow[mt][rr] - mnew);
                mrow[mt][rr] = mnew;
                float rs = 0.0f;
#pragma unroll
                for (int nt = 0; nt < 8; nt++) {
                    s[mt][nt][rr * 2]     = ex2f(s[mt][nt][rr * 2] - mnew);
                    s[mt][nt][rr * 2 + 1] = ex2f(s[mt][nt][rr * 2 + 1] - mnew);
                    rs += s[mt][nt][rr * 2] + s[mt][nt][rr * 2 + 1];
                }
                rs += __shfl_xor_sync(0xffffffffu, rs, 1);
                rs += __shfl_xor_sync(0xffffffffu, rs, 2);
                lrow[mt][rr] = lrow[mt][rr] * alpha + rs;
#pragma unroll
                for (int dt = 0; dt < 8; dt++) {
                    o[mt][dt][rr * 2]     *= alpha;
                    o[mt][dt][rr * 2 + 1] *= alpha;
                }
            }

        // ---- O += P V  (P single fp16; V via trans-ldmatrix on [kv][d]) ----
#pragma unroll
        for (int ksv = 0; ksv < 4; ksv++) {
            uint32_t pah[2][4];
#pragma unroll
            for (int mt = 0; mt < 2; mt++)
#pragma unroll
                for (int q = 0; q < 4; q++) {
                    int nt = 2 * ksv + (q >> 1);
                    int j0 = (q & 1) * 2;
                    __half2 hv = __floats2half2_rn(s[mt][nt][j0], s[mt][nt][j0 + 1]);
                    pah[mt][q] = *(uint32_t*)&hv;
                }
            uint32_t bv[4][4];
#pragma unroll
            for (int dtp = 0; dtp < 4; dtp++) {
                uint32_t addr = sVc + (uint32_t)(
                    (ksv * 16 + ((lane >> 3) & 1) * 8 + (lane & 7)) * APAD +
                    dtp * 16 + (lane >> 4) * 8) * 2;
                LDSM_X4_T(bv[dtp], addr);
            }
#pragma unroll
            for (int dtp = 0; dtp < 4; dtp++)
#pragma unroll
                for (int mt = 0; mt < 2; mt++)
#pragma unroll
                    for (int h2 = 0; h2 < 2; h2++)
                        MMA16816(o[mt][dtp * 2 + h2], pah[mt],
                                 bv[dtp][h2 * 2], bv[dtp][h2 * 2 + 1]);
        }
    }

    // ---- epilogue: normalize, emit Y single fp16 [B,T,C] ----
    int bb = bh >> 4, h = bh & 15;
#pragma unroll
    for (int mt = 0; mt < 2; mt++) {
        float inv0 = 1.0f / lrow[mt][0];
        float inv1 = 1.0f / lrow[mt][1];
        int gq0 = q0 + w * 32 + mt * 16 + r0;
        int gq1 = gq0 + 8;
#pragma unroll
        for (int dt = 0; dt < 8; dt++) {
            int col = h * HD + dt * 8 + (lane & 3) * 2;
            size_t o0 = (size_t)(bb * Tt + gq0) * Cc + col;
            size_t o1 = (size_t)(bb * Tt + gq1) * Cc + col;
            *(__half2*)&g_Y[o0] = __floats2half2_rn(o[mt][dt][0] * inv0, o[mt][dt][1] * inv0);
            *(__half2*)&g_Y[o1] = __floats2half2_rn(o[mt][dt][2] * inv1, o[mt][dt][3] * inv1);
        }
    }
}

// ---------------------------------------------------------------------------
extern "C" void kernel_launch(void* const* d_in, const int* in_sizes, int n_in,
                              void* d_out, int out_size) {
    const float* x      = (const float*)d_in[0];
    const float* W_attn = (const float*)d_in[1];
    const float* b_attn = (const float*)d_in[2];
    const float* W_proj = (const float*)d_in[3];
    const float* b_proj = (const float*)d_in[4];
    float* out = (float*)d_out;

    __half *xp, *wa, *wp, *yp;
    cudaGetSymbolAddress((void**)&xp, g_X);
    cudaGetSymbolAddress((void**)&wa, g_WA);
    cudaGetSymbolAddress((void**)&wp, g_WP);
    cudaGetSymbolAddress((void**)&yp, g_Y);

    cudaFuncSetAttribute(tc_gemm<0>, cudaFuncAttributeMaxDynamicSharedMemorySize, GSMEM);
    cudaFuncSetAttribute(tc_gemm<1>, cudaFuncAttributeMaxDynamicSharedMemorySize, GSMEM);
    cudaFuncSetAttribute(attn_tc, cudaFuncAttributeMaxDynamicSharedMemorySize, ASMEM);

    convert_x_kernel<<<1024, 256>>>((const float4*)x, MR * Cc / 4);
    transconv_kernel<<<dim3(3 * Cc / 32, Cc / 32), dim3(32, 8)>>>(W_attn, wa, Cc, 3 * Cc);
    transconv_kernel<<<dim3(Cc / 32, Cc / 32), dim3(32, 8)>>>(W_proj, wp, Cc, Cc);

    tc_gemm<0><<<dim3(3 * Cc / 128, MR / 128), 128, GSMEM>>>(xp, wa, b_attn, nullptr);

    attn_tc<<<dim3(Tt / BQ, Bb * Hh), 128, ASMEM>>>();

    tc_gemm<1><<<dim3(Cc / 128, MR / 128), 128, GSMEM>>>(yp, wp, b_proj, out);
}

// round 16
// speedup vs baseline: 2.5878x; 1.1021x over previous
#include <cuda_runtime.h>
#include <cuda_fp16.h>
#include <cstdint>

#define Bb 4
#define Tt 2048
#define Cc 1024
#define Hh 16
#define HD 64
#define MR (Bb*Tt)      // 8192 rows

// ---------------------------------------------------------------------------
// device scratch (allocation-free rule)
// ---------------------------------------------------------------------------
__device__ __half g_Q  [Bb*Hh*Tt*HD];    // pre-scaled by 0.125*log2e
__device__ __half g_K  [Bb*Hh*Tt*HD];
__device__ __half g_V  [Bb*Hh*Tt*HD];
__device__ __half g_X  [MR*Cc];
__device__ __half g_WA [3*Cc*Cc];        // [N,K] single fp16
__device__ __half g_WP [Cc*Cc];
__device__ __half g_Y  [MR*Cc];

// ---------------------------------------------------------------------------
// helpers (base sm_10x-legal PTX only: cp.async / ldmatrix / mma.sync)
// ---------------------------------------------------------------------------
__device__ __forceinline__ uint32_t smem_u32(const void* p) {
    uint32_t a;
    asm("{ .reg .u64 t; cvta.to.shared.u64 t, %1; cvt.u32.u64 %0, t; }" : "=r"(a) : "l"(p));
    return a;
}

__device__ __forceinline__ void cp_async16(uint32_t s, const void* g) {
    asm volatile("cp.async.cg.shared.global [%0], [%1], 16;" :: "r"(s), "l"(g));
}
__device__ __forceinline__ void cp_commit() {
    asm volatile("cp.async.commit_group;" ::: "memory");
}

__device__ __forceinline__ float ex2f(float x) {
    float r;
    asm("ex2.approx.ftz.f32 %0, %1;" : "=f"(r) : "f"(x));
    return r;
}

#define LDSM_X4(r, addr) \
    asm volatile("ldmatrix.sync.aligned.m8n8.x4.shared.b16 {%0,%1,%2,%3}, [%4];" \
        : "=r"((r)[0]), "=r"((r)[1]), "=r"((r)[2]), "=r"((r)[3]) : "r"(addr))

#define LDSM_X4_T(r, addr) \
    asm volatile("ldmatrix.sync.aligned.m8n8.x4.trans.shared.b16 {%0,%1,%2,%3}, [%4];" \
        : "=r"((r)[0]), "=r"((r)[1]), "=r"((r)[2]), "=r"((r)[3]) : "r"(addr))

#define MMA16816(c, a, b0v, b1v) \
    asm volatile("mma.sync.aligned.m16n8k16.row.col.f32.f16.f16.f32 " \
        "{%0,%1,%2,%3}, {%4,%5,%6,%7}, {%8,%9}, {%0,%1,%2,%3};" \
        : "+f"((c)[0]), "+f"((c)[1]), "+f"((c)[2]), "+f"((c)[3]) \
        : "r"((a)[0]), "r"((a)[1]), "r"((a)[2]), "r"((a)[3]), "r"(b0v), "r"(b1v))

// ---------------------------------------------------------------------------
// prep kernels
// ---------------------------------------------------------------------------
__global__ void convert_x_kernel(const float4* __restrict__ x, int n4) {
    __half2* d2 = (__half2*)g_X;
    for (int i = blockIdx.x * blockDim.x + threadIdx.x; i < n4; i += gridDim.x * blockDim.x) {
        float4 v = x[i];
        d2[i * 2]     = __floats2half2_rn(v.x, v.y);
        d2[i * 2 + 1] = __floats2half2_rn(v.z, v.w);
    }
}

// src [K,N] fp32 -> dst [N,K] single fp16
__global__ void transconv_kernel(const float* __restrict__ src, __half* __restrict__ dst,
                                 int K, int N) {
    __shared__ float sm[32][33];
    int n0 = blockIdx.x * 32, k0 = blockIdx.y * 32;
    int tx = threadIdx.x, ty = threadIdx.y;   // 32 x 8
#pragma unroll
    for (int i = 0; i < 32; i += 8)
        sm[ty + i][tx] = src[(size_t)(k0 + ty + i) * N + n0 + tx];
    __syncthreads();
#pragma unroll
    for (int i = 0; i < 32; i += 8)
        dst[(size_t)(n0 + ty + i) * K + k0 + tx] = __float2half(sm[tx][ty + i]);
}

// ---------------------------------------------------------------------------
// HMMA fp16 GEMM, single fp16 A and B. CTA 128x128, 4 warps of 64x64,
// 128 threads, 2 CTAs/SM, BK=64, 3-stage cp.async pipeline.
// MODE 0: emit Q(0.18034x = 0.125*log2e), K, V (single fp16) into [bh][t][d].
// MODE 1: row-major fp32 out [MR,Cc].
// ---------------------------------------------------------------------------
#define BK 64
#define PAD 72
#define MATB (128*PAD*2)             // 18432 per matrix (A | B)
#define BUFB (2*MATB)                // 36864
#define GSMEM (3*BUFB)               // 110592

#define QSCALE 0.1803368801111f      // 0.125 * log2(e)

__device__ __forceinline__ void issue_chunk(
    uint32_t sbase,
    const __half* __restrict__ Am, const __half* __restrict__ Bm,
    int m0, int n0, int kc, int tid)
{
#pragma unroll
    for (int it = 0; it < 8; it++) {
        int idx = it * 128 + tid;            // 0..1023
        int row = idx >> 3, seg = idx & 7;
        uint32_t soff = (uint32_t)(row * PAD + seg * 8) * 2;
        size_t ga = (size_t)(m0 + row) * Cc + kc + seg * 8;
        size_t gb = (size_t)(n0 + row) * Cc + kc + seg * 8;
        cp_async16(sbase + soff,        Am + ga);
        cp_async16(sbase + MATB + soff, Bm + gb);
    }
    cp_commit();
}

template <int MODE>
__global__ __launch_bounds__(128, 2)
void tc_gemm(const __half* __restrict__ Am, const __half* __restrict__ Bm,
             const float* __restrict__ bias, float* __restrict__ out) {
    extern __shared__ char smx[];
    uint32_t sb = smem_u32(smx);
    int tid = threadIdx.x;
    int lane = tid & 31, warp = tid >> 5;
    int wm = warp >> 1;
    int wn = warp & 1;
    int m0 = blockIdx.y * 128, n0 = blockIdx.x * 128;

    float acc[4][8][4] = {};

    const int NCH = Cc / BK;   // 16
    issue_chunk(sb,        Am, Bm, m0, n0, 0,  tid);
    issue_chunk(sb + BUFB, Am, Bm, m0, n0, BK, tid);

    int arow = wm * 64 + (lane & 15);
    int acol_base = (lane >> 4) * 8;
    int brow = wn * 64 + (lane >> 4) * 8 + (lane & 7);
    int bcol_base = ((lane >> 3) & 1) * 8;

    int bufi = 0;
    int nbuf = 2;
    for (int i = 0; i < NCH; i++) {
        if (i + 1 < NCH) {
            asm volatile("cp.async.wait_group 1;" ::: "memory");
        } else {
            asm volatile("cp.async.wait_group 0;" ::: "memory");
        }
        __syncthreads();
        if (i + 2 < NCH)
            issue_chunk(sb + nbuf * BUFB, Am, Bm, m0, n0, (i + 2) * BK, tid);
        uint32_t buf = sb + bufi * BUFB;
        bufi = (bufi + 1 == 3) ? 0 : bufi + 1;
        nbuf = (nbuf + 1 == 3) ? 0 : nbuf + 1;

#pragma unroll
        for (int ks = 0; ks < 4; ks++) {
            int acol = ks * 16 + acol_base;
            int bcol = ks * 16 + bcol_base;
            uint32_t ah[4][4], bf4[4][4];
#pragma unroll
            for (int mt = 0; mt < 4; mt++)
                LDSM_X4(ah[mt], buf + (uint32_t)((arow + mt * 16) * PAD + acol) * 2);
#pragma unroll
            for (int np = 0; np < 4; np++)
                LDSM_X4(bf4[np], buf + MATB + (uint32_t)((brow + np * 16) * PAD + bcol) * 2);
#pragma unroll
            for (int np = 0; np < 4; np++)
#pragma unroll
                for (int mt = 0; mt < 4; mt++)
#pragma unroll
                    for (int half = 0; half < 2; half++)
                        MMA16816(acc[mt][np * 2 + half], ah[mt],
                                 bf4[np][half * 2], bf4[np][half * 2 + 1]);
        }
    }

    int mrow = m0 + wm * 64 + (lane >> 2);
#pragma unroll
    for (int mt = 0; mt < 4; mt++) {
#pragma unroll
        for (int nt = 0; nt < 8; nt++) {
            int n = n0 + wn * 64 + nt * 8 + (lane & 3) * 2;
            float bx = bias[n], by = bias[n + 1];
            float2 v0 = make_float2(acc[mt][nt][0] + bx, acc[mt][nt][1] + by);
            float2 v1 = make_float2(acc[mt][nt][2] + bx, acc[mt][nt][3] + by);
            int m_a = mrow + mt * 16;
            int m_b = m_a + 8;
            if (MODE == 0) {
                int sec = n >> 10;
                int c2 = n & (Cc - 1);
                int h = c2 >> 6, d = c2 & 63;
                int ba = m_a >> 11, ta = m_a & (Tt - 1);
                int bb2 = m_b >> 11, tb = m_b & (Tt - 1);
                size_t o0 = (((size_t)(ba * Hh + h)) * Tt + ta) * HD + d;
                size_t o1 = (((size_t)(bb2 * Hh + h)) * Tt + tb) * HD + d;
                __half* dst;
                if (sec == 0) {
                    dst = g_Q;
                    v0.x *= QSCALE; v0.y *= QSCALE; v1.x *= QSCALE; v1.y *= QSCALE;
                } else {
                    dst = (sec == 1) ? g_K : g_V;
                }
                *(__half2*)&dst[o0] = __floats2half2_rn(v0.x, v0.y);
                *(__half2*)&dst[o1] = __floats2half2_rn(v1.x, v1.y);
            } else {
                *(float2*)&out[(size_t)m_a * Cc + n] = v0;
                *(float2*)&out[(size_t)m_b * Cc + n] = v1;
            }
        }
    }
}

// ---------------------------------------------------------------------------
// Tensor-core flash attention, all-single fp16 operands (1-term S, 1-term PV).
// exp2-domain softmax (Q pre-scaled by 0.125*log2e). Bq=128, Bk=64, 128 thr.
// Q fragments hoisted to registers; 3-buffer KV pipeline, 1 barrier/tile.
// ---------------------------------------------------------------------------
#define BQ 128
#define APAD 72
#define QMAT (BQ*APAD)
#define KMAT (64*APAD)
#define ASMEM ((QMAT + 6*KMAT)*2)    // 73728 B

__device__ __forceinline__ void issue_kv(uint32_t sK, uint32_t sV,
                                         const __half* gK, const __half* gV,
                                         int kv0, int tid) {
#pragma unroll
    for (int it = 0; it < 4; it++) {
        int idx = it * 128 + tid;
        int row = idx >> 3, seg = idx & 7;
        uint32_t so = (uint32_t)(row * APAD + seg * 8) * 2;
        size_t g = (size_t)(kv0 + row) * HD + seg * 8;
        cp_async16(sK + so, gK + g);
        cp_async16(sV + so, gV + g);
    }
    cp_commit();
}

__global__ __launch_bounds__(128, 2) void attn_tc() {
    extern __shared__ __half sa[];
    uint32_t sQ = smem_u32(sa);
    uint32_t sKV0 = sQ + QMAT * 2;             // K0|V0 | K1|V1 | K2|V2
    uint32_t sKb[3], sVb[3];
#pragma unroll
    for (int i = 0; i < 3; i++) {
        sKb[i] = sKV0 + (2 * i) * KMAT * 2;
        sVb[i] = sKV0 + (2 * i + 1) * KMAT * 2;
    }

    int tid = threadIdx.x;
    int lane = tid & 31, w = tid >> 5;
    int bh = blockIdx.y;
    int qtile = (gridDim.x - 1) - blockIdx.x;    // heavy tiles first
    int q0 = qtile * BQ;

    const __half* gQ = g_Q + (size_t)bh * Tt * HD;
    const __half* gK = g_K + (size_t)bh * Tt * HD;
    const __half* gV = g_V + (size_t)bh * Tt * HD;

    // G0: Q tile (128 x 64)
#pragma unroll
    for (int it = 0; it < 8; it++) {
        int idx = it * 128 + tid;
        int row = idx >> 3, seg = idx & 7;
        uint32_t so = (uint32_t)(row * APAD + seg * 8) * 2;
        cp_async16(sQ + so, gQ + (size_t)(q0 + row) * HD + seg * 8);
    }
    cp_commit();
    int ktmax = 2 * qtile + 1;
    issue_kv(sKb[0], sVb[0], gK, gV, 0, tid);
    issue_kv(sKb[1], sVb[1], gK, gV, 64, tid);

    float o[2][8][4] = {};
    float mrow[2][2] = {{-1e30f, -1e30f}, {-1e30f, -1e30f}};
    float lrow[2][2] = {};
    uint32_t aq[4][2][4];                        // hoisted Q fragments

    int r0 = lane >> 2;

    int bufi = 0;
    int nbuf = 2;
    for (int kt = 0; kt <= ktmax; kt++) {
        int kv0 = kt * 64;
        if (kt + 1 <= ktmax) {
            asm volatile("cp.async.wait_group 1;" ::: "memory");
        } else {
            asm volatile("cp.async.wait_group 0;" ::: "memory");
        }
        __syncthreads();
        if (kt == 0) {
#pragma unroll
            for (int ks = 0; ks < 4; ks++)
#pragma unroll
                for (int mt = 0; mt < 2; mt++) {
                    uint32_t off = (uint32_t)((w * 32 + mt * 16 + (lane & 15)) * APAD +
                                              ks * 16 + (lane >> 4) * 8) * 2;
                    LDSM_X4(aq[ks][mt], sQ + off);
                }
        }
        if (kt + 2 <= ktmax)
            issue_kv(sKb[nbuf], sVb[nbuf], gK, gV, (kt + 2) * 64, tid);
        uint32_t sKc = sKb[bufi], sVc = sVb[bufi];
        bufi = (bufi + 1 == 3) ? 0 : bufi + 1;
        nbuf = (nbuf + 1 == 3) ? 0 : nbuf + 1;

        // ---- S = Q K^T  (single term); result in log2 domain ----
        float s[2][8][4] = {};
#pragma unroll
        for (int ks = 0; ks < 4; ks++) {
            uint32_t bk[4][4];
#pragma unroll
            for (int ntp = 0; ntp < 4; ntp++)
                LDSM_X4(bk[ntp], sKc + (uint32_t)((ntp * 16 + (lane >> 4) * 8 + (lane & 7)) * APAD +
                                                  ks * 16 + ((lane >> 3) & 1) * 8) * 2);
#pragma unroll
            for (int ntp = 0; ntp < 4; ntp++)
#pragma unroll
                for (int mt = 0; mt < 2; mt++)
#pragma unroll
                    for (int h2 = 0; h2 < 2; h2++)
                        MMA16816(s[mt][ntp * 2 + h2], aq[ks][mt],
                                 bk[ntp][h2 * 2], bk[ntp][h2 * 2 + 1]);
        }

        // causal mask
        if (kv0 + 63 > q0 + w * 32) {
#pragma unroll
            for (int mt = 0; mt < 2; mt++)
#pragma unroll
                for (int nt = 0; nt < 8; nt++)
#pragma unroll
                    for (int j = 0; j < 4; j++) {
                        int c = kv0 + nt * 8 + (lane & 3) * 2 + (j & 1);
                        int r = q0 + w * 32 + mt * 16 + r0 + ((j >> 1) ? 8 : 0);
                        if (c > r) s[mt][nt][j] = -1e30f;
                    }
        }

        // ---- online softmax (exp2 domain) ----
#pragma unroll
        for (int mt = 0; mt < 2; mt++)
#pragma unroll
            for (int rr = 0; rr < 2; rr++) {
                float rm = -1e30f;
#pragma unroll
                for (int nt = 0; nt < 8; nt++)
                    rm = fmaxf(rm, fmaxf(s[mt][nt][rr * 2], s[mt][nt][rr * 2 + 1]));
                rm = fmaxf(rm, __shfl_xor_sync(0xffffffffu, rm, 1));
                rm = fmaxf(rm, __shfl_xor_sync(0xffffffffu, rm, 2));
                float mnew = fmaxf(mrow[mt][rr], rm);
                float alpha = ex2f(mrow[mt][rr] - mnew);
                mrow[mt][rr] = mnew;
                float rs = 0.0f;
#pragma unroll
                for (int nt = 0; nt < 8; nt++) {
                    s[mt][nt][rr * 2]     = ex2f(s[mt][nt][rr * 2] - mnew);
                    s[mt][nt][rr * 2 + 1] = ex2f(s[mt][nt][rr * 2 + 1] - mnew);
                    rs += s[mt][nt][rr * 2] + s[mt][nt][rr * 2 + 1];
                }
                rs += __shfl_xor_sync(0xffffffffu, rs, 1);
                rs += __shfl_xor_sync(0xffffffffu, rs, 2);
                lrow[mt][rr] = lrow[mt][rr] * alpha + rs;
#pragma unroll
                for (int dt = 0; dt < 8; dt++) {
                    o[mt][dt][rr * 2]     *= alpha;
                    o[mt][dt][rr * 2 + 1] *= alpha;
                }
            }

        // ---- O += P V  (P single fp16; V via trans-ldmatrix on [kv][d]) ----
#pragma unroll
        for (int ksv = 0; ksv < 4; ksv++) {
            uint32_t pah[2][4];
#pragma unroll
            for (int mt = 0; mt < 2; mt++)
#pragma unroll
                for (int q = 0; q < 4; q++) {
                    int nt = 2 * ksv + (q >> 1);
                    int j0 = (q & 1) * 2;
                    __half2 hv = __floats2half2_rn(s[mt][nt][j0], s[mt][nt][j0 + 1]);
                    pah[mt][q] = *(uint32_t*)&hv;
                }
            uint32_t bv[4][4];
#pragma unroll
            for (int dtp = 0; dtp < 4; dtp++) {
                uint32_t addr = sVc + (uint32_t)(
                    (ksv * 16 + ((lane >> 3) & 1) * 8 + (lane & 7)) * APAD +
                    dtp * 16 + (lane >> 4) * 8) * 2;
                LDSM_X4_T(bv[dtp], addr);
            }
#pragma unroll
            for (int dtp = 0; dtp < 4; dtp++)
#pragma unroll
                for (int mt = 0; mt < 2; mt++)
#pragma unroll
                    for (int h2 = 0; h2 < 2; h2++)
                        MMA16816(o[mt][dtp * 2 + h2], pah[mt],
                                 bv[dtp][h2 * 2], bv[dtp][h2 * 2 + 1]);
        }
    }

    // ---- epilogue: normalize, emit Y single fp16 [B,T,C] ----
    int bb = bh >> 4, h = bh & 15;
#pragma unroll
    for (int mt = 0; mt < 2; mt++) {
        float inv0 = 1.0f / lrow[mt][0];
        float inv1 = 1.0f / lrow[mt][1];
        int gq0 = q0 + w * 32 + mt * 16 + r0;
        int gq1 = gq0 + 8;
#pragma unroll
        for (int dt = 0; dt < 8; dt++) {
            int col = h * HD + dt * 8 + (lane & 3) * 2;
            size_t o0 = (size_t)(bb * Tt + gq0) * Cc + col;
            size_t o1 = (size_t)(bb * Tt + gq1) * Cc + col;
            *(__half2*)&g_Y[o0] = __floats2half2_rn(o[mt][dt][0] * inv0, o[mt][dt][1] * inv0);
            *(__half2*)&g_Y[o1] = __floats2half2_rn(o[mt][dt][2] * inv1, o[mt][dt][3] * inv1);
        }
    }
}

// ---------------------------------------------------------------------------
extern "C" void kernel_launch(void* const* d_in, const int* in_sizes, int n_in,
                              void* d_out, int out_size) {
    const float* x      = (const float*)d_in[0];
    const float* W_attn = (const float*)d_in[1];
    const float* b_attn = (const float*)d_in[2];
    const float* W_proj = (const float*)d_in[3];
    const float* b_proj = (const float*)d_in[4];
    float* out = (float*)d_out;

    __half *xp, *wa, *wp, *yp;
    cudaGetSymbolAddress((void**)&xp, g_X);
    cudaGetSymbolAddress((void**)&wa, g_WA);
    cudaGetSymbolAddress((void**)&wp, g_WP);
    cudaGetSymbolAddress((void**)&yp, g_Y);

    cudaFuncSetAttribute(tc_gemm<0>, cudaFuncAttributeMaxDynamicSharedMemorySize, GSMEM);
    cudaFuncSetAttribute(tc_gemm<1>, cudaFuncAttributeMaxDynamicSharedMemorySize, GSMEM);
    cudaFuncSetAttribute(attn_tc, cudaFuncAttributeMaxDynamicSharedMemorySize, ASMEM);

    convert_x_kernel<<<1024, 256>>>((const float4*)x, MR * Cc / 4);
    transconv_kernel<<<dim3(3 * Cc / 32, Cc / 32), dim3(32, 8)>>>(W_attn, wa, Cc, 3 * Cc);
    transconv_kernel<<<dim3(Cc / 32, Cc / 32), dim3(32, 8)>>>(W_proj, wp, Cc, Cc);

    tc_gemm<0><<<dim3(3 * Cc / 128, MR / 128), 128, GSMEM>>>(xp, wa, b_attn, nullptr);

    attn_tc<<<dim3(Tt / BQ, Bb * Hh), 128, ASMEM>>>();

    tc_gemm<1><<<dim3(Cc / 128, MR / 128), 128, GSMEM>>>(yp, wp, b_proj, out);
}

// round 17
// speedup vs baseline: 2.7585x; 1.0659x over previous
#include <cuda_runtime.h>
#include <cuda_fp16.h>
#include <cstdint>

#define Bb 4
#define Tt 2048
#define Cc 1024
#define Hh 16
#define HD 64
#define MR (Bb*Tt)      // 8192 rows

// ---------------------------------------------------------------------------
// device scratch (allocation-free rule)
// ---------------------------------------------------------------------------
__device__ __half g_Q  [Bb*Hh*Tt*HD];    // pre-scaled by 0.125*log2e
__device__ __half g_K  [Bb*Hh*Tt*HD];
__device__ __half g_V  [Bb*Hh*Tt*HD];
__device__ __half g_X  [MR*Cc];
__device__ __half g_WA [3*Cc*Cc];        // [N,K] single fp16
__device__ __half g_WP [Cc*Cc];
__device__ __half g_Y  [MR*Cc];

// ---------------------------------------------------------------------------
// helpers (base sm_10x-legal PTX only: cp.async / ldmatrix / mma.sync)
// ---------------------------------------------------------------------------
__device__ __forceinline__ uint32_t smem_u32(const void* p) {
    uint32_t a;
    asm("{ .reg .u64 t; cvta.to.shared.u64 t, %1; cvt.u32.u64 %0, t; }" : "=r"(a) : "l"(p));
    return a;
}

__device__ __forceinline__ void cp_async16(uint32_t s, const void* g) {
    asm volatile("cp.async.cg.shared.global [%0], [%1], 16;" :: "r"(s), "l"(g));
}
__device__ __forceinline__ void cp_commit() {
    asm volatile("cp.async.commit_group;" ::: "memory");
}

__device__ __forceinline__ float ex2f(float x) {
    float r;
    asm("ex2.approx.ftz.f32 %0, %1;" : "=f"(r) : "f"(x));
    return r;
}

#define LDSM_X4(r, addr) \
    asm volatile("ldmatrix.sync.aligned.m8n8.x4.shared.b16 {%0,%1,%2,%3}, [%4];" \
        : "=r"((r)[0]), "=r"((r)[1]), "=r"((r)[2]), "=r"((r)[3]) : "r"(addr))

#define LDSM_X4_T(r, addr) \
    asm volatile("ldmatrix.sync.aligned.m8n8.x4.trans.shared.b16 {%0,%1,%2,%3}, [%4];" \
        : "=r"((r)[0]), "=r"((r)[1]), "=r"((r)[2]), "=r"((r)[3]) : "r"(addr))

#define MMA16816(c, a, b0v, b1v) \
    asm volatile("mma.sync.aligned.m16n8k16.row.col.f32.f16.f16.f32 " \
        "{%0,%1,%2,%3}, {%4,%5,%6,%7}, {%8,%9}, {%0,%1,%2,%3};" \
        : "+f"((c)[0]), "+f"((c)[1]), "+f"((c)[2]), "+f"((c)[3]) \
        : "r"((a)[0]), "r"((a)[1]), "r"((a)[2]), "r"((a)[3]), "r"(b0v), "r"(b1v))

// ---------------------------------------------------------------------------
// prep kernels
// ---------------------------------------------------------------------------
__global__ void convert_x_kernel(const float4* __restrict__ x, int n4) {
    __half2* d2 = (__half2*)g_X;
    for (int i = blockIdx.x * blockDim.x + threadIdx.x; i < n4; i += gridDim.x * blockDim.x) {
        float4 v = x[i];
        d2[i * 2]     = __floats2half2_rn(v.x, v.y);
        d2[i * 2 + 1] = __floats2half2_rn(v.z, v.w);
    }
}

// src [K,N] fp32 -> dst [N,K] single fp16
__global__ void transconv_kernel(const float* __restrict__ src, __half* __restrict__ dst,
                                 int K, int N) {
    __shared__ float sm[32][33];
    int n0 = blockIdx.x * 32, k0 = blockIdx.y * 32;
    int tx = threadIdx.x, ty = threadIdx.y;   // 32 x 8
#pragma unroll
    for (int i = 0; i < 32; i += 8)
        sm[ty + i][tx] = src[(size_t)(k0 + ty + i) * N + n0 + tx];
    __syncthreads();
#pragma unroll
    for (int i = 0; i < 32; i += 8)
        dst[(size_t)(n0 + ty + i) * K + k0 + tx] = __float2half(sm[tx][ty + i]);
}

// ---------------------------------------------------------------------------
// HMMA fp16 GEMM, single fp16 A and B. CTA 128x128, 4 warps of 64x64,
// 128 threads, BK=64, 2-stage cp.async pipeline, 3 CTAs/SM (12 warps/SM).
// MODE 0: emit Q(0.18034x = 0.125*log2e), K, V (single fp16) into [bh][t][d].
// MODE 1: row-major fp32 out [MR,Cc].
// ---------------------------------------------------------------------------
#define BK 64
#define PAD 72
#define MATB (128*PAD*2)             // 18432 per matrix (A | B)
#define BUFB (2*MATB)                // 36864
#define GSMEM (2*BUFB)               // 73728

#define QSCALE 0.1803368801111f      // 0.125 * log2(e)

__device__ __forceinline__ void issue_chunk(
    uint32_t sbase,
    const __half* __restrict__ Am, const __half* __restrict__ Bm,
    int m0, int n0, int kc, int tid)
{
#pragma unroll
    for (int it = 0; it < 8; it++) {
        int idx = it * 128 + tid;            // 0..1023
        int row = idx >> 3, seg = idx & 7;
        uint32_t soff = (uint32_t)(row * PAD + seg * 8) * 2;
        size_t ga = (size_t)(m0 + row) * Cc + kc + seg * 8;
        size_t gb = (size_t)(n0 + row) * Cc + kc + seg * 8;
        cp_async16(sbase + soff,        Am + ga);
        cp_async16(sbase + MATB + soff, Bm + gb);
    }
    cp_commit();
}

template <int MODE>
__global__ __launch_bounds__(128, 3)
void tc_gemm(const __half* __restrict__ Am, const __half* __restrict__ Bm,
             const float* __restrict__ bias, float* __restrict__ out) {
    extern __shared__ char smx[];
    uint32_t sb = smem_u32(smx);
    int tid = threadIdx.x;
    int lane = tid & 31, warp = tid >> 5;
    int wm = warp >> 1;
    int wn = warp & 1;
    int m0 = blockIdx.y * 128, n0 = blockIdx.x * 128;

    float acc[4][8][4] = {};

    const int NCH = Cc / BK;   // 16
    issue_chunk(sb,        Am, Bm, m0, n0, 0,  tid);
    issue_chunk(sb + BUFB, Am, Bm, m0, n0, BK, tid);

    int arow = wm * 64 + (lane & 15);
    int acol_base = (lane >> 4) * 8;
    int brow = wn * 64 + (lane >> 4) * 8 + (lane & 7);
    int bcol_base = ((lane >> 3) & 1) * 8;

    for (int i = 0; i < NCH; i++) {
        if (i + 1 < NCH) {
            asm volatile("cp.async.wait_group 1;" ::: "memory");
        } else {
            asm volatile("cp.async.wait_group 0;" ::: "memory");
        }
        __syncthreads();                       // chunk i visible to all warps
        uint32_t buf = sb + (i & 1) * BUFB;

#pragma unroll
        for (int ks = 0; ks < 4; ks++) {
            int acol = ks * 16 + acol_base;
            int bcol = ks * 16 + bcol_base;
            uint32_t ah[4][4], bf4[4][4];
#pragma unroll
            for (int mt = 0; mt < 4; mt++)
                LDSM_X4(ah[mt], buf + (uint32_t)((arow + mt * 16) * PAD + acol) * 2);
#pragma unroll
            for (int np = 0; np < 4; np++)
                LDSM_X4(bf4[np], buf + MATB + (uint32_t)((brow + np * 16) * PAD + bcol) * 2);
#pragma unroll
            for (int np = 0; np < 4; np++)
#pragma unroll
                for (int mt = 0; mt < 4; mt++)
#pragma unroll
                    for (int half = 0; half < 2; half++)
                        MMA16816(acc[mt][np * 2 + half], ah[mt],
                                 bf4[np][half * 2], bf4[np][half * 2 + 1]);
        }
        if (i + 2 < NCH) {
            __syncthreads();                   // all warps done reading buf i&1
            issue_chunk(buf, Am, Bm, m0, n0, (i + 2) * BK, tid);
        }
    }

    int mrow = m0 + wm * 64 + (lane >> 2);
#pragma unroll
    for (int mt = 0; mt < 4; mt++) {
#pragma unroll
        for (int nt = 0; nt < 8; nt++) {
            int n = n0 + wn * 64 + nt * 8 + (lane & 3) * 2;
            float bx = bias[n], by = bias[n + 1];
            float2 v0 = make_float2(acc[mt][nt][0] + bx, acc[mt][nt][1] + by);
            float2 v1 = make_float2(acc[mt][nt][2] + bx, acc[mt][nt][3] + by);
            int m_a = mrow + mt * 16;
            int m_b = m_a + 8;
            if (MODE == 0) {
                int sec = n >> 10;
                int c2 = n & (Cc - 1);
                int h = c2 >> 6, d = c2 & 63;
                int ba = m_a >> 11, ta = m_a & (Tt - 1);
                int bb2 = m_b >> 11, tb = m_b & (Tt - 1);
                size_t o0 = (((size_t)(ba * Hh + h)) * Tt + ta) * HD + d;
                size_t o1 = (((size_t)(bb2 * Hh + h)) * Tt + tb) * HD + d;
                __half* dst;
                if (sec == 0) {
                    dst = g_Q;
                    v0.x *= QSCALE; v0.y *= QSCALE; v1.x *= QSCALE; v1.y *= QSCALE;
                } else {
                    dst = (sec == 1) ? g_K : g_V;
                }
                *(__half2*)&dst[o0] = __floats2half2_rn(v0.x, v0.y);
                *(__half2*)&dst[o1] = __floats2half2_rn(v1.x, v1.y);
            } else {
                *(float2*)&out[(size_t)m_a * Cc + n] = v0;
                *(float2*)&out[(size_t)m_b * Cc + n] = v1;
            }
        }
    }
}

// ---------------------------------------------------------------------------
// Tensor-core flash attention, all-single fp16 operands (1-term S, 1-term PV).
// exp2-domain softmax (Q pre-scaled by 0.125*log2e). Bq=128, Bk=64, 128 thr.
// Q fragments hoisted to registers; 3-buffer KV pipeline, 1 barrier/tile.
// ---------------------------------------------------------------------------
#define BQ 128
#define APAD 72
#define QMAT (BQ*APAD)
#define KMAT (64*APAD)
#define ASMEM ((QMAT + 6*KMAT)*2)    // 73728 B

__device__ __forceinline__ void issue_kv(uint32_t sK, uint32_t sV,
                                         const __half* gK, const __half* gV,
                                         int kv0, int tid) {
#pragma unroll
    for (int it = 0; it < 4; it++) {
        int idx = it * 128 + tid;
        int row = idx >> 3, seg = idx & 7;
        uint32_t so = (uint32_t)(row * APAD + seg * 8) * 2;
        size_t g = (size_t)(kv0 + row) * HD + seg * 8;
        cp_async16(sK + so, gK + g);
        cp_async16(sV + so, gV + g);
    }
    cp_commit();
}

__global__ __launch_bounds__(128, 2) void attn_tc() {
    extern __shared__ __half sa[];
    uint32_t sQ = smem_u32(sa);
    uint32_t sKV0 = sQ + QMAT * 2;             // K0|V0 | K1|V1 | K2|V2
    uint32_t sKb[3], sVb[3];
#pragma unroll
    for (int i = 0; i < 3; i++) {
        sKb[i] = sKV0 + (2 * i) * KMAT * 2;
        sVb[i] = sKV0 + (2 * i + 1) * KMAT * 2;
    }

    int tid = threadIdx.x;
    int lane = tid & 31, w = tid >> 5;
    int bh = blockIdx.y;
    int qtile = (gridDim.x - 1) - blockIdx.x;    // heavy tiles first
    int q0 = qtile * BQ;

    const __half* gQ = g_Q + (size_t)bh * Tt * HD;
    const __half* gK = g_K + (size_t)bh * Tt * HD;
    const __half* gV = g_V + (size_t)bh * Tt * HD;

    // G0: Q tile (128 x 64)
#pragma unroll
    for (int it = 0; it < 8; it++) {
        int idx = it * 128 + tid;
        int row = idx >> 3, seg = idx & 7;
        uint32_t so = (uint32_t)(row * APAD + seg * 8) * 2;
        cp_async16(sQ + so, gQ + (size_t)(q0 + row) * HD + seg * 8);
    }
    cp_commit();
    int ktmax = 2 * qtile + 1;
    issue_kv(sKb[0], sVb[0], gK, gV, 0, tid);
    issue_kv(sKb[1], sVb[1], gK, gV, 64, tid);

    float o[2][8][4] = {};
    float mrow[2][2] = {{-1e30f, -1e30f}, {-1e30f, -1e30f}};
    float lrow[2][2] = {};
    uint32_t aq[4][2][4];                        // hoisted Q fragments

    int r0 = lane >> 2;

    int bufi = 0;
    int nbuf = 2;
    for (int kt = 0; kt <= ktmax; kt++) {
        int kv0 = kt * 64;
        if (kt + 1 <= ktmax) {
            asm volatile("cp.async.wait_group 1;" ::: "memory");
        } else {
            asm volatile("cp.async.wait_group 0;" ::: "memory");
        }
        __syncthreads();
        if (kt == 0) {
#pragma unroll
            for (int ks = 0; ks < 4; ks++)
#pragma unroll
                for (int mt = 0; mt < 2; mt++) {
                    uint32_t off = (uint32_t)((w * 32 + mt * 16 + (lane & 15)) * APAD +
                                              ks * 16 + (lane >> 4) * 8) * 2;
                    LDSM_X4(aq[ks][mt], sQ + off);
                }
        }
        if (kt + 2 <= ktmax)
            issue_kv(sKb[nbuf], sVb[nbuf], gK, gV, (kt + 2) * 64, tid);
        uint32_t sKc = sKb[bufi], sVc = sVb[bufi];
        bufi = (bufi + 1 == 3) ? 0 : bufi + 1;
        nbuf = (nbuf + 1 == 3) ? 0 : nbuf + 1;

        // ---- S = Q K^T  (single term); result in log2 domain ----
        float s[2][8][4] = {};
#pragma unroll
        for (int ks = 0; ks < 4; ks++) {
            uint32_t bk[4][4];
#pragma unroll
            for (int ntp = 0; ntp < 4; ntp++)
                LDSM_X4(bk[ntp], sKc + (uint32_t)((ntp * 16 + (lane >> 4) * 8 + (lane & 7)) * APAD +
                                                  ks * 16 + ((lane >> 3) & 1) * 8) * 2);
#pragma unroll
            for (int ntp = 0; ntp < 4; ntp++)
#pragma unroll
                for (int mt = 0; mt < 2; mt++)
#pragma unroll
                    for (int h2 = 0; h2 < 2; h2++)
                        MMA16816(s[mt][ntp * 2 + h2], aq[ks][mt],
                                 bk[ntp][h2 * 2], bk[ntp][h2 * 2 + 1]);
        }

        // causal mask
        if (kv0 + 63 > q0 + w * 32) {
#pragma unroll
            for (int mt = 0; mt < 2; mt++)
#pragma unroll
                for (int nt = 0; nt < 8; nt++)
#pragma unroll
                    for (int j = 0; j < 4; j++) {
                        int c = kv0 + nt * 8 + (lane & 3) * 2 + (j & 1);
                        int r = q0 + w * 32 + mt * 16 + r0 + ((j >> 1) ? 8 : 0);
                        if (c > r) s[mt][nt][j] = -1e30f;
                    }
        }

        // ---- online softmax (exp2 domain) ----
#pragma unroll
        for (int mt = 0; mt < 2; mt++)
#pragma unroll
            for (int rr = 0; rr < 2; rr++) {
                float rm = -1e30f;
#pragma unroll
                for (int nt = 0; nt < 8; nt++)
                    rm = fmaxf(rm, fmaxf(s[mt][nt][rr * 2], s[mt][nt][rr * 2 + 1]));
                rm = fmaxf(rm, __shfl_xor_sync(0xffffffffu, rm, 1));
                rm = fmaxf(rm, __shfl_xor_sync(0xffffffffu, rm, 2));
                float mnew = fmaxf(mrow[mt][rr], rm);
                float alpha = ex2f(mrow[mt][rr] - mnew);
                mrow[mt][rr] = mnew;
                float rs = 0.0f;
#pragma unroll
                for (int nt = 0; nt < 8; nt++) {
                    s[mt][nt][rr * 2]     = ex2f(s[mt][nt][rr * 2] - mnew);
                    s[mt][nt][rr * 2 + 1] = ex2f(s[mt][nt][rr * 2 + 1] - mnew);
                    rs += s[mt][nt][rr * 2] + s[mt][nt][rr * 2 + 1];
                }
                rs += __shfl_xor_sync(0xffffffffu, rs, 1);
                rs += __shfl_xor_sync(0xffffffffu, rs, 2);
                lrow[mt][rr] = lrow[mt][rr] * alpha + rs;
#pragma unroll
                for (int dt = 0; dt < 8; dt++) {
                    o[mt][dt][rr * 2]     *= alpha;
                    o[mt][dt][rr * 2 + 1] *= alpha;
                }
            }

        // ---- O += P V  (P single fp16; V via trans-ldmatrix on [kv][d]) ----
#pragma unroll
        for (int ksv = 0; ksv < 4; ksv++) {
            uint32_t pah[2][4];
#pragma unroll
            for (int mt = 0; mt < 2; mt++)
#pragma unroll
                for (int q = 0; q < 4; q++) {
                    int nt = 2 * ksv + (q >> 1);
                    int j0 = (q & 1) * 2;
                    __half2 hv = __floats2half2_rn(s[mt][nt][j0], s[mt][nt][j0 + 1]);
                    pah[mt][q] = *(uint32_t*)&hv;
                }
            uint32_t bv[4][4];
#pragma unroll
            for (int dtp = 0; dtp < 4; dtp++) {
                uint32_t addr = sVc + (uint32_t)(
                    (ksv * 16 + ((lane >> 3) & 1) * 8 + (lane & 7)) * APAD +
                    dtp * 16 + (lane >> 4) * 8) * 2;
                LDSM_X4_T(bv[dtp], addr);
            }
#pragma unroll
            for (int dtp = 0; dtp < 4; dtp++)
#pragma unroll
                for (int mt = 0; mt < 2; mt++)
#pragma unroll
                    for (int h2 = 0; h2 < 2; h2++)
                        MMA16816(o[mt][dtp * 2 + h2], pah[mt],
                                 bv[dtp][h2 * 2], bv[dtp][h2 * 2 + 1]);
        }
    }

    // ---- epilogue: normalize, emit Y single fp16 [B,T,C] ----
    int bb = bh >> 4, h = bh & 15;
#pragma unroll
    for (int mt = 0; mt < 2; mt++) {
        float inv0 = 1.0f / lrow[mt][0];
        float inv1 = 1.0f / lrow[mt][1];
        int gq0 = q0 + w * 32 + mt * 16 + r0;
        int gq1 = gq0 + 8;
#pragma unroll
        for (int dt = 0; dt < 8; dt++) {
            int col = h * HD + dt * 8 + (lane & 3) * 2;
            size_t o0 = (size_t)(bb * Tt + gq0) * Cc + col;
            size_t o1 = (size_t)(bb * Tt + gq1) * Cc + col;
            *(__half2*)&g_Y[o0] = __floats2half2_rn(o[mt][dt][0] * inv0, o[mt][dt][1] * inv0);
            *(__half2*)&g_Y[o1] = __floats2half2_rn(o[mt][dt][2] * inv1, o[mt][dt][3] * inv1);
        }
    }
}

// ---------------------------------------------------------------------------
extern "C" void kernel_launch(void* const* d_in, const int* in_sizes, int n_in,
                              void* d_out, int out_size) {
    const float* x      = (const float*)d_in[0];
    const float* W_attn = (const float*)d_in[1];
    const float* b_attn = (const float*)d_in[2];
    const float* W_proj = (const float*)d_in[3];
    const float* b_proj = (const float*)d_in[4];
    float* out = (float*)d_out;

    __half *xp, *wa, *wp, *yp;
    cudaGetSymbolAddress((void**)&xp, g_X);
    cudaGetSymbolAddress((void**)&wa, g_WA);
    cudaGetSymbolAddress((void**)&wp, g_WP);
    cudaGetSymbolAddress((void**)&yp, g_Y);

    cudaFuncSetAttribute(tc_gemm<0>, cudaFuncAttributeMaxDynamicSharedMemorySize, GSMEM);
    cudaFuncSetAttribute(tc_gemm<1>, cudaFuncAttributeMaxDynamicSharedMemorySize, GSMEM);
    cudaFuncSetAttribute(attn_tc, cudaFuncAttributeMaxDynamicSharedMemorySize, ASMEM);

    convert_x_kernel<<<1024, 256>>>((const float4*)x, MR * Cc / 4);
    transconv_kernel<<<dim3(3 * Cc / 32, Cc / 32), dim3(32, 8)>>>(W_attn, wa, Cc, 3 * Cc);
    transconv_kernel<<<dim3(Cc / 32, Cc / 32), dim3(32, 8)>>>(W_proj, wp, Cc, Cc);

    tc_gemm<0><<<dim3(3 * Cc / 128, MR / 128), 128, GSMEM>>>(xp, wa, b_attn, nullptr);

    attn_tc<<<dim3(Tt / BQ, Bb * Hh), 128, ASMEM>>>();

    tc_gemm<1><<<dim3(Cc / 128, MR / 128), 128, GSMEM>>>(yp, wp, b_proj, out);
}